// round 7
// baseline (speedup 1.0000x reference)
#include <cuda_runtime.h>
#include <cuda_bf16.h>
#include <mma.h>
#include <math.h>
#include <stdint.h>

using namespace nvcuda;

#define S_LEN 2048
#define D_MODEL 2048
#define N_H 16
#define N_KV 4
#define H_DIM 128
#define SCALING 0.08838834764831845f
#define DM0 0.9779029130879204f
#define KV_DIM (N_KV * H_DIM)

typedef __nv_bfloat16 bf16;

// fp32 scratch
__device__ float g_q[(size_t)S_LEN * N_H * H_DIM];
__device__ float g_k[(size_t)S_LEN * KV_DIM];
__device__ float g_v[(size_t)S_LEN * KV_DIM];
__device__ float g_ctx[(size_t)S_LEN * N_H * H_DIM];
__device__ float g_attn[(size_t)N_H * S_LEN * S_LEN];

// pre-split bf16 hi/lo scratch
#define SZ_BIG  ((size_t)2048 * 2048)
#define SZ_SML  ((size_t)2048 * 512)
__device__ bf16 g_hsh[SZ_BIG], g_hsl[SZ_BIG];
__device__ bf16 g_wqh[SZ_BIG], g_wql[SZ_BIG];
__device__ bf16 g_wkh[SZ_SML], g_wkl[SZ_SML];
__device__ bf16 g_wvh[SZ_SML], g_wvl[SZ_SML];
__device__ bf16 g_woh[SZ_BIG], g_wol[SZ_BIG];
__device__ bf16 g_qh[SZ_BIG],  g_ql[SZ_BIG];
__device__ bf16 g_kh[SZ_SML],  g_kl[SZ_SML];
__device__ bf16 g_vh[SZ_SML],  g_vl[SZ_SML];
__device__ bf16 g_cth[SZ_BIG], g_ctl[SZ_BIG];

__device__ __forceinline__ void split_bf16(float v, bf16& hi, bf16& lo) {
    hi = __float2bfloat16_rn(v);
    lo = __float2bfloat16_rn(v - __bfloat162float(hi));
}
__device__ __forceinline__ uint32_t smem_u32(const void* p) {
    return (uint32_t)__cvta_generic_to_shared(p);
}
#define CP16(dst, src) asm volatile("cp.async.cg.shared.global [%0], [%1], 16;" :: "r"(dst), "l"(src))
#define CP_COMMIT()    asm volatile("cp.async.commit_group;" ::: "memory")
#define CP_WAIT1()     asm volatile("cp.async.wait_group 1;" ::: "memory")
#define CP_WAIT0()     asm volatile("cp.async.wait_group 0;" ::: "memory")

// ===========================================================================
// split: fp32 -> (bf16 hi, bf16 lo), 4 elems/thread
// ===========================================================================
__global__ void split_kernel(const float* __restrict__ x,
                             bf16* __restrict__ hi, bf16* __restrict__ lo, int n)
{
    int i = (blockIdx.x * blockDim.x + threadIdx.x) * 4;
    if (i >= n) return;
    float4 v = *(const float4*)(x + i);
    bf16 h0, l0, h1, l1, h2, l2, h3, l3;
    split_bf16(v.x, h0, l0); split_bf16(v.y, h1, l1);
    split_bf16(v.z, h2, l2); split_bf16(v.w, h3, l3);
    __nv_bfloat162* H = (__nv_bfloat162*)(hi + i);
    __nv_bfloat162* L = (__nv_bfloat162*)(lo + i);
    H[0] = __halves2bfloat162(h0, h1); H[1] = __halves2bfloat162(h2, h3);
    L[0] = __halves2bfloat162(l0, l1); L[1] = __halves2bfloat162(l2, l3);
}

// ===========================================================================
// RoPE + split
// ===========================================================================
__global__ void rope_split_kernel(const float* __restrict__ X,
                                  const float* __restrict__ cosb,
                                  const float* __restrict__ sinb, int nHeads,
                                  bf16* __restrict__ hi, bf16* __restrict__ lo)
{
    int idx = blockIdx.x * blockDim.x + threadIdx.x;
    int total = S_LEN * nHeads * (H_DIM / 2);
    if (idx >= total) return;
    int d = idx & 63;
    int t = idx >> 6;
    int hh = t % nHeads;
    int s  = t / nHeads;
    float c1 = cosb[s * H_DIM + d];
    float s1 = sinb[s * H_DIM + d];
    float c2 = cosb[s * H_DIM + d + 64];
    float s2 = sinb[s * H_DIM + d + 64];
    size_t base = (size_t)s * nHeads * H_DIM + (size_t)hh * H_DIM + d;
    float x1 = X[base];
    float x2 = X[base + 64];
    float y1 = x1 * c1 - x2 * s1;
    float y2 = x2 * c2 + x1 * s2;
    bf16 h, l;
    split_bf16(y1, h, l); hi[base] = h;      lo[base] = l;
    split_bf16(y2, h, l); hi[base + 64] = h; lo[base + 64] = l;
}

// ===========================================================================
// Pipelined split-bf16 NT GEMM core: CTA tile 256m x 128n, warp tile 64x64.
// 8 warps (256 thr), BK=32, 2-stage cp.async.
// Stage layout (bytes): Ah[256x40]@0, Al@20480, Bh[128x40]@40960, Bl@51200.
// ===========================================================================
#define ST_BYTES 61440
#define ST_ELEMS 30720
#define A_L_OFFB 20480
#define B_H_OFFB 40960
#define B_L_OFFB 51200
#define GEMM_SMEM (2 * ST_BYTES)

__device__ __forceinline__ void gemm_core(
    const bf16* __restrict__ Ah, const bf16* __restrict__ Al,
    const bf16* __restrict__ Bh, const bf16* __restrict__ Bl,
    int lda, int ldb, int K, int mBase, int nBase,
    float* __restrict__ C, int ldc, float scale)
{
    extern __shared__ bf16 sm[];
    const int tid = threadIdx.x;
    const int warp = tid >> 5;
    const int wm = warp >> 1;      // 0..3  (m group of 64)
    const int wn = warp & 1;       // 0..1  (n group of 64)

    wmma::fragment<wmma::accumulator, 16, 16, 16, float> acc[4][4];
#pragma unroll
    for (int i = 0; i < 4; i++)
#pragma unroll
        for (int j = 0; j < 4; j++) wmma::fill_fragment(acc[i][j], 0.0f);

    const int r_a = tid;               // A row 0..255
    const int r_b = tid >> 1;          // B row 0..127
    const int c_b = (tid & 1) * 16;    // B col 0 or 16

    const bf16* Aph = Ah + (size_t)(mBase + r_a) * lda;
    const bf16* Apl = Al + (size_t)(mBase + r_a) * lda;
    const bf16* Bph = Bh + (size_t)(nBase + r_b) * ldb + c_b;
    const bf16* Bpl = Bl + (size_t)(nBase + r_b) * ldb + c_b;

    const uint32_t sbase = smem_u32(sm);
    const uint32_t dA = sbase + r_a * 80;
    const uint32_t dB = sbase + B_H_OFFB + r_b * 80 + c_b * 2;

    const int T = K >> 5;

    // stage loader
#define LOAD_STAGE(buf, k0) do { \
        uint32_t da = dA + (buf) * ST_BYTES; \
        CP16(da,      Aph + (k0));      CP16(da + 16, Aph + (k0) + 8); \
        CP16(da + 32, Aph + (k0) + 16); CP16(da + 48, Aph + (k0) + 24); \
        uint32_t dal = da + A_L_OFFB; \
        CP16(dal,      Apl + (k0));      CP16(dal + 16, Apl + (k0) + 8); \
        CP16(dal + 32, Apl + (k0) + 16); CP16(dal + 48, Apl + (k0) + 24); \
        uint32_t db = dB + (buf) * ST_BYTES; \
        CP16(db, Bph + (k0)); CP16(db + 16, Bph + (k0) + 8); \
        uint32_t dbl = db + (B_L_OFFB - B_H_OFFB); \
        CP16(dbl, Bpl + (k0)); CP16(dbl + 16, Bpl + (k0) + 8); \
        CP_COMMIT(); \
    } while (0)

    LOAD_STAGE(0, 0);

#pragma unroll 1
    for (int t = 0; t < T; t++) {
        if (t + 1 < T) {
            LOAD_STAGE((t + 1) & 1, (t + 1) * 32);
            CP_WAIT1();
        } else {
            CP_WAIT0();
        }
        __syncthreads();

        bf16* st   = sm + (t & 1) * ST_ELEMS;
        bf16* Ah_s = st;
        bf16* Al_s = st + 10240;
        bf16* Bh_s = st + 20480;
        bf16* Bl_s = st + 25600;
#pragma unroll
        for (int ks = 0; ks < 32; ks += 16) {
            wmma::fragment<wmma::matrix_b, 16, 16, 16, bf16, wmma::col_major> bh[4], bl[4];
#pragma unroll
            for (int j = 0; j < 4; j++) {
                wmma::load_matrix_sync(bh[j], &Bh_s[(wn * 64 + j * 16) * 40 + ks], 40);
                wmma::load_matrix_sync(bl[j], &Bl_s[(wn * 64 + j * 16) * 40 + ks], 40);
            }
#pragma unroll
            for (int i = 0; i < 4; i++) {
                wmma::fragment<wmma::matrix_a, 16, 16, 16, bf16, wmma::row_major> ah, al;
                wmma::load_matrix_sync(ah, &Ah_s[(wm * 64 + i * 16) * 40 + ks], 40);
                wmma::load_matrix_sync(al, &Al_s[(wm * 64 + i * 16) * 40 + ks], 40);
#pragma unroll
                for (int j = 0; j < 4; j++) {
                    wmma::mma_sync(acc[i][j], ah, bl[j], acc[i][j]);
                    wmma::mma_sync(acc[i][j], al, bh[j], acc[i][j]);
                    wmma::mma_sync(acc[i][j], ah, bh[j], acc[i][j]);
                }
            }
        }
        __syncthreads();
    }
#undef LOAD_STAGE

#pragma unroll
    for (int i = 0; i < 4; i++)
#pragma unroll
        for (int j = 0; j < 4; j++) {
#pragma unroll
            for (int t = 0; t < acc[i][j].num_elements; t++) acc[i][j].x[t] *= scale;
            wmma::store_matrix_sync(
                C + (size_t)(mBase + wm * 64 + i * 16) * ldc + nBase + wn * 64 + j * 16,
                acc[i][j], ldc, wmma::mem_row_major);
        }
}

__global__ void __launch_bounds__(256) gemm_pre_kernel(
    const bf16* Ah, const bf16* Al, const bf16* Bh, const bf16* Bl,
    float* C, int N, int K)
{
    gemm_core(Ah, Al, Bh, Bl, K, K, K, blockIdx.y * 256, blockIdx.x * 128, C, N, 1.0f);
}

__global__ void __launch_bounds__(256) scores_pre_kernel(float* __restrict__ attn)
{
    const int h = blockIdx.z;
    const int mBase = blockIdx.y * 256;
    const int nBase = blockIdx.x * 128;
    if (nBase > mBase + 255) return;
    gemm_core(g_qh + h * H_DIM, g_ql + h * H_DIM,
              g_kh + (h >> 2) * H_DIM, g_kl + (h >> 2) * H_DIM,
              N_H * H_DIM, KV_DIM, H_DIM, mBase, nBase,
              attn + (size_t)h * S_LEN * S_LEN, S_LEN, SCALING);
}

// ===========================================================================
// Block reductions (256 threads)
// ===========================================================================
__device__ __forceinline__ float block_reduce_sum(float v, float* sm)
{
#pragma unroll
    for (int o = 16; o > 0; o >>= 1) v += __shfl_down_sync(0xffffffffu, v, o);
    const int lane = threadIdx.x & 31, wid = threadIdx.x >> 5;
    __syncthreads();
    if (lane == 0) sm[wid] = v;
    __syncthreads();
    if (wid == 0) {
        v = (lane < 8) ? sm[lane] : 0.f;
#pragma unroll
        for (int o = 4; o > 0; o >>= 1) v += __shfl_down_sync(0xffffffffu, v, o);
        if (lane == 0) sm[8] = v;
    }
    __syncthreads();
    return sm[8];
}

__device__ __forceinline__ float block_reduce_max(float v, float* sm)
{
#pragma unroll
    for (int o = 16; o > 0; o >>= 1) v = fmaxf(v, __shfl_down_sync(0xffffffffu, v, o));
    const int lane = threadIdx.x & 31, wid = threadIdx.x >> 5;
    __syncthreads();
    if (lane == 0) sm[wid] = v;
    __syncthreads();
    if (wid == 0) {
        v = (lane < 8) ? sm[lane] : -INFINITY;
#pragma unroll
        for (int o = 4; o > 0; o >>= 1) v = fmaxf(v, __shfl_down_sync(0xffffffffu, v, o));
        if (lane == 0) sm[8] = v;
    }
    __syncthreads();
    return sm[8];
}

// ===========================================================================
// alpha-entmax (alpha=1.5), 32-iter bisection
// ===========================================================================
__global__ void __launch_bounds__(256) entmax_kernel(float* __restrict__ attn)
{
    __shared__ float sm[9];
    const int row = blockIdx.x;
    const int h = row >> 11;
    const int q = row & 2047;
    float* x = attn + (size_t)h * S_LEN * S_LEN + (size_t)q * S_LEN;
    const int n = q + 1;
    const int tid = threadIdx.x;

    float X[8];
    float lmax = -INFINITY;
#pragma unroll
    for (int i = 0; i < 8; i++) {
        int j = tid + i * 256;
        if (j < n) {
            float v = x[j] * 0.5f;
            X[i] = v;
            lmax = fmaxf(lmax, v);
        } else {
            X[i] = -INFINITY;
        }
    }
    float maxv = block_reduce_max(lmax, sm);

    float tau_lo = maxv - 1.0f;
    float dm = DM0;
    float tau_m = tau_lo;
#pragma unroll 1
    for (int it = 0; it < 32; it++) {
        dm *= 0.5f;
        tau_m = tau_lo + dm;
        float ls = 0.f;
#pragma unroll
        for (int i = 0; i < 8; i++) {
            float t = fmaxf(X[i] - tau_m, 0.f);
            ls = fmaf(t, t, ls);
        }
        float f = block_reduce_sum(ls, sm);
        if (f >= 1.0f) tau_lo = tau_m;
    }

    float p[8];
    float ls = 0.f;
#pragma unroll
    for (int i = 0; i < 8; i++) {
        float t = fmaxf(X[i] - tau_m, 0.f);
        p[i] = t * t;
        ls += p[i];
    }
    float s = block_reduce_sum(ls, sm);
    float inv = 1.0f / s;
#pragma unroll
    for (int i = 0; i < 8; i++) {
        int j = tid + i * 256;
        x[j] = (j < n) ? p[i] * inv : 0.0f;
    }
}

// ===========================================================================
// attn @ V: A fp32 (split in-kernel), V pre-split. 128x128 tile, BK=32.
// ===========================================================================
__global__ void __launch_bounds__(256) av_kernel(const float* __restrict__ attn)
{
    const int h = blockIdx.z;
    const int mBase = blockIdx.y * 128;

    __shared__ bf16 Ah[128][40], Al[128][40];
    __shared__ bf16 Bh[32][136], Bl[32][136];

    const int tid = threadIdx.x;
    const int warp = tid >> 5;
    const int wm = warp & 3;
    const int wn = warp >> 2;

    const int lrA = tid >> 1;
    const int lcA = (tid & 1) * 16;
    const int krB = tid >> 3;
    const int ncB = (tid & 7) * 16;

    const float* A = attn + (size_t)h * S_LEN * S_LEN;
    const bf16* Bh_g = g_vh + (h >> 2) * H_DIM;
    const bf16* Bl_g = g_vl + (h >> 2) * H_DIM;

    wmma::fragment<wmma::accumulator, 16, 16, 16, float> acc[2][4];
#pragma unroll
    for (int i = 0; i < 2; i++)
#pragma unroll
        for (int j = 0; j < 4; j++) wmma::fill_fragment(acc[i][j], 0.0f);

    const int kmax = mBase + 128;
    for (int k0 = 0; k0 < kmax; k0 += 32) {
        float4 va[4];
#pragma unroll
        for (int t = 0; t < 4; t++)
            va[t] = *(const float4*)(A + (size_t)(mBase + lrA) * S_LEN + k0 + lcA + t * 4);
        size_t boff = (size_t)(k0 + krB) * KV_DIM + ncB;
        uint4 bh0 = *(const uint4*)(Bh_g + boff);
        uint4 bh1 = *(const uint4*)(Bh_g + boff + 8);
        uint4 bl0 = *(const uint4*)(Bl_g + boff);
        uint4 bl1 = *(const uint4*)(Bl_g + boff + 8);
        __syncthreads();
#pragma unroll
        for (int t = 0; t < 4; t++) {
            const float* pa = (const float*)&va[t];
#pragma unroll
            for (int e = 0; e < 4; e++) {
                bf16 hh2, ll;
                split_bf16(pa[e], hh2, ll);
                Ah[lrA][lcA + t * 4 + e] = hh2;
                Al[lrA][lcA + t * 4 + e] = ll;
            }
        }
        *(uint4*)&Bh[krB][ncB]     = bh0;
        *(uint4*)&Bh[krB][ncB + 8] = bh1;
        *(uint4*)&Bl[krB][ncB]     = bl0;
        *(uint4*)&Bl[krB][ncB + 8] = bl1;
        __syncthreads();
#pragma unroll
        for (int ks = 0; ks < 32; ks += 16) {
            wmma::fragment<wmma::matrix_a, 16, 16, 16, bf16, wmma::row_major> ah[2], al[2];
            wmma::fragment<wmma::matrix_b, 16, 16, 16, bf16, wmma::row_major> bh[4], bl[4];
#pragma unroll
            for (int i = 0; i < 2; i++) {
                wmma::load_matrix_sync(ah[i], &Ah[wm * 32 + i * 16][ks], 40);
                wmma::load_matrix_sync(al[i], &Al[wm * 32 + i * 16][ks], 40);
            }
#pragma unroll
            for (int j = 0; j < 4; j++) {
                wmma::load_matrix_sync(bh[j], &Bh[ks][wn * 64 + j * 16], 136);
                wmma::load_matrix_sync(bl[j], &Bl[ks][wn * 64 + j * 16], 136);
            }
#pragma unroll
            for (int i = 0; i < 2; i++)
#pragma unroll
                for (int j = 0; j < 4; j++) {
                    wmma::mma_sync(acc[i][j], ah[i], bl[j], acc[i][j]);
                    wmma::mma_sync(acc[i][j], al[i], bh[j], acc[i][j]);
                    wmma::mma_sync(acc[i][j], ah[i], bh[j], acc[i][j]);
                }
        }
    }

#pragma unroll
    for (int i = 0; i < 2; i++)
#pragma unroll
        for (int j = 0; j < 4; j++)
            wmma::store_matrix_sync(
                g_ctx + (size_t)(mBase + wm * 32 + i * 16) * (N_H * H_DIM)
                      + h * H_DIM + wn * 64 + j * 16,
                acc[i][j], N_H * H_DIM, wmma::mem_row_major);
}

// ===========================================================================
extern "C" void kernel_launch(void* const* d_in, const int* in_sizes, int n_in,
                              void* d_out, int out_size)
{
    const float* hs   = (const float*)d_in[0];
    const float* cosb = (const float*)d_in[1];
    const float* sinb = (const float*)d_in[2];
    const float* wq   = (const float*)d_in[3];
    const float* wk   = (const float*)d_in[4];
    const float* wv   = (const float*)d_in[5];
    const float* wo   = (const float*)d_in[6];
    float* out = (float*)d_out;

    float *qp, *kp, *vp, *cp, *ap;
    cudaGetSymbolAddress((void**)&qp, g_q);
    cudaGetSymbolAddress((void**)&kp, g_k);
    cudaGetSymbolAddress((void**)&vp, g_v);
    cudaGetSymbolAddress((void**)&cp, g_ctx);
    cudaGetSymbolAddress((void**)&ap, g_attn);

    bf16 *hsh, *hsl, *wqh, *wql, *wkh, *wkl, *wvh, *wvl, *woh, *wol;
    bf16 *qh, *ql, *kh, *kl, *vh, *vl, *cth, *ctl;
    cudaGetSymbolAddress((void**)&hsh, g_hsh); cudaGetSymbolAddress((void**)&hsl, g_hsl);
    cudaGetSymbolAddress((void**)&wqh, g_wqh); cudaGetSymbolAddress((void**)&wql, g_wql);
    cudaGetSymbolAddress((void**)&wkh, g_wkh); cudaGetSymbolAddress((void**)&wkl, g_wkl);
    cudaGetSymbolAddress((void**)&wvh, g_wvh); cudaGetSymbolAddress((void**)&wvl, g_wvl);
    cudaGetSymbolAddress((void**)&woh, g_woh); cudaGetSymbolAddress((void**)&wol, g_wol);
    cudaGetSymbolAddress((void**)&qh, g_qh);   cudaGetSymbolAddress((void**)&ql, g_ql);
    cudaGetSymbolAddress((void**)&kh, g_kh);   cudaGetSymbolAddress((void**)&kl, g_kl);
    cudaGetSymbolAddress((void**)&vh, g_vh);   cudaGetSymbolAddress((void**)&vl, g_vl);
    cudaGetSymbolAddress((void**)&cth, g_cth); cudaGetSymbolAddress((void**)&ctl, g_ctl);

    const size_t need = (size_t)S_LEN * D_MODEL + (size_t)N_H * S_LEN * S_LEN;
    float* attnBuf = ((size_t)out_size >= need) ? (out + (size_t)S_LEN * D_MODEL) : ap;

    cudaFuncSetAttribute(gemm_pre_kernel, cudaFuncAttributeMaxDynamicSharedMemorySize, GEMM_SMEM);
    cudaFuncSetAttribute(scores_pre_kernel, cudaFuncAttributeMaxDynamicSharedMemorySize, GEMM_SMEM);

    const int nBig = 2048 * 2048, nSml = 2048 * 512;

    // 0) pre-split inputs
    split_kernel<<<nBig / 1024, 256>>>(hs, hsh, hsl, nBig);
    split_kernel<<<nBig / 1024, 256>>>(wq, wqh, wql, nBig);
    split_kernel<<<nSml / 1024, 256>>>(wk, wkh, wkl, nSml);
    split_kernel<<<nSml / 1024, 256>>>(wv, wvh, wvl, nSml);
    split_kernel<<<nBig / 1024, 256>>>(wo, woh, wol, nBig);

    // 1) projections (256x128 tiles, warp 64x64)
    gemm_pre_kernel<<<dim3(D_MODEL / 128, S_LEN / 256), 256, GEMM_SMEM>>>(hsh, hsl, wqh, wql, qp, D_MODEL, D_MODEL);
    gemm_pre_kernel<<<dim3(KV_DIM / 128, S_LEN / 256), 256, GEMM_SMEM>>>(hsh, hsl, wkh, wkl, kp, KV_DIM, D_MODEL);
    gemm_pre_kernel<<<dim3(KV_DIM / 128, S_LEN / 256), 256, GEMM_SMEM>>>(hsh, hsl, wvh, wvl, vp, KV_DIM, D_MODEL);

    // 2) RoPE + split (q, k); split v
    {
        int totQ = S_LEN * N_H * (H_DIM / 2);
        int totK = S_LEN * N_KV * (H_DIM / 2);
        rope_split_kernel<<<(totQ + 255) / 256, 256>>>(qp, cosb, sinb, N_H, qh, ql);
        rope_split_kernel<<<(totK + 255) / 256, 256>>>(kp, cosb, sinb, N_KV, kh, kl);
        split_kernel<<<nSml / 1024, 256>>>(vp, vh, vl, nSml);
    }

    // 3) causal scores
    scores_pre_kernel<<<dim3(S_LEN / 128, S_LEN / 256, N_H), 256, GEMM_SMEM>>>(attnBuf);

    // 4) entmax in place
    entmax_kernel<<<N_H * S_LEN, 256>>>(attnBuf);

    // 5) attn @ v -> ctx, then split ctx
    av_kernel<<<dim3(1, S_LEN / 128, N_H), 256>>>(attnBuf);
    split_kernel<<<nBig / 1024, 256>>>(cp, cth, ctl, nBig);

    // 6) out = ctx @ wo^T
    gemm_pre_kernel<<<dim3(D_MODEL / 128, S_LEN / 256), 256, GEMM_SMEM>>>(cth, ctl, woh, wol, out, D_MODEL, D_MODEL);
}

// round 8
// speedup vs baseline: 1.1711x; 1.1711x over previous
#include <cuda_runtime.h>
#include <cuda_bf16.h>
#include <mma.h>
#include <math.h>
#include <stdint.h>

using namespace nvcuda;

#define S_LEN 2048
#define D_MODEL 2048
#define N_H 16
#define N_KV 4
#define H_DIM 128
#define SCALING 0.08838834764831845f
#define DM0 0.9779029130879204f
#define KV_DIM (N_KV * H_DIM)
#define QKV_DIM (N_H * H_DIM + 2 * KV_DIM)   // 3072

typedef __nv_bfloat16 bf16;

// fp32 scratch
__device__ float g_qkv[(size_t)S_LEN * QKV_DIM];
__device__ float g_ctx[(size_t)S_LEN * N_H * H_DIM];
__device__ float g_attn[(size_t)N_H * S_LEN * S_LEN];

// pre-split bf16 hi/lo scratch
#define SZ_BIG  ((size_t)2048 * 2048)
#define SZ_SML  ((size_t)2048 * 512)
#define SZ_W    ((size_t)3072 * 2048)
__device__ bf16 g_hsh[SZ_BIG], g_hsl[SZ_BIG];
__device__ bf16 g_wh[SZ_W],    g_wl[SZ_W];      // fused [wq; wk; wv]
__device__ bf16 g_woh[SZ_BIG], g_wol[SZ_BIG];
__device__ bf16 g_qh[SZ_BIG],  g_ql[SZ_BIG];
__device__ bf16 g_kh[SZ_SML],  g_kl[SZ_SML];
__device__ bf16 g_vh[SZ_SML],  g_vl[SZ_SML];
__device__ bf16 g_cth[SZ_BIG], g_ctl[SZ_BIG];

__device__ __forceinline__ void split_bf16(float v, bf16& hi, bf16& lo) {
    hi = __float2bfloat16_rn(v);
    lo = __float2bfloat16_rn(v - __bfloat162float(hi));
}
__device__ __forceinline__ uint32_t smem_u32(const void* p) {
    return (uint32_t)__cvta_generic_to_shared(p);
}
#define CP16(dst, src) asm volatile("cp.async.cg.shared.global [%0], [%1], 16;" :: "r"(dst), "l"(src))
#define CP_COMMIT()    asm volatile("cp.async.commit_group;" ::: "memory")
#define CP_WAIT1()     asm volatile("cp.async.wait_group 1;" ::: "memory")
#define CP_WAIT0()     asm volatile("cp.async.wait_group 0;" ::: "memory")

// ===========================================================================
// split: fp32 -> (bf16 hi, bf16 lo), contiguous, 4 elems/thread
// ===========================================================================
__global__ void split_kernel(const float* __restrict__ x,
                             bf16* __restrict__ hi, bf16* __restrict__ lo, int n)
{
    int i = (blockIdx.x * blockDim.x + threadIdx.x) * 4;
    if (i >= n) return;
    float4 v = *(const float4*)(x + i);
    bf16 h0, l0, h1, l1, h2, l2, h3, l3;
    split_bf16(v.x, h0, l0); split_bf16(v.y, h1, l1);
    split_bf16(v.z, h2, l2); split_bf16(v.w, h3, l3);
    __nv_bfloat162* H = (__nv_bfloat162*)(hi + i);
    __nv_bfloat162* L = (__nv_bfloat162*)(lo + i);
    H[0] = __halves2bfloat162(h0, h1); H[1] = __halves2bfloat162(h2, h3);
    L[0] = __halves2bfloat162(l0, l1); L[1] = __halves2bfloat162(l2, l3);
}

// strided split: src rows of `width` at stride srcStride -> dense hi/lo
__global__ void split_strided_kernel(const float* __restrict__ x, int srcStride, int width,
                                     bf16* __restrict__ hi, bf16* __restrict__ lo, int n)
{
    int i = (blockIdx.x * blockDim.x + threadIdx.x) * 4;
    if (i >= n) return;
    int s = i / width;
    int c = i - s * width;
    float4 v = *(const float4*)(x + (size_t)s * srcStride + c);
    bf16 h0, l0, h1, l1, h2, l2, h3, l3;
    split_bf16(v.x, h0, l0); split_bf16(v.y, h1, l1);
    split_bf16(v.z, h2, l2); split_bf16(v.w, h3, l3);
    __nv_bfloat162* H = (__nv_bfloat162*)(hi + i);
    __nv_bfloat162* L = (__nv_bfloat162*)(lo + i);
    H[0] = __halves2bfloat162(h0, h1); H[1] = __halves2bfloat162(h2, h3);
    L[0] = __halves2bfloat162(l0, l1); L[1] = __halves2bfloat162(l2, l3);
}

// ===========================================================================
// RoPE + split: reads fp32 [S][*] rows at xStride, writes rotated dense bf16 hi/lo
// ===========================================================================
__global__ void rope_split_kernel(const float* __restrict__ X, int xStride,
                                  const float* __restrict__ cosb,
                                  const float* __restrict__ sinb, int nHeads,
                                  bf16* __restrict__ hi, bf16* __restrict__ lo)
{
    int idx = blockIdx.x * blockDim.x + threadIdx.x;
    int total = S_LEN * nHeads * (H_DIM / 2);
    if (idx >= total) return;
    int d = idx & 63;
    int t = idx >> 6;
    int hh = t % nHeads;
    int s  = t / nHeads;
    float c1 = cosb[s * H_DIM + d];
    float s1 = sinb[s * H_DIM + d];
    float c2 = cosb[s * H_DIM + d + 64];
    float s2 = sinb[s * H_DIM + d + 64];
    size_t src = (size_t)s * xStride + (size_t)hh * H_DIM + d;
    size_t dst = (size_t)s * nHeads * H_DIM + (size_t)hh * H_DIM + d;
    float x1 = X[src];
    float x2 = X[src + 64];
    float y1 = x1 * c1 - x2 * s1;
    float y2 = x2 * c2 + x1 * s2;
    bf16 h, l;
    split_bf16(y1, h, l); hi[dst] = h;      lo[dst] = l;
    split_bf16(y2, h, l); hi[dst + 64] = h; lo[dst + 64] = l;
}

// ===========================================================================
// Pipelined split-bf16 NT GEMM core (round-6): BM=BN=128, BK=32, 256 thr,
// warp tile 32x64, 2-stage cp.async, 80KB SMEM -> 2 CTAs/SM.
// Stage layout (bytes): Ah@0, Al@10240, Bh@20480, Bl@30720. Stage=40960B.
// ===========================================================================
#define GEMM_SMEM (2 * 20480 * (int)sizeof(bf16))

__device__ __forceinline__ void gemm_core(
    const bf16* __restrict__ Ah, const bf16* __restrict__ Al,
    const bf16* __restrict__ Bh, const bf16* __restrict__ Bl,
    int lda, int ldb, int K, int mBase, int nBase,
    float* __restrict__ C, int ldc, float scale)
{
    extern __shared__ bf16 sm[];
    const int tid = threadIdx.x;
    const int warp = tid >> 5;
    const int wm = warp & 3;
    const int wn = warp >> 2;

    wmma::fragment<wmma::accumulator, 16, 16, 16, float> acc[2][4];
#pragma unroll
    for (int i = 0; i < 2; i++)
#pragma unroll
        for (int j = 0; j < 4; j++) wmma::fill_fragment(acc[i][j], 0.0f);

    const int r  = tid >> 1;            // 0..127
    const int cc = (tid & 1) * 16;      // 0 or 16

    const bf16* Ap_h = Ah + (size_t)(mBase + r) * lda + cc;
    const bf16* Ap_l = Al + (size_t)(mBase + r) * lda + cc;
    const bf16* Bp_h = Bh + (size_t)(nBase + r) * ldb + cc;
    const bf16* Bp_l = Bl + (size_t)(nBase + r) * ldb + cc;
    const uint32_t dbase = smem_u32(sm + r * 40 + cc);

    const int T = K >> 5;

    {
        CP16(dbase,             Ap_h); CP16(dbase + 16,         Ap_h + 8);
        CP16(dbase + 10240,     Ap_l); CP16(dbase + 10240 + 16, Ap_l + 8);
        CP16(dbase + 20480,     Bp_h); CP16(dbase + 20480 + 16, Bp_h + 8);
        CP16(dbase + 30720,     Bp_l); CP16(dbase + 30720 + 16, Bp_l + 8);
        CP_COMMIT();
    }

#pragma unroll 1
    for (int t = 0; t < T; t++) {
        if (t + 1 < T) {
            const int k1 = (t + 1) * 32;
            const uint32_t d = dbase + ((t + 1) & 1) * 40960;
            CP16(d,             Ap_h + k1); CP16(d + 16,         Ap_h + k1 + 8);
            CP16(d + 10240,     Ap_l + k1); CP16(d + 10240 + 16, Ap_l + k1 + 8);
            CP16(d + 20480,     Bp_h + k1); CP16(d + 20480 + 16, Bp_h + k1 + 8);
            CP16(d + 30720,     Bp_l + k1); CP16(d + 30720 + 16, Bp_l + k1 + 8);
            CP_COMMIT();
            CP_WAIT1();
        } else {
            CP_WAIT0();
        }
        __syncthreads();

        bf16* st   = sm + (t & 1) * 20480;
        bf16* Ah_s = st;
        bf16* Al_s = st + 5120;
        bf16* Bh_s = st + 10240;
        bf16* Bl_s = st + 15360;
#pragma unroll
        for (int ks = 0; ks < 32; ks += 16) {
            wmma::fragment<wmma::matrix_a, 16, 16, 16, bf16, wmma::row_major> ah[2], al[2];
            wmma::fragment<wmma::matrix_b, 16, 16, 16, bf16, wmma::col_major> bh[4], bl[4];
#pragma unroll
            for (int i = 0; i < 2; i++) {
                wmma::load_matrix_sync(ah[i], &Ah_s[(wm * 32 + i * 16) * 40 + ks], 40);
                wmma::load_matrix_sync(al[i], &Al_s[(wm * 32 + i * 16) * 40 + ks], 40);
            }
#pragma unroll
            for (int j = 0; j < 4; j++) {
                wmma::load_matrix_sync(bh[j], &Bh_s[(wn * 64 + j * 16) * 40 + ks], 40);
                wmma::load_matrix_sync(bl[j], &Bl_s[(wn * 64 + j * 16) * 40 + ks], 40);
            }
#pragma unroll
            for (int i = 0; i < 2; i++)
#pragma unroll
                for (int j = 0; j < 4; j++) {
                    wmma::mma_sync(acc[i][j], ah[i], bl[j], acc[i][j]);
                    wmma::mma_sync(acc[i][j], al[i], bh[j], acc[i][j]);
                    wmma::mma_sync(acc[i][j], ah[i], bh[j], acc[i][j]);
                }
        }
        __syncthreads();
    }

#pragma unroll
    for (int i = 0; i < 2; i++)
#pragma unroll
        for (int j = 0; j < 4; j++) {
#pragma unroll
            for (int t = 0; t < acc[i][j].num_elements; t++) acc[i][j].x[t] *= scale;
            wmma::store_matrix_sync(
                C + (size_t)(mBase + wm * 32 + i * 16) * ldc + nBase + wn * 64 + j * 16,
                acc[i][j], ldc, wmma::mem_row_major);
        }
}

__global__ void __launch_bounds__(256) gemm_pre_kernel(
    const bf16* Ah, const bf16* Al, const bf16* Bh, const bf16* Bl,
    float* C, int ldc, int K)
{
    gemm_core(Ah, Al, Bh, Bl, K, K, K, blockIdx.y * 128, blockIdx.x * 128, C, ldc, 1.0f);
}

__global__ void __launch_bounds__(256) scores_pre_kernel(float* __restrict__ attn)
{
    const int h = blockIdx.z;
    const int mBase = blockIdx.y * 128;
    const int nBase = blockIdx.x * 128;
    if (nBase > mBase + 127) return;
    gemm_core(g_qh + h * H_DIM, g_ql + h * H_DIM,
              g_kh + (h >> 2) * H_DIM, g_kl + (h >> 2) * H_DIM,
              N_H * H_DIM, KV_DIM, H_DIM, mBase, nBase,
              attn + (size_t)h * S_LEN * S_LEN, S_LEN, SCALING);
}

// ===========================================================================
// 2-sync block reductions with caller-provided buffer (alternating, lag-2 safe)
// ===========================================================================
__device__ __forceinline__ float bred_sum(float v, float* buf)
{
#pragma unroll
    for (int o = 16; o > 0; o >>= 1) v += __shfl_down_sync(0xffffffffu, v, o);
    const int lane = threadIdx.x & 31, wid = threadIdx.x >> 5;
    if (lane == 0) buf[wid] = v;
    __syncthreads();
    if (wid == 0) {
        v = (lane < 8) ? buf[lane] : 0.f;
#pragma unroll
        for (int o = 4; o > 0; o >>= 1) v += __shfl_down_sync(0xffffffffu, v, o);
        if (lane == 0) buf[8] = v;
    }
    __syncthreads();
    return buf[8];
}

__device__ __forceinline__ float bred_max(float v, float* buf)
{
#pragma unroll
    for (int o = 16; o > 0; o >>= 1) v = fmaxf(v, __shfl_down_sync(0xffffffffu, v, o));
    const int lane = threadIdx.x & 31, wid = threadIdx.x >> 5;
    if (lane == 0) buf[wid] = v;
    __syncthreads();
    if (wid == 0) {
        v = (lane < 8) ? buf[lane] : -INFINITY;
#pragma unroll
        for (int o = 4; o > 0; o >>= 1) v = fmaxf(v, __shfl_down_sync(0xffffffffu, v, o));
        if (lane == 0) buf[8] = v;
    }
    __syncthreads();
    return buf[8];
}

// ===========================================================================
// alpha-entmax (alpha=1.5), 32-iter bisection, alternating reduce buffers
// ===========================================================================
__global__ void __launch_bounds__(256) entmax_kernel(float* __restrict__ attn)
{
    __shared__ float sm[2][9];
    const int row = blockIdx.x;
    const int h = row >> 11;
    const int q = row & 2047;
    float* x = attn + (size_t)h * S_LEN * S_LEN + (size_t)q * S_LEN;
    const int n = q + 1;
    const int tid = threadIdx.x;

    float X[8];
    float lmax = -INFINITY;
#pragma unroll
    for (int i = 0; i < 8; i++) {
        int j = tid + i * 256;
        if (j < n) {
            float v = x[j] * 0.5f;
            X[i] = v;
            lmax = fmaxf(lmax, v);
        } else {
            X[i] = -INFINITY;
        }
    }
    float maxv = bred_max(lmax, sm[0]);

    float tau_lo = maxv - 1.0f;
    float dm = DM0;
    float tau_m = tau_lo;
#pragma unroll 1
    for (int it = 0; it < 32; it++) {
        dm *= 0.5f;
        tau_m = tau_lo + dm;
        float ls = 0.f;
#pragma unroll
        for (int i = 0; i < 8; i++) {
            float t = fmaxf(X[i] - tau_m, 0.f);
            ls = fmaf(t, t, ls);
        }
        float f = bred_sum(ls, sm[(it + 1) & 1]);
        if (f >= 1.0f) tau_lo = tau_m;
    }

    float p[8];
    float ls = 0.f;
#pragma unroll
    for (int i = 0; i < 8; i++) {
        float t = fmaxf(X[i] - tau_m, 0.f);
        p[i] = t * t;
        ls += p[i];
    }
    float s = bred_sum(ls, sm[1]);   // last loop iter used buffer 0
    float inv = 1.0f / s;
#pragma unroll
    for (int i = 0; i < 8; i++) {
        int j = tid + i * 256;
        x[j] = (j < n) ? p[i] * inv : 0.0f;
    }
}

// ===========================================================================
// attn @ V: A fp32 (split in-kernel), V pre-split. 128x128 tile, BK=32.
// ===========================================================================
__global__ void __launch_bounds__(256) av_kernel(const float* __restrict__ attn)
{
    const int h = blockIdx.z;
    const int mBase = blockIdx.y * 128;

    __shared__ bf16 Ah[128][40], Al[128][40];
    __shared__ bf16 Bh[32][136], Bl[32][136];

    const int tid = threadIdx.x;
    const int warp = tid >> 5;
    const int wm = warp & 3;
    const int wn = warp >> 2;

    const int lrA = tid >> 1;
    const int lcA = (tid & 1) * 16;
    const int krB = tid >> 3;
    const int ncB = (tid & 7) * 16;

    const float* A = attn + (size_t)h * S_LEN * S_LEN;
    const bf16* Bh_g = g_vh + (h >> 2) * H_DIM;
    const bf16* Bl_g = g_vl + (h >> 2) * H_DIM;

    wmma::fragment<wmma::accumulator, 16, 16, 16, float> acc[2][4];
#pragma unroll
    for (int i = 0; i < 2; i++)
#pragma unroll
        for (int j = 0; j < 4; j++) wmma::fill_fragment(acc[i][j], 0.0f);

    const int kmax = mBase + 128;
    for (int k0 = 0; k0 < kmax; k0 += 32) {
        float4 va[4];
#pragma unroll
        for (int t = 0; t < 4; t++)
            va[t] = *(const float4*)(A + (size_t)(mBase + lrA) * S_LEN + k0 + lcA + t * 4);
        size_t boff = (size_t)(k0 + krB) * KV_DIM + ncB;
        uint4 bh0 = *(const uint4*)(Bh_g + boff);
        uint4 bh1 = *(const uint4*)(Bh_g + boff + 8);
        uint4 bl0 = *(const uint4*)(Bl_g + boff);
        uint4 bl1 = *(const uint4*)(Bl_g + boff + 8);
        __syncthreads();
#pragma unroll
        for (int t = 0; t < 4; t++) {
            const float* pa = (const float*)&va[t];
#pragma unroll
            for (int e = 0; e < 4; e++) {
                bf16 hh2, ll;
                split_bf16(pa[e], hh2, ll);
                Ah[lrA][lcA + t * 4 + e] = hh2;
                Al[lrA][lcA + t * 4 + e] = ll;
            }
        }
        *(uint4*)&Bh[krB][ncB]     = bh0;
        *(uint4*)&Bh[krB][ncB + 8] = bh1;
        *(uint4*)&Bl[krB][ncB]     = bl0;
        *(uint4*)&Bl[krB][ncB + 8] = bl1;
        __syncthreads();
#pragma unroll
        for (int ks = 0; ks < 32; ks += 16) {
            wmma::fragment<wmma::matrix_a, 16, 16, 16, bf16, wmma::row_major> ah[2], al[2];
            wmma::fragment<wmma::matrix_b, 16, 16, 16, bf16, wmma::row_major> bh[4], bl[4];
#pragma unroll
            for (int i = 0; i < 2; i++) {
                wmma::load_matrix_sync(ah[i], &Ah[wm * 32 + i * 16][ks], 40);
                wmma::load_matrix_sync(al[i], &Al[wm * 32 + i * 16][ks], 40);
            }
#pragma unroll
            for (int j = 0; j < 4; j++) {
                wmma::load_matrix_sync(bh[j], &Bh[ks][wn * 64 + j * 16], 136);
                wmma::load_matrix_sync(bl[j], &Bl[ks][wn * 64 + j * 16], 136);
            }
#pragma unroll
            for (int i = 0; i < 2; i++)
#pragma unroll
                for (int j = 0; j < 4; j++) {
                    wmma::mma_sync(acc[i][j], ah[i], bl[j], acc[i][j]);
                    wmma::mma_sync(acc[i][j], al[i], bh[j], acc[i][j]);
                    wmma::mma_sync(acc[i][j], ah[i], bh[j], acc[i][j]);
                }
        }
    }

#pragma unroll
    for (int i = 0; i < 2; i++)
#pragma unroll
        for (int j = 0; j < 4; j++)
            wmma::store_matrix_sync(
                g_ctx + (size_t)(mBase + wm * 32 + i * 16) * (N_H * H_DIM)
                      + h * H_DIM + wn * 64 + j * 16,
                acc[i][j], N_H * H_DIM, wmma::mem_row_major);
}

// ===========================================================================
extern "C" void kernel_launch(void* const* d_in, const int* in_sizes, int n_in,
                              void* d_out, int out_size)
{
    const float* hs   = (const float*)d_in[0];
    const float* cosb = (const float*)d_in[1];
    const float* sinb = (const float*)d_in[2];
    const float* wq   = (const float*)d_in[3];
    const float* wk   = (const float*)d_in[4];
    const float* wv   = (const float*)d_in[5];
    const float* wo   = (const float*)d_in[6];
    float* out = (float*)d_out;

    float *qkvp, *cp, *ap;
    cudaGetSymbolAddress((void**)&qkvp, g_qkv);
    cudaGetSymbolAddress((void**)&cp, g_ctx);
    cudaGetSymbolAddress((void**)&ap, g_attn);

    bf16 *hsh, *hsl, *wh, *wl, *woh, *wol;
    bf16 *qh, *ql, *kh, *kl, *vh, *vl, *cth, *ctl;
    cudaGetSymbolAddress((void**)&hsh, g_hsh); cudaGetSymbolAddress((void**)&hsl, g_hsl);
    cudaGetSymbolAddress((void**)&wh, g_wh);   cudaGetSymbolAddress((void**)&wl, g_wl);
    cudaGetSymbolAddress((void**)&woh, g_woh); cudaGetSymbolAddress((void**)&wol, g_wol);
    cudaGetSymbolAddress((void**)&qh, g_qh);   cudaGetSymbolAddress((void**)&ql, g_ql);
    cudaGetSymbolAddress((void**)&kh, g_kh);   cudaGetSymbolAddress((void**)&kl, g_kl);
    cudaGetSymbolAddress((void**)&vh, g_vh);   cudaGetSymbolAddress((void**)&vl, g_vl);
    cudaGetSymbolAddress((void**)&cth, g_cth); cudaGetSymbolAddress((void**)&ctl, g_ctl);

    const size_t need = (size_t)S_LEN * D_MODEL + (size_t)N_H * S_LEN * S_LEN;
    float* attnBuf = ((size_t)out_size >= need) ? (out + (size_t)S_LEN * D_MODEL) : ap;

    cudaFuncSetAttribute(gemm_pre_kernel, cudaFuncAttributeMaxDynamicSharedMemorySize, GEMM_SMEM);
    cudaFuncSetAttribute(scores_pre_kernel, cudaFuncAttributeMaxDynamicSharedMemorySize, GEMM_SMEM);

    const int nBig = 2048 * 2048, nSml = 2048 * 512;

    // 0) pre-split inputs; weights into fused [wq; wk; wv] layout
    split_kernel<<<nBig / 1024, 256>>>(hs, hsh, hsl, nBig);
    split_kernel<<<nBig / 1024, 256>>>(wq, wh, wl, nBig);
    split_kernel<<<nSml / 1024, 256>>>(wk, wh + (size_t)2048 * 2048, wl + (size_t)2048 * 2048, nSml);
    split_kernel<<<nSml / 1024, 256>>>(wv, wh + (size_t)2560 * 2048, wl + (size_t)2560 * 2048, nSml);
    split_kernel<<<nBig / 1024, 256>>>(wo, woh, wol, nBig);

    // 1) fused qkv projection: [2048 x 3072] = hs @ [wq;wk;wv]^T
    gemm_pre_kernel<<<dim3(QKV_DIM / 128, S_LEN / 128), 256, GEMM_SMEM>>>(
        hsh, hsl, wh, wl, qkvp, QKV_DIM, D_MODEL);

    // 2) RoPE + split (q, k); strided split v
    {
        int totQ = S_LEN * N_H * (H_DIM / 2);
        int totK = S_LEN * N_KV * (H_DIM / 2);
        rope_split_kernel<<<(totQ + 255) / 256, 256>>>(qkvp, QKV_DIM, cosb, sinb, N_H, qh, ql);
        rope_split_kernel<<<(totK + 255) / 256, 256>>>(qkvp + 2048, QKV_DIM, cosb, sinb, N_KV, kh, kl);
        split_strided_kernel<<<nSml / 1024, 256>>>(qkvp + 2560, QKV_DIM, KV_DIM, vh, vl, nSml);
    }

    // 3) causal scores
    scores_pre_kernel<<<dim3(S_LEN / 128, S_LEN / 128, N_H), 256, GEMM_SMEM>>>(attnBuf);

    // 4) entmax in place
    entmax_kernel<<<N_H * S_LEN, 256>>>(attnBuf);

    // 5) attn @ v -> ctx, then split ctx
    av_kernel<<<dim3(1, S_LEN / 128, N_H), 256>>>(attnBuf);
    split_kernel<<<nBig / 1024, 256>>>(cp, cth, ctl, nBig);

    // 6) out = ctx @ wo^T
    gemm_pre_kernel<<<dim3(D_MODEL / 128, S_LEN / 128), 256, GEMM_SMEM>>>(
        cth, ctl, woh, wol, out, D_MODEL, D_MODEL);
}

// round 9
// speedup vs baseline: 1.2375x; 1.0567x over previous
#include <cuda_runtime.h>
#include <cuda_bf16.h>
#include <mma.h>
#include <math.h>
#include <stdint.h>

using namespace nvcuda;

#define S_LEN 2048
#define D_MODEL 2048
#define N_H 16
#define N_KV 4
#define H_DIM 128
#define SCALING 0.08838834764831845f
#define DM0 0.9779029130879204f
#define KV_DIM (N_KV * H_DIM)
#define QKV_DIM (N_H * H_DIM + 2 * KV_DIM)   // 3072

typedef __nv_bfloat16 bf16;

// fp32 scratch
__device__ float g_qkv[(size_t)S_LEN * QKV_DIM];
__device__ float g_ctx[(size_t)S_LEN * N_H * H_DIM];
__device__ float g_attn[(size_t)N_H * S_LEN * S_LEN];

// pre-split bf16 hi/lo scratch
#define SZ_BIG  ((size_t)2048 * 2048)
#define SZ_SML  ((size_t)2048 * 512)
#define SZ_W    ((size_t)3072 * 2048)
__device__ bf16 g_hsh[SZ_BIG], g_hsl[SZ_BIG];
__device__ bf16 g_wh[SZ_W],    g_wl[SZ_W];      // fused [wq; wk; wv]
__device__ bf16 g_woh[SZ_BIG], g_wol[SZ_BIG];
__device__ bf16 g_qh[SZ_BIG],  g_ql[SZ_BIG];
__device__ bf16 g_kh[SZ_SML],  g_kl[SZ_SML];
__device__ bf16 g_vh[SZ_SML],  g_vl[SZ_SML];
__device__ bf16 g_cth[SZ_BIG], g_ctl[SZ_BIG];

__device__ __forceinline__ void split_bf16(float v, bf16& hi, bf16& lo) {
    hi = __float2bfloat16_rn(v);
    lo = __float2bfloat16_rn(v - __bfloat162float(hi));
}
__device__ __forceinline__ uint32_t smem_u32(const void* p) {
    return (uint32_t)__cvta_generic_to_shared(p);
}
#define CP16(dst, src) asm volatile("cp.async.cg.shared.global [%0], [%1], 16;" :: "r"(dst), "l"(src))
#define CP_COMMIT()    asm volatile("cp.async.commit_group;" ::: "memory")
#define CP_WAIT1()     asm volatile("cp.async.wait_group 1;" ::: "memory")
#define CP_WAIT0()     asm volatile("cp.async.wait_group 0;" ::: "memory")

// ===========================================================================
// split kernels
// ===========================================================================
__global__ void split_kernel(const float* __restrict__ x,
                             bf16* __restrict__ hi, bf16* __restrict__ lo, int n)
{
    int i = (blockIdx.x * blockDim.x + threadIdx.x) * 4;
    if (i >= n) return;
    float4 v = *(const float4*)(x + i);
    bf16 h0, l0, h1, l1, h2, l2, h3, l3;
    split_bf16(v.x, h0, l0); split_bf16(v.y, h1, l1);
    split_bf16(v.z, h2, l2); split_bf16(v.w, h3, l3);
    __nv_bfloat162* H = (__nv_bfloat162*)(hi + i);
    __nv_bfloat162* L = (__nv_bfloat162*)(lo + i);
    H[0] = __halves2bfloat162(h0, h1); H[1] = __halves2bfloat162(h2, h3);
    L[0] = __halves2bfloat162(l0, l1); L[1] = __halves2bfloat162(l2, l3);
}

__global__ void split_strided_kernel(const float* __restrict__ x, int srcStride, int width,
                                     bf16* __restrict__ hi, bf16* __restrict__ lo, int n)
{
    int i = (blockIdx.x * blockDim.x + threadIdx.x) * 4;
    if (i >= n) return;
    int s = i / width;
    int c = i - s * width;
    float4 v = *(const float4*)(x + (size_t)s * srcStride + c);
    bf16 h0, l0, h1, l1, h2, l2, h3, l3;
    split_bf16(v.x, h0, l0); split_bf16(v.y, h1, l1);
    split_bf16(v.z, h2, l2); split_bf16(v.w, h3, l3);
    __nv_bfloat162* H = (__nv_bfloat162*)(hi + i);
    __nv_bfloat162* L = (__nv_bfloat162*)(lo + i);
    H[0] = __halves2bfloat162(h0, h1); H[1] = __halves2bfloat162(h2, h3);
    L[0] = __halves2bfloat162(l0, l1); L[1] = __halves2bfloat162(l2, l3);
}

// ===========================================================================
// RoPE + split
// ===========================================================================
__global__ void rope_split_kernel(const float* __restrict__ X, int xStride,
                                  const float* __restrict__ cosb,
                                  const float* __restrict__ sinb, int nHeads,
                                  bf16* __restrict__ hi, bf16* __restrict__ lo)
{
    int idx = blockIdx.x * blockDim.x + threadIdx.x;
    int total = S_LEN * nHeads * (H_DIM / 2);
    if (idx >= total) return;
    int d = idx & 63;
    int t = idx >> 6;
    int hh = t % nHeads;
    int s  = t / nHeads;
    float c1 = cosb[s * H_DIM + d];
    float s1 = sinb[s * H_DIM + d];
    float c2 = cosb[s * H_DIM + d + 64];
    float s2 = sinb[s * H_DIM + d + 64];
    size_t src = (size_t)s * xStride + (size_t)hh * H_DIM + d;
    size_t dst = (size_t)s * nHeads * H_DIM + (size_t)hh * H_DIM + d;
    float x1 = X[src];
    float x2 = X[src + 64];
    float y1 = x1 * c1 - x2 * s1;
    float y2 = x2 * c2 + x1 * s2;
    bf16 h, l;
    split_bf16(y1, h, l); hi[dst] = h;      lo[dst] = l;
    split_bf16(y2, h, l); hi[dst + 64] = h; lo[dst + 64] = l;
}

// ===========================================================================
// Pipelined split-bf16 NT GEMM core: BM=BN=128, BK=32, 128 threads (4 warps),
// warp tile 64x64, 2-stage cp.async, 80KB SMEM -> 2 CTAs/SM.
// Stage layout (bytes): Ah@0, Al@10240, Bh@20480, Bl@30720. Stage=40960B.
// ===========================================================================
#define GEMM_SMEM (2 * 20480 * (int)sizeof(bf16))

__device__ __forceinline__ void gemm_core(
    const bf16* __restrict__ Ah, const bf16* __restrict__ Al,
    const bf16* __restrict__ Bh, const bf16* __restrict__ Bl,
    int lda, int ldb, int K, int mBase, int nBase,
    float* __restrict__ C, int ldc, float scale)
{
    extern __shared__ bf16 sm[];
    const int tid = threadIdx.x;          // 0..127
    const int warp = tid >> 5;            // 0..3
    const int wm = warp >> 1;             // 0..1 (m group of 64)
    const int wn = warp & 1;              // 0..1 (n group of 64)

    wmma::fragment<wmma::accumulator, 16, 16, 16, float> acc[4][4];
#pragma unroll
    for (int i = 0; i < 4; i++)
#pragma unroll
        for (int j = 0; j < 4; j++) wmma::fill_fragment(acc[i][j], 0.0f);

    const bf16* Ap_h = Ah + (size_t)(mBase + tid) * lda;
    const bf16* Ap_l = Al + (size_t)(mBase + tid) * lda;
    const bf16* Bp_h = Bh + (size_t)(nBase + tid) * ldb;
    const bf16* Bp_l = Bl + (size_t)(nBase + tid) * ldb;
    const uint32_t dbase = smem_u32(sm) + tid * 80;

    const int T = K >> 5;

#define LOAD_STAGE(buf, k0) do { \
        uint32_t d = dbase + (buf) * 40960; \
        CP16(d,          Ap_h + (k0));      CP16(d + 16,          Ap_h + (k0) + 8); \
        CP16(d + 32,     Ap_h + (k0) + 16); CP16(d + 48,          Ap_h + (k0) + 24); \
        CP16(d + 10240,      Ap_l + (k0));      CP16(d + 10240 + 16, Ap_l + (k0) + 8); \
        CP16(d + 10240 + 32, Ap_l + (k0) + 16); CP16(d + 10240 + 48, Ap_l + (k0) + 24); \
        CP16(d + 20480,      Bp_h + (k0));      CP16(d + 20480 + 16, Bp_h + (k0) + 8); \
        CP16(d + 20480 + 32, Bp_h + (k0) + 16); CP16(d + 20480 + 48, Bp_h + (k0) + 24); \
        CP16(d + 30720,      Bp_l + (k0));      CP16(d + 30720 + 16, Bp_l + (k0) + 8); \
        CP16(d + 30720 + 32, Bp_l + (k0) + 16); CP16(d + 30720 + 48, Bp_l + (k0) + 24); \
        CP_COMMIT(); \
    } while (0)

    LOAD_STAGE(0, 0);

#pragma unroll 1
    for (int t = 0; t < T; t++) {
        if (t + 1 < T) {
            LOAD_STAGE((t + 1) & 1, (t + 1) * 32);
            CP_WAIT1();
        } else {
            CP_WAIT0();
        }
        __syncthreads();

        bf16* st   = sm + (t & 1) * 20480;
        bf16* Ah_s = st;
        bf16* Al_s = st + 5120;
        bf16* Bh_s = st + 10240;
        bf16* Bl_s = st + 15360;
#pragma unroll
        for (int ks = 0; ks < 32; ks += 16) {
            wmma::fragment<wmma::matrix_b, 16, 16, 16, bf16, wmma::col_major> bh[4], bl[4];
#pragma unroll
            for (int j = 0; j < 4; j++) {
                wmma::load_matrix_sync(bh[j], &Bh_s[(wn * 64 + j * 16) * 40 + ks], 40);
                wmma::load_matrix_sync(bl[j], &Bl_s[(wn * 64 + j * 16) * 40 + ks], 40);
            }
#pragma unroll
            for (int i = 0; i < 4; i++) {
                wmma::fragment<wmma::matrix_a, 16, 16, 16, bf16, wmma::row_major> ah, al;
                wmma::load_matrix_sync(ah, &Ah_s[(wm * 64 + i * 16) * 40 + ks], 40);
                wmma::load_matrix_sync(al, &Al_s[(wm * 64 + i * 16) * 40 + ks], 40);
#pragma unroll
                for (int j = 0; j < 4; j++) {
                    wmma::mma_sync(acc[i][j], ah, bl[j], acc[i][j]);
                    wmma::mma_sync(acc[i][j], al, bh[j], acc[i][j]);
                    wmma::mma_sync(acc[i][j], ah, bh[j], acc[i][j]);
                }
            }
        }
        __syncthreads();
    }
#undef LOAD_STAGE

#pragma unroll
    for (int i = 0; i < 4; i++)
#pragma unroll
        for (int j = 0; j < 4; j++) {
#pragma unroll
            for (int t = 0; t < acc[i][j].num_elements; t++) acc[i][j].x[t] *= scale;
            wmma::store_matrix_sync(
                C + (size_t)(mBase + wm * 64 + i * 16) * ldc + nBase + wn * 64 + j * 16,
                acc[i][j], ldc, wmma::mem_row_major);
        }
}

__global__ void __launch_bounds__(128) gemm_pre_kernel(
    const bf16* Ah, const bf16* Al, const bf16* Bh, const bf16* Bl,
    float* C, int ldc, int K)
{
    gemm_core(Ah, Al, Bh, Bl, K, K, K, blockIdx.y * 128, blockIdx.x * 128, C, ldc, 1.0f);
}

__global__ void __launch_bounds__(128) scores_pre_kernel(float* __restrict__ attn)
{
    const int h = blockIdx.z;
    const int mBase = blockIdx.y * 128;
    const int nBase = blockIdx.x * 128;
    if (nBase > mBase + 127) return;
    gemm_core(g_qh + h * H_DIM, g_ql + h * H_DIM,
              g_kh + (h >> 2) * H_DIM, g_kl + (h >> 2) * H_DIM,
              N_H * H_DIM, KV_DIM, H_DIM, mBase, nBase,
              attn + (size_t)h * S_LEN * S_LEN, S_LEN, SCALING);
}

// ===========================================================================
// 2-sync block reductions (alternating buffers, lag-2 safe)
// ===========================================================================
__device__ __forceinline__ float bred_sum(float v, float* buf)
{
#pragma unroll
    for (int o = 16; o > 0; o >>= 1) v += __shfl_down_sync(0xffffffffu, v, o);
    const int lane = threadIdx.x & 31, wid = threadIdx.x >> 5;
    if (lane == 0) buf[wid] = v;
    __syncthreads();
    if (wid == 0) {
        v = (lane < 8) ? buf[lane] : 0.f;
#pragma unroll
        for (int o = 4; o > 0; o >>= 1) v += __shfl_down_sync(0xffffffffu, v, o);
        if (lane == 0) buf[8] = v;
    }
    __syncthreads();
    return buf[8];
}

__device__ __forceinline__ float bred_max(float v, float* buf)
{
#pragma unroll
    for (int o = 16; o > 0; o >>= 1) v = fmaxf(v, __shfl_down_sync(0xffffffffu, v, o));
    const int lane = threadIdx.x & 31, wid = threadIdx.x >> 5;
    if (lane == 0) buf[wid] = v;
    __syncthreads();
    if (wid == 0) {
        v = (lane < 8) ? buf[lane] : -INFINITY;
#pragma unroll
        for (int o = 4; o > 0; o >>= 1) v = fmaxf(v, __shfl_down_sync(0xffffffffu, v, o));
        if (lane == 0) buf[8] = v;
    }
    __syncthreads();
    return buf[8];
}

// ===========================================================================
// alpha-entmax (alpha=1.5), 32-iter bisection, templated live-chunk count
// ===========================================================================
template <int C>
__device__ __forceinline__ void entmax_row(float* __restrict__ x, int n, int tid,
                                           float (*sm)[9])
{
    float X[C];
    float lmax = -INFINITY;
#pragma unroll
    for (int i = 0; i < C; i++) {
        int j = tid + i * 256;
        if (j < n) {
            float v = x[j] * 0.5f;
            X[i] = v;
            lmax = fmaxf(lmax, v);
        } else {
            X[i] = -INFINITY;
        }
    }
    float maxv = bred_max(lmax, sm[0]);

    float tau_lo = maxv - 1.0f;
    float dm = DM0;
    float tau_m = tau_lo;
#pragma unroll 1
    for (int it = 0; it < 32; it++) {
        dm *= 0.5f;
        tau_m = tau_lo + dm;
        float ls = 0.f;
#pragma unroll
        for (int i = 0; i < C; i++) {
            float t = fmaxf(X[i] - tau_m, 0.f);
            ls = fmaf(t, t, ls);
        }
        float f = bred_sum(ls, sm[(it + 1) & 1]);
        if (f >= 1.0f) tau_lo = tau_m;
    }

    float p[C];
    float ls = 0.f;
#pragma unroll
    for (int i = 0; i < C; i++) {
        float t = fmaxf(X[i] - tau_m, 0.f);
        p[i] = t * t;
        ls += p[i];
    }
    float s = bred_sum(ls, sm[1]);   // last loop iter used buffer 0
    float inv = 1.0f / s;
#pragma unroll
    for (int i = 0; i < C; i++) {
        int j = tid + i * 256;
        x[j] = (j < n) ? p[i] * inv : 0.0f;
    }
#pragma unroll
    for (int i = C; i < 8; i++) x[tid + i * 256] = 0.0f;
}

__global__ void __launch_bounds__(256) entmax_kernel(float* __restrict__ attn)
{
    __shared__ float sm[2][9];
    const int row = blockIdx.x;
    const int h = row >> 11;
    const int q = row & 2047;
    float* x = attn + (size_t)h * S_LEN * S_LEN + (size_t)q * S_LEN;
    const int n = q + 1;
    const int tid = threadIdx.x;
    const int c = (n + 255) >> 8;

    switch (c) {
        case 1: entmax_row<1>(x, n, tid, sm); break;
        case 2: entmax_row<2>(x, n, tid, sm); break;
        case 3: entmax_row<3>(x, n, tid, sm); break;
        case 4: entmax_row<4>(x, n, tid, sm); break;
        case 5: entmax_row<5>(x, n, tid, sm); break;
        case 6: entmax_row<6>(x, n, tid, sm); break;
        case 7: entmax_row<7>(x, n, tid, sm); break;
        default: entmax_row<8>(x, n, tid, sm); break;
    }
}

// ===========================================================================
// attn @ V: A fp32 (split in-kernel), V pre-split. 128x128 tile, BK=32.
// Heaviest m-tiles launch first (reversed order) to shrink the tail wave.
// ===========================================================================
__global__ void __launch_bounds__(256) av_kernel(const float* __restrict__ attn)
{
    const int h = blockIdx.z;
    const int mBase = (gridDim.y - 1 - blockIdx.y) * 128;

    __shared__ bf16 Ah[128][40], Al[128][40];
    __shared__ bf16 Bh[32][136], Bl[32][136];

    const int tid = threadIdx.x;
    const int warp = tid >> 5;
    const int wm = warp & 3;
    const int wn = warp >> 2;

    const int lrA = tid >> 1;
    const int lcA = (tid & 1) * 16;
    const int krB = tid >> 3;
    const int ncB = (tid & 7) * 16;

    const float* A = attn + (size_t)h * S_LEN * S_LEN;
    const bf16* Bh_g = g_vh + (h >> 2) * H_DIM;
    const bf16* Bl_g = g_vl + (h >> 2) * H_DIM;

    wmma::fragment<wmma::accumulator, 16, 16, 16, float> acc[2][4];
#pragma unroll
    for (int i = 0; i < 2; i++)
#pragma unroll
        for (int j = 0; j < 4; j++) wmma::fill_fragment(acc[i][j], 0.0f);

    const int kmax = mBase + 128;
    for (int k0 = 0; k0 < kmax; k0 += 32) {
        float4 va[4];
#pragma unroll
        for (int t = 0; t < 4; t++)
            va[t] = *(const float4*)(A + (size_t)(mBase + lrA) * S_LEN + k0 + lcA + t * 4);
        size_t boff = (size_t)(k0 + krB) * KV_DIM + ncB;
        uint4 bh0 = *(const uint4*)(Bh_g + boff);
        uint4 bh1 = *(const uint4*)(Bh_g + boff + 8);
        uint4 bl0 = *(const uint4*)(Bl_g + boff);
        uint4 bl1 = *(const uint4*)(Bl_g + boff + 8);
        __syncthreads();
#pragma unroll
        for (int t = 0; t < 4; t++) {
            const float* pa = (const float*)&va[t];
#pragma unroll
            for (int e = 0; e < 4; e++) {
                bf16 hh2, ll;
                split_bf16(pa[e], hh2, ll);
                Ah[lrA][lcA + t * 4 + e] = hh2;
                Al[lrA][lcA + t * 4 + e] = ll;
            }
        }
        *(uint4*)&Bh[krB][ncB]     = bh0;
        *(uint4*)&Bh[krB][ncB + 8] = bh1;
        *(uint4*)&Bl[krB][ncB]     = bl0;
        *(uint4*)&Bl[krB][ncB + 8] = bl1;
        __syncthreads();
#pragma unroll
        for (int ks = 0; ks < 32; ks += 16) {
            wmma::fragment<wmma::matrix_a, 16, 16, 16, bf16, wmma::row_major> ah[2], al[2];
            wmma::fragment<wmma::matrix_b, 16, 16, 16, bf16, wmma::row_major> bh[4], bl[4];
#pragma unroll
            for (int i = 0; i < 2; i++) {
                wmma::load_matrix_sync(ah[i], &Ah[wm * 32 + i * 16][ks], 40);
                wmma::load_matrix_sync(al[i], &Al[wm * 32 + i * 16][ks], 40);
            }
#pragma unroll
            for (int j = 0; j < 4; j++) {
                wmma::load_matrix_sync(bh[j], &Bh[ks][wn * 64 + j * 16], 136);
                wmma::load_matrix_sync(bl[j], &Bl[ks][wn * 64 + j * 16], 136);
            }
#pragma unroll
            for (int i = 0; i < 2; i++)
#pragma unroll
                for (int j = 0; j < 4; j++) {
                    wmma::mma_sync(acc[i][j], ah[i], bl[j], acc[i][j]);
                    wmma::mma_sync(acc[i][j], al[i], bh[j], acc[i][j]);
                    wmma::mma_sync(acc[i][j], ah[i], bh[j], acc[i][j]);
                }
        }
    }

#pragma unroll
    for (int i = 0; i < 2; i++)
#pragma unroll
        for (int j = 0; j < 4; j++)
            wmma::store_matrix_sync(
                g_ctx + (size_t)(mBase + wm * 32 + i * 16) * (N_H * H_DIM)
                      + h * H_DIM + wn * 64 + j * 16,
                acc[i][j], N_H * H_DIM, wmma::mem_row_major);
}

// ===========================================================================
extern "C" void kernel_launch(void* const* d_in, const int* in_sizes, int n_in,
                              void* d_out, int out_size)
{
    const float* hs   = (const float*)d_in[0];
    const float* cosb = (const float*)d_in[1];
    const float* sinb = (const float*)d_in[2];
    const float* wq   = (const float*)d_in[3];
    const float* wk   = (const float*)d_in[4];
    const float* wv   = (const float*)d_in[5];
    const float* wo   = (const float*)d_in[6];
    float* out = (float*)d_out;

    float *qkvp, *cp, *ap;
    cudaGetSymbolAddress((void**)&qkvp, g_qkv);
    cudaGetSymbolAddress((void**)&cp, g_ctx);
    cudaGetSymbolAddress((void**)&ap, g_attn);

    bf16 *hsh, *hsl, *wh, *wl, *woh, *wol;
    bf16 *qh, *ql, *kh, *kl, *vh, *vl, *cth, *ctl;
    cudaGetSymbolAddress((void**)&hsh, g_hsh); cudaGetSymbolAddress((void**)&hsl, g_hsl);
    cudaGetSymbolAddress((void**)&wh, g_wh);   cudaGetSymbolAddress((void**)&wl, g_wl);
    cudaGetSymbolAddress((void**)&woh, g_woh); cudaGetSymbolAddress((void**)&wol, g_wol);
    cudaGetSymbolAddress((void**)&qh, g_qh);   cudaGetSymbolAddress((void**)&ql, g_ql);
    cudaGetSymbolAddress((void**)&kh, g_kh);   cudaGetSymbolAddress((void**)&kl, g_kl);
    cudaGetSymbolAddress((void**)&vh, g_vh);   cudaGetSymbolAddress((void**)&vl, g_vl);
    cudaGetSymbolAddress((void**)&cth, g_cth); cudaGetSymbolAddress((void**)&ctl, g_ctl);

    const size_t need = (size_t)S_LEN * D_MODEL + (size_t)N_H * S_LEN * S_LEN;
    float* attnBuf = ((size_t)out_size >= need) ? (out + (size_t)S_LEN * D_MODEL) : ap;

    cudaFuncSetAttribute(gemm_pre_kernel, cudaFuncAttributeMaxDynamicSharedMemorySize, GEMM_SMEM);
    cudaFuncSetAttribute(scores_pre_kernel, cudaFuncAttributeMaxDynamicSharedMemorySize, GEMM_SMEM);

    const int nBig = 2048 * 2048, nSml = 2048 * 512;

    // 0) pre-split inputs; weights into fused [wq; wk; wv] layout
    split_kernel<<<nBig / 1024, 256>>>(hs, hsh, hsl, nBig);
    split_kernel<<<nBig / 1024, 256>>>(wq, wh, wl, nBig);
    split_kernel<<<nSml / 1024, 256>>>(wk, wh + (size_t)2048 * 2048, wl + (size_t)2048 * 2048, nSml);
    split_kernel<<<nSml / 1024, 256>>>(wv, wh + (size_t)2560 * 2048, wl + (size_t)2560 * 2048, nSml);
    split_kernel<<<nBig / 1024, 256>>>(wo, woh, wol, nBig);

    // 1) fused qkv projection: [2048 x 3072] = hs @ [wq;wk;wv]^T
    gemm_pre_kernel<<<dim3(QKV_DIM / 128, S_LEN / 128), 128, GEMM_SMEM>>>(
        hsh, hsl, wh, wl, qkvp, QKV_DIM, D_MODEL);

    // 2) RoPE + split (q, k); strided split v
    {
        int totQ = S_LEN * N_H * (H_DIM / 2);
        int totK = S_LEN * N_KV * (H_DIM / 2);
        rope_split_kernel<<<(totQ + 255) / 256, 256>>>(qkvp, QKV_DIM, cosb, sinb, N_H, qh, ql);
        rope_split_kernel<<<(totK + 255) / 256, 256>>>(qkvp + 2048, QKV_DIM, cosb, sinb, N_KV, kh, kl);
        split_strided_kernel<<<nSml / 1024, 256>>>(qkvp + 2560, QKV_DIM, KV_DIM, vh, vl, nSml);
    }

    // 3) causal scores
    scores_pre_kernel<<<dim3(S_LEN / 128, S_LEN / 128, N_H), 128, GEMM_SMEM>>>(attnBuf);

    // 4) entmax in place
    entmax_kernel<<<N_H * S_LEN, 256>>>(attnBuf);

    // 5) attn @ v -> ctx, then split ctx
    av_kernel<<<dim3(1, S_LEN / 128, N_H), 256>>>(attnBuf);
    split_kernel<<<nBig / 1024, 256>>>(cp, cth, ctl, nBig);

    // 6) out = ctx @ wo^T
    gemm_pre_kernel<<<dim3(D_MODEL / 128, S_LEN / 128), 128, GEMM_SMEM>>>(
        cth, ctl, woh, wol, out, D_MODEL, D_MODEL);
}

// round 10
// speedup vs baseline: 1.4343x; 1.1590x over previous
#include <cuda_runtime.h>
#include <cuda_bf16.h>
#include <mma.h>
#include <math.h>
#include <stdint.h>

using namespace nvcuda;

#define S_LEN 2048
#define D_MODEL 2048
#define N_H 16
#define N_KV 4
#define H_DIM 128
#define SCALING 0.08838834764831845f
#define DM0 0.9779029130879204f
#define KV_DIM (N_KV * H_DIM)
#define QKV_DIM (N_H * H_DIM + 2 * KV_DIM)   // 3072

typedef __nv_bfloat16 bf16;

// fp32 scratch
__device__ float g_qkv[(size_t)S_LEN * QKV_DIM];
__device__ float g_ctx[(size_t)S_LEN * N_H * H_DIM];
__device__ float g_attn[(size_t)N_H * S_LEN * S_LEN];

// pre-split bf16 hi/lo scratch
#define SZ_BIG  ((size_t)2048 * 2048)
#define SZ_SML  ((size_t)2048 * 512)
#define SZ_W    ((size_t)3072 * 2048)
#define SZ_ATT  ((size_t)N_H * S_LEN * S_LEN)
__device__ bf16 g_hsh[SZ_BIG], g_hsl[SZ_BIG];
__device__ bf16 g_wh[SZ_W],    g_wl[SZ_W];      // fused [wq; wk; wv]
__device__ bf16 g_woh[SZ_BIG], g_wol[SZ_BIG];
__device__ bf16 g_qh[SZ_BIG],  g_ql[SZ_BIG];
__device__ bf16 g_kh[SZ_SML],  g_kl[SZ_SML];
__device__ bf16 g_vh[SZ_SML],  g_vl[SZ_SML];
__device__ bf16 g_cth[SZ_BIG], g_ctl[SZ_BIG];
__device__ bf16 g_ath[SZ_ATT], g_atl[SZ_ATT];   // split attn (written by entmax)

__device__ __forceinline__ void split_bf16(float v, bf16& hi, bf16& lo) {
    hi = __float2bfloat16_rn(v);
    lo = __float2bfloat16_rn(v - __bfloat162float(hi));
}
__device__ __forceinline__ uint32_t smem_u32(const void* p) {
    return (uint32_t)__cvta_generic_to_shared(p);
}
#define CP16(dst, src) asm volatile("cp.async.cg.shared.global [%0], [%1], 16;" :: "r"(dst), "l"(src))
#define CP_COMMIT()    asm volatile("cp.async.commit_group;" ::: "memory")
#define CP_WAIT1()     asm volatile("cp.async.wait_group 1;" ::: "memory")
#define CP_WAIT0()     asm volatile("cp.async.wait_group 0;" ::: "memory")

// ===========================================================================
// split kernels
// ===========================================================================
__global__ void split_kernel(const float* __restrict__ x,
                             bf16* __restrict__ hi, bf16* __restrict__ lo, int n)
{
    int i = (blockIdx.x * blockDim.x + threadIdx.x) * 4;
    if (i >= n) return;
    float4 v = *(const float4*)(x + i);
    bf16 h0, l0, h1, l1, h2, l2, h3, l3;
    split_bf16(v.x, h0, l0); split_bf16(v.y, h1, l1);
    split_bf16(v.z, h2, l2); split_bf16(v.w, h3, l3);
    __nv_bfloat162* H = (__nv_bfloat162*)(hi + i);
    __nv_bfloat162* L = (__nv_bfloat162*)(lo + i);
    H[0] = __halves2bfloat162(h0, h1); H[1] = __halves2bfloat162(h2, h3);
    L[0] = __halves2bfloat162(l0, l1); L[1] = __halves2bfloat162(l2, l3);
}

__global__ void split_strided_kernel(const float* __restrict__ x, int srcStride, int width,
                                     bf16* __restrict__ hi, bf16* __restrict__ lo, int n)
{
    int i = (blockIdx.x * blockDim.x + threadIdx.x) * 4;
    if (i >= n) return;
    int s = i / width;
    int c = i - s * width;
    float4 v = *(const float4*)(x + (size_t)s * srcStride + c);
    bf16 h0, l0, h1, l1, h2, l2, h3, l3;
    split_bf16(v.x, h0, l0); split_bf16(v.y, h1, l1);
    split_bf16(v.z, h2, l2); split_bf16(v.w, h3, l3);
    __nv_bfloat162* H = (__nv_bfloat162*)(hi + i);
    __nv_bfloat162* L = (__nv_bfloat162*)(lo + i);
    H[0] = __halves2bfloat162(h0, h1); H[1] = __halves2bfloat162(h2, h3);
    L[0] = __halves2bfloat162(l0, l1); L[1] = __halves2bfloat162(l2, l3);
}

// ===========================================================================
// RoPE + split
// ===========================================================================
__global__ void rope_split_kernel(const float* __restrict__ X, int xStride,
                                  const float* __restrict__ cosb,
                                  const float* __restrict__ sinb, int nHeads,
                                  bf16* __restrict__ hi, bf16* __restrict__ lo)
{
    int idx = blockIdx.x * blockDim.x + threadIdx.x;
    int total = S_LEN * nHeads * (H_DIM / 2);
    if (idx >= total) return;
    int d = idx & 63;
    int t = idx >> 6;
    int hh = t % nHeads;
    int s  = t / nHeads;
    float c1 = cosb[s * H_DIM + d];
    float s1 = sinb[s * H_DIM + d];
    float c2 = cosb[s * H_DIM + d + 64];
    float s2 = sinb[s * H_DIM + d + 64];
    size_t src = (size_t)s * xStride + (size_t)hh * H_DIM + d;
    size_t dst = (size_t)s * nHeads * H_DIM + (size_t)hh * H_DIM + d;
    float x1 = X[src];
    float x2 = X[src + 64];
    float y1 = x1 * c1 - x2 * s1;
    float y2 = x2 * c2 + x1 * s2;
    bf16 h, l;
    split_bf16(y1, h, l); hi[dst] = h;      lo[dst] = l;
    split_bf16(y2, h, l); hi[dst + 64] = h; lo[dst + 64] = l;
}

// ===========================================================================
// Pipelined split-bf16 NT GEMM core: BM=BN=128, BK=32, 128 threads (4 warps),
// warp tile 64x64, 2-stage cp.async, 80KB SMEM -> 2 CTAs/SM.
// ===========================================================================
#define GEMM_SMEM (2 * 20480 * (int)sizeof(bf16))

__device__ __forceinline__ void gemm_core(
    const bf16* __restrict__ Ah, const bf16* __restrict__ Al,
    const bf16* __restrict__ Bh, const bf16* __restrict__ Bl,
    int lda, int ldb, int K, int mBase, int nBase,
    float* __restrict__ C, int ldc, float scale)
{
    extern __shared__ bf16 sm[];
    const int tid = threadIdx.x;          // 0..127
    const int warp = tid >> 5;            // 0..3
    const int wm = warp >> 1;             // 0..1 (m group of 64)
    const int wn = warp & 1;              // 0..1 (n group of 64)

    wmma::fragment<wmma::accumulator, 16, 16, 16, float> acc[4][4];
#pragma unroll
    for (int i = 0; i < 4; i++)
#pragma unroll
        for (int j = 0; j < 4; j++) wmma::fill_fragment(acc[i][j], 0.0f);

    const bf16* Ap_h = Ah + (size_t)(mBase + tid) * lda;
    const bf16* Ap_l = Al + (size_t)(mBase + tid) * lda;
    const bf16* Bp_h = Bh + (size_t)(nBase + tid) * ldb;
    const bf16* Bp_l = Bl + (size_t)(nBase + tid) * ldb;
    const uint32_t dbase = smem_u32(sm) + tid * 80;

    const int T = K >> 5;

#define LOAD_STAGE(buf, k0) do { \
        uint32_t d = dbase + (buf) * 40960; \
        CP16(d,          Ap_h + (k0));      CP16(d + 16,          Ap_h + (k0) + 8); \
        CP16(d + 32,     Ap_h + (k0) + 16); CP16(d + 48,          Ap_h + (k0) + 24); \
        CP16(d + 10240,      Ap_l + (k0));      CP16(d + 10240 + 16, Ap_l + (k0) + 8); \
        CP16(d + 10240 + 32, Ap_l + (k0) + 16); CP16(d + 10240 + 48, Ap_l + (k0) + 24); \
        CP16(d + 20480,      Bp_h + (k0));      CP16(d + 20480 + 16, Bp_h + (k0) + 8); \
        CP16(d + 20480 + 32, Bp_h + (k0) + 16); CP16(d + 20480 + 48, Bp_h + (k0) + 24); \
        CP16(d + 30720,      Bp_l + (k0));      CP16(d + 30720 + 16, Bp_l + (k0) + 8); \
        CP16(d + 30720 + 32, Bp_l + (k0) + 16); CP16(d + 30720 + 48, Bp_l + (k0) + 24); \
        CP_COMMIT(); \
    } while (0)

    LOAD_STAGE(0, 0);

#pragma unroll 1
    for (int t = 0; t < T; t++) {
        if (t + 1 < T) {
            LOAD_STAGE((t + 1) & 1, (t + 1) * 32);
            CP_WAIT1();
        } else {
            CP_WAIT0();
        }
        __syncthreads();

        bf16* st   = sm + (t & 1) * 20480;
        bf16* Ah_s = st;
        bf16* Al_s = st + 5120;
        bf16* Bh_s = st + 10240;
        bf16* Bl_s = st + 15360;
#pragma unroll
        for (int ks = 0; ks < 32; ks += 16) {
            wmma::fragment<wmma::matrix_b, 16, 16, 16, bf16, wmma::col_major> bh[4], bl[4];
#pragma unroll
            for (int j = 0; j < 4; j++) {
                wmma::load_matrix_sync(bh[j], &Bh_s[(wn * 64 + j * 16) * 40 + ks], 40);
                wmma::load_matrix_sync(bl[j], &Bl_s[(wn * 64 + j * 16) * 40 + ks], 40);
            }
#pragma unroll
            for (int i = 0; i < 4; i++) {
                wmma::fragment<wmma::matrix_a, 16, 16, 16, bf16, wmma::row_major> ah, al;
                wmma::load_matrix_sync(ah, &Ah_s[(wm * 64 + i * 16) * 40 + ks], 40);
                wmma::load_matrix_sync(al, &Al_s[(wm * 64 + i * 16) * 40 + ks], 40);
#pragma unroll
                for (int j = 0; j < 4; j++) {
                    wmma::mma_sync(acc[i][j], ah, bl[j], acc[i][j]);
                    wmma::mma_sync(acc[i][j], al, bh[j], acc[i][j]);
                    wmma::mma_sync(acc[i][j], ah, bh[j], acc[i][j]);
                }
            }
        }
        __syncthreads();
    }
#undef LOAD_STAGE

#pragma unroll
    for (int i = 0; i < 4; i++)
#pragma unroll
        for (int j = 0; j < 4; j++) {
#pragma unroll
            for (int t = 0; t < acc[i][j].num_elements; t++) acc[i][j].x[t] *= scale;
            wmma::store_matrix_sync(
                C + (size_t)(mBase + wm * 64 + i * 16) * ldc + nBase + wn * 64 + j * 16,
                acc[i][j], ldc, wmma::mem_row_major);
        }
}

__global__ void __launch_bounds__(128) gemm_pre_kernel(
    const bf16* Ah, const bf16* Al, const bf16* Bh, const bf16* Bl,
    float* C, int ldc, int K)
{
    gemm_core(Ah, Al, Bh, Bl, K, K, K, blockIdx.y * 128, blockIdx.x * 128, C, ldc, 1.0f);
}

__global__ void __launch_bounds__(128) scores_pre_kernel(float* __restrict__ attn)
{
    const int h = blockIdx.z;
    const int mBase = blockIdx.y * 128;
    const int nBase = blockIdx.x * 128;
    if (nBase > mBase + 127) return;
    gemm_core(g_qh + h * H_DIM, g_ql + h * H_DIM,
              g_kh + (h >> 2) * H_DIM, g_kl + (h >> 2) * H_DIM,
              N_H * H_DIM, KV_DIM, H_DIM, mBase, nBase,
              attn + (size_t)h * S_LEN * S_LEN, S_LEN, SCALING);
}

// ===========================================================================
// alpha-entmax (alpha=1.5), 32-iter bisection, ONE WARP PER ROW (shfl only).
// Also emits bf16 hi/lo split of the attn row for the AV GEMM.
// ===========================================================================
template <int CH>
__device__ __forceinline__ void entmax_row_warp(float* __restrict__ x,
                                                bf16* __restrict__ xh,
                                                bf16* __restrict__ xl,
                                                int n, int lane)
{
    float X[CH];
    float lmax = -INFINITY;
#pragma unroll
    for (int i = 0; i < CH; i++) {
        int j = lane + i * 32;
        if (j < n) {
            float v = x[j] * 0.5f;
            X[i] = v;
            lmax = fmaxf(lmax, v);
        } else {
            X[i] = -INFINITY;
        }
    }
#pragma unroll
    for (int o = 16; o > 0; o >>= 1) lmax = fmaxf(lmax, __shfl_xor_sync(0xffffffffu, lmax, o));

    float tau_lo = lmax - 1.0f;
    float dm = DM0;
    float tau_m = tau_lo;
#pragma unroll 1
    for (int it = 0; it < 32; it++) {
        dm *= 0.5f;
        tau_m = tau_lo + dm;
        float ls = 0.f;
#pragma unroll
        for (int i = 0; i < CH; i++) {
            float t = fmaxf(X[i] - tau_m, 0.f);
            ls = fmaf(t, t, ls);
        }
#pragma unroll
        for (int o = 16; o > 0; o >>= 1) ls += __shfl_xor_sync(0xffffffffu, ls, o);
        if (ls >= 1.0f) tau_lo = tau_m;
    }

    float ls = 0.f;
#pragma unroll
    for (int i = 0; i < CH; i++) {
        float t = fmaxf(X[i] - tau_m, 0.f);
        ls = fmaf(t, t, ls);
    }
#pragma unroll
    for (int o = 16; o > 0; o >>= 1) ls += __shfl_xor_sync(0xffffffffu, ls, o);
    float inv = 1.0f / ls;

#pragma unroll
    for (int i = 0; i < CH; i++) {
        int j = lane + i * 32;
        float t = fmaxf(X[i] - tau_m, 0.f);
        float v = (j < n) ? t * t * inv : 0.0f;
        x[j] = v;
        bf16 h, l;
        split_bf16(v, h, l);
        xh[j] = h; xl[j] = l;
    }
#pragma unroll
    for (int i = CH; i < 64; i++) {
        int j = lane + i * 32;
        x[j] = 0.0f;
        xh[j] = __float2bfloat16_rn(0.0f);
        xl[j] = __float2bfloat16_rn(0.0f);
    }
}

__global__ void __launch_bounds__(256) entmax_kernel(float* __restrict__ attn,
                                                     bf16* __restrict__ ath,
                                                     bf16* __restrict__ atl)
{
    const int idx = blockIdx.x * 8 + (threadIdx.x >> 5);   // global row id
    const int lane = threadIdx.x & 31;
    const int h = idx >> 11;
    const int q = idx & 2047;
    size_t off = (size_t)h * S_LEN * S_LEN + (size_t)q * S_LEN;
    float* x = attn + off;
    bf16* xh = ath + off;
    bf16* xl = atl + off;
    const int n = q + 1;
    const int c8 = (((n + 31) >> 5) + 7) >> 3;   // chunks of 32, rounded up to mult of 8

    switch (c8) {
        case 1: entmax_row_warp<8>(x, xh, xl, n, lane); break;
        case 2: entmax_row_warp<16>(x, xh, xl, n, lane); break;
        case 3: entmax_row_warp<24>(x, xh, xl, n, lane); break;
        case 4: entmax_row_warp<32>(x, xh, xl, n, lane); break;
        case 5: entmax_row_warp<40>(x, xh, xl, n, lane); break;
        case 6: entmax_row_warp<48>(x, xh, xl, n, lane); break;
        case 7: entmax_row_warp<56>(x, xh, xl, n, lane); break;
        default: entmax_row_warp<64>(x, xh, xl, n, lane); break;
    }
}

// ===========================================================================
// attn @ V: both operands pre-split bf16, pipelined cp.async double buffer.
// 128x128 C tile, BK=32, 256 threads, warp tile 32x64.
// Stage layout (bytes): Ah[128x40]@0, Al@10240, Bh[32x136]@20480, Bl@29184.
// Stage = 37888 B, 2 stages = 75776 B.
// ===========================================================================
#define AV_STAGE 37888
#define AV_SMEM  (2 * AV_STAGE)

__global__ void __launch_bounds__(256) av_kernel()
{
    extern __shared__ bf16 sm[];
    const int h = blockIdx.z;
    const int mBase = (gridDim.y - 1 - blockIdx.y) * 128;

    const int tid = threadIdx.x;
    const int warp = tid >> 5;
    const int wm = warp & 3;
    const int wn = warp >> 2;

    const size_t aoff = (size_t)h * S_LEN * S_LEN;
    const bf16* Ah_g = g_ath + aoff;
    const bf16* Al_g = g_atl + aoff;
    const bf16* Bh_g = g_vh + (h >> 2) * H_DIM;
    const bf16* Bl_g = g_vl + (h >> 2) * H_DIM;

    // A loader indices: row = tid>>1 (0..127), col = (tid&1)*16 (2x CP16)
    const int rA = tid >> 1;
    const int cA = (tid & 1) * 16;
    // B loader indices: krow = tid>>3 (0..31), col = (tid&7)*16 (2x CP16)
    const int rB = tid >> 3;
    const int cB = (tid & 7) * 16;

    const bf16* ApH = Ah_g + (size_t)(mBase + rA) * S_LEN + cA;
    const bf16* ApL = Al_g + (size_t)(mBase + rA) * S_LEN + cA;
    const bf16* BpH = Bh_g + (size_t)rB * KV_DIM + cB;
    const bf16* BpL = Bl_g + (size_t)rB * KV_DIM + cB;

    const uint32_t sb = smem_u32(sm);
    const uint32_t dA = sb + rA * 80 + cA * 2;
    const uint32_t dB = sb + 20480 + rB * 272 + cB * 2;

    wmma::fragment<wmma::accumulator, 16, 16, 16, float> acc[2][4];
#pragma unroll
    for (int i = 0; i < 2; i++)
#pragma unroll
        for (int j = 0; j < 4; j++) wmma::fill_fragment(acc[i][j], 0.0f);

    const int T = (mBase + 128) >> 5;

#define AV_LOAD(buf, k0) do { \
        uint32_t da = dA + (buf) * AV_STAGE; \
        CP16(da,          ApH + (k0)); CP16(da + 16,          ApH + (k0) + 8); \
        CP16(da + 10240,  ApL + (k0)); CP16(da + 10240 + 16,  ApL + (k0) + 8); \
        uint32_t db = dB + (buf) * AV_STAGE; \
        CP16(db,          BpH + (size_t)(k0) * KV_DIM); CP16(db + 16, BpH + (size_t)(k0) * KV_DIM + 8); \
        CP16(db + 8704,   BpL + (size_t)(k0) * KV_DIM); CP16(db + 8704 + 16, BpL + (size_t)(k0) * KV_DIM + 8); \
        CP_COMMIT(); \
    } while (0)

    AV_LOAD(0, 0);

#pragma unroll 1
    for (int t = 0; t < T; t++) {
        if (t + 1 < T) {
            AV_LOAD((t + 1) & 1, (t + 1) * 32);
            CP_WAIT1();
        } else {
            CP_WAIT0();
        }
        __syncthreads();

        bf16* st   = sm + (t & 1) * (AV_STAGE / 2);
        bf16* Ah_s = st;
        bf16* Al_s = st + 5120;
        bf16* Bh_s = st + 10240;
        bf16* Bl_s = st + 14592;
#pragma unroll
        for (int ks = 0; ks < 32; ks += 16) {
            wmma::fragment<wmma::matrix_a, 16, 16, 16, bf16, wmma::row_major> ah[2], al[2];
            wmma::fragment<wmma::matrix_b, 16, 16, 16, bf16, wmma::row_major> bh[4], bl[4];
#pragma unroll
            for (int i = 0; i < 2; i++) {
                wmma::load_matrix_sync(ah[i], &Ah_s[(wm * 32 + i * 16) * 40 + ks], 40);
                wmma::load_matrix_sync(al[i], &Al_s[(wm * 32 + i * 16) * 40 + ks], 40);
            }
#pragma unroll
            for (int j = 0; j < 4; j++) {
                wmma::load_matrix_sync(bh[j], &Bh_s[ks * 136 + wn * 64 + j * 16], 136);
                wmma::load_matrix_sync(bl[j], &Bl_s[ks * 136 + wn * 64 + j * 16], 136);
            }
#pragma unroll
            for (int i = 0; i < 2; i++)
#pragma unroll
                for (int j = 0; j < 4; j++) {
                    wmma::mma_sync(acc[i][j], ah[i], bl[j], acc[i][j]);
                    wmma::mma_sync(acc[i][j], al[i], bh[j], acc[i][j]);
                    wmma::mma_sync(acc[i][j], ah[i], bh[j], acc[i][j]);
                }
        }
        __syncthreads();
    }
#undef AV_LOAD

#pragma unroll
    for (int i = 0; i < 2; i++)
#pragma unroll
        for (int j = 0; j < 4; j++)
            wmma::store_matrix_sync(
                g_ctx + (size_t)(mBase + wm * 32 + i * 16) * (N_H * H_DIM)
                      + h * H_DIM + wn * 64 + j * 16,
                acc[i][j], N_H * H_DIM, wmma::mem_row_major);
}

// ===========================================================================
extern "C" void kernel_launch(void* const* d_in, const int* in_sizes, int n_in,
                              void* d_out, int out_size)
{
    const float* hs   = (const float*)d_in[0];
    const float* cosb = (const float*)d_in[1];
    const float* sinb = (const float*)d_in[2];
    const float* wq   = (const float*)d_in[3];
    const float* wk   = (const float*)d_in[4];
    const float* wv   = (const float*)d_in[5];
    const float* wo   = (const float*)d_in[6];
    float* out = (float*)d_out;

    float *qkvp, *cp, *ap;
    cudaGetSymbolAddress((void**)&qkvp, g_qkv);
    cudaGetSymbolAddress((void**)&cp, g_ctx);
    cudaGetSymbolAddress((void**)&ap, g_attn);

    bf16 *hsh, *hsl, *wh, *wl, *woh, *wol;
    bf16 *qh, *ql, *kh, *kl, *vh, *vl, *cth, *ctl, *ath, *atl;
    cudaGetSymbolAddress((void**)&hsh, g_hsh); cudaGetSymbolAddress((void**)&hsl, g_hsl);
    cudaGetSymbolAddress((void**)&wh, g_wh);   cudaGetSymbolAddress((void**)&wl, g_wl);
    cudaGetSymbolAddress((void**)&woh, g_woh); cudaGetSymbolAddress((void**)&wol, g_wol);
    cudaGetSymbolAddress((void**)&qh, g_qh);   cudaGetSymbolAddress((void**)&ql, g_ql);
    cudaGetSymbolAddress((void**)&kh, g_kh);   cudaGetSymbolAddress((void**)&kl, g_kl);
    cudaGetSymbolAddress((void**)&vh, g_vh);   cudaGetSymbolAddress((void**)&vl, g_vl);
    cudaGetSymbolAddress((void**)&cth, g_cth); cudaGetSymbolAddress((void**)&ctl, g_ctl);
    cudaGetSymbolAddress((void**)&ath, g_ath); cudaGetSymbolAddress((void**)&atl, g_atl);

    const size_t need = (size_t)S_LEN * D_MODEL + (size_t)N_H * S_LEN * S_LEN;
    float* attnBuf = ((size_t)out_size >= need) ? (out + (size_t)S_LEN * D_MODEL) : ap;

    cudaFuncSetAttribute(gemm_pre_kernel, cudaFuncAttributeMaxDynamicSharedMemorySize, GEMM_SMEM);
    cudaFuncSetAttribute(scores_pre_kernel, cudaFuncAttributeMaxDynamicSharedMemorySize, GEMM_SMEM);
    cudaFuncSetAttribute(av_kernel, cudaFuncAttributeMaxDynamicSharedMemorySize, AV_SMEM);

    const int nBig = 2048 * 2048, nSml = 2048 * 512;

    // 0) pre-split inputs; weights into fused [wq; wk; wv] layout
    split_kernel<<<nBig / 1024, 256>>>(hs, hsh, hsl, nBig);
    split_kernel<<<nBig / 1024, 256>>>(wq, wh, wl, nBig);
    split_kernel<<<nSml / 1024, 256>>>(wk, wh + (size_t)2048 * 2048, wl + (size_t)2048 * 2048, nSml);
    split_kernel<<<nSml / 1024, 256>>>(wv, wh + (size_t)2560 * 2048, wl + (size_t)2560 * 2048, nSml);
    split_kernel<<<nBig / 1024, 256>>>(wo, woh, wol, nBig);

    // 1) fused qkv projection: [2048 x 3072] = hs @ [wq;wk;wv]^T
    gemm_pre_kernel<<<dim3(QKV_DIM / 128, S_LEN / 128), 128, GEMM_SMEM>>>(
        hsh, hsl, wh, wl, qkvp, QKV_DIM, D_MODEL);

    // 2) RoPE + split (q, k); strided split v
    {
        int totQ = S_LEN * N_H * (H_DIM / 2);
        int totK = S_LEN * N_KV * (H_DIM / 2);
        rope_split_kernel<<<(totQ + 255) / 256, 256>>>(qkvp, QKV_DIM, cosb, sinb, N_H, qh, ql);
        rope_split_kernel<<<(totK + 255) / 256, 256>>>(qkvp + 2048, QKV_DIM, cosb, sinb, N_KV, kh, kl);
        split_strided_kernel<<<nSml / 1024, 256>>>(qkvp + 2560, QKV_DIM, KV_DIM, vh, vl, nSml);
    }

    // 3) causal scores
    scores_pre_kernel<<<dim3(S_LEN / 128, S_LEN / 128, N_H), 128, GEMM_SMEM>>>(attnBuf);

    // 4) entmax in place (warp-per-row) + emit bf16 hi/lo attn
    entmax_kernel<<<(N_H * S_LEN) / 8, 256>>>(attnBuf, ath, atl);

    // 5) attn @ v -> ctx (pre-split operands), then split ctx
    av_kernel<<<dim3(1, S_LEN / 128, N_H), 256, AV_SMEM>>>();
    split_kernel<<<nBig / 1024, 256>>>(cp, cth, ctl, nBig);

    // 6) out = ctx @ wo^T
    gemm_pre_kernel<<<dim3(D_MODEL / 128, S_LEN / 128), 128, GEMM_SMEM>>>(
        cth, ctl, woh, wol, out, D_MODEL, D_MODEL);
}

// round 11
// speedup vs baseline: 1.5669x; 1.0925x over previous
#include <cuda_runtime.h>
#include <cuda_bf16.h>
#include <cuda_fp16.h>
#include <mma.h>
#include <math.h>
#include <stdint.h>

using namespace nvcuda;

#define S_LEN 2048
#define D_MODEL 2048
#define N_H 16
#define N_KV 4
#define H_DIM 128
#define SCALING 0.08838834764831845f
#define DM0 0.9779029130879204f
#define KV_DIM (N_KV * H_DIM)
#define QKV_DIM (N_H * H_DIM + 2 * KV_DIM)   // 3072

typedef __nv_bfloat16 bf16;
typedef __half fp16;

// fp32 scratch
__device__ float g_qkv[(size_t)S_LEN * QKV_DIM];
__device__ float g_ctx[(size_t)S_LEN * N_H * H_DIM];
__device__ float g_attn[(size_t)N_H * S_LEN * S_LEN];

// pre-split scratch
#define SZ_BIG  ((size_t)2048 * 2048)
#define SZ_SML  ((size_t)2048 * 512)
#define SZ_W    ((size_t)3072 * 2048)
#define SZ_ATT  ((size_t)N_H * S_LEN * S_LEN)
__device__ bf16 g_hsh[SZ_BIG], g_hsl[SZ_BIG];
__device__ bf16 g_wh[SZ_W],    g_wl[SZ_W];      // fused [wq; wk; wv]
__device__ bf16 g_qh[SZ_BIG],  g_ql[SZ_BIG];
__device__ bf16 g_kh[SZ_SML],  g_kl[SZ_SML];
__device__ bf16 g_vh[SZ_SML],  g_vl[SZ_SML];
__device__ bf16 g_ath[SZ_ATT], g_atl[SZ_ATT];   // split attn (written by entmax)
// fp16 planes for the 2-product wo GEMM
__device__ fp16 g_ch16[SZ_BIG], g_cl16[SZ_BIG];
__device__ fp16 g_wo16[SZ_BIG];

__device__ __forceinline__ void split_bf16(float v, bf16& hi, bf16& lo) {
    hi = __float2bfloat16_rn(v);
    lo = __float2bfloat16_rn(v - __bfloat162float(hi));
}
__device__ __forceinline__ uint32_t smem_u32(const void* p) {
    return (uint32_t)__cvta_generic_to_shared(p);
}
#define CP16(dst, src) asm volatile("cp.async.cg.shared.global [%0], [%1], 16;" :: "r"(dst), "l"(src))
#define CP_COMMIT()    asm volatile("cp.async.commit_group;" ::: "memory")
#define CP_WAIT1()     asm volatile("cp.async.wait_group 1;" ::: "memory")
#define CP_WAIT0()     asm volatile("cp.async.wait_group 0;" ::: "memory")

// ===========================================================================
// split kernels
// ===========================================================================
__global__ void split_kernel(const float* __restrict__ x,
                             bf16* __restrict__ hi, bf16* __restrict__ lo, int n)
{
    int i = (blockIdx.x * blockDim.x + threadIdx.x) * 4;
    if (i >= n) return;
    float4 v = *(const float4*)(x + i);
    bf16 h0, l0, h1, l1, h2, l2, h3, l3;
    split_bf16(v.x, h0, l0); split_bf16(v.y, h1, l1);
    split_bf16(v.z, h2, l2); split_bf16(v.w, h3, l3);
    __nv_bfloat162* H = (__nv_bfloat162*)(hi + i);
    __nv_bfloat162* L = (__nv_bfloat162*)(lo + i);
    H[0] = __halves2bfloat162(h0, h1); H[1] = __halves2bfloat162(h2, h3);
    L[0] = __halves2bfloat162(l0, l1); L[1] = __halves2bfloat162(l2, l3);
}

__global__ void split_strided_kernel(const float* __restrict__ x, int srcStride, int width,
                                     bf16* __restrict__ hi, bf16* __restrict__ lo, int n)
{
    int i = (blockIdx.x * blockDim.x + threadIdx.x) * 4;
    if (i >= n) return;
    int s = i / width;
    int c = i - s * width;
    float4 v = *(const float4*)(x + (size_t)s * srcStride + c);
    bf16 h0, l0, h1, l1, h2, l2, h3, l3;
    split_bf16(v.x, h0, l0); split_bf16(v.y, h1, l1);
    split_bf16(v.z, h2, l2); split_bf16(v.w, h3, l3);
    __nv_bfloat162* H = (__nv_bfloat162*)(hi + i);
    __nv_bfloat162* L = (__nv_bfloat162*)(lo + i);
    H[0] = __halves2bfloat162(h0, h1); H[1] = __halves2bfloat162(h2, h3);
    L[0] = __halves2bfloat162(l0, l1); L[1] = __halves2bfloat162(l2, l3);
}

// fp32 -> fp16 hi/lo pair
__global__ void split16_pair_kernel(const float* __restrict__ x,
                                    fp16* __restrict__ hi, fp16* __restrict__ lo, int n)
{
    int i = (blockIdx.x * blockDim.x + threadIdx.x) * 4;
    if (i >= n) return;
    float4 v = *(const float4*)(x + i);
    fp16 h[4], l[4];
    const float* p = (const float*)&v;
#pragma unroll
    for (int e = 0; e < 4; e++) {
        h[e] = __float2half_rn(p[e]);
        l[e] = __float2half_rn(p[e] - __half2float(h[e]));
    }
    __half2* H = (__half2*)(hi + i);
    __half2* L = (__half2*)(lo + i);
    H[0] = __halves2half2(h[0], h[1]); H[1] = __halves2half2(h[2], h[3]);
    L[0] = __halves2half2(l[0], l[1]); L[1] = __halves2half2(l[2], l[3]);
}

// fp32 -> fp16 single plane
__global__ void split16_single_kernel(const float* __restrict__ x,
                                      fp16* __restrict__ h, int n)
{
    int i = (blockIdx.x * blockDim.x + threadIdx.x) * 4;
    if (i >= n) return;
    float4 v = *(const float4*)(x + i);
    __half2* H = (__half2*)(h + i);
    H[0] = __halves2half2(__float2half_rn(v.x), __float2half_rn(v.y));
    H[1] = __halves2half2(__float2half_rn(v.z), __float2half_rn(v.w));
}

// ===========================================================================
// RoPE + split
// ===========================================================================
__global__ void rope_split_kernel(const float* __restrict__ X, int xStride,
                                  const float* __restrict__ cosb,
                                  const float* __restrict__ sinb, int nHeads,
                                  bf16* __restrict__ hi, bf16* __restrict__ lo)
{
    int idx = blockIdx.x * blockDim.x + threadIdx.x;
    int total = S_LEN * nHeads * (H_DIM / 2);
    if (idx >= total) return;
    int d = idx & 63;
    int t = idx >> 6;
    int hh = t % nHeads;
    int s  = t / nHeads;
    float c1 = cosb[s * H_DIM + d];
    float s1 = sinb[s * H_DIM + d];
    float c2 = cosb[s * H_DIM + d + 64];
    float s2 = sinb[s * H_DIM + d + 64];
    size_t src = (size_t)s * xStride + (size_t)hh * H_DIM + d;
    size_t dst = (size_t)s * nHeads * H_DIM + (size_t)hh * H_DIM + d;
    float x1 = X[src];
    float x2 = X[src + 64];
    float y1 = x1 * c1 - x2 * s1;
    float y2 = x2 * c2 + x1 * s2;
    bf16 h, l;
    split_bf16(y1, h, l); hi[dst] = h;      lo[dst] = l;
    split_bf16(y2, h, l); hi[dst + 64] = h; lo[dst + 64] = l;
}

// ===========================================================================
// Pipelined split-bf16 NT GEMM core: BM=BN=128, BK=32, 128 threads (4 warps),
// warp tile 64x64, 2-stage cp.async, 80KB SMEM.
// ===========================================================================
#define GEMM_SMEM (2 * 20480 * (int)sizeof(bf16))

__device__ __forceinline__ void gemm_core(
    const bf16* __restrict__ Ah, const bf16* __restrict__ Al,
    const bf16* __restrict__ Bh, const bf16* __restrict__ Bl,
    int lda, int ldb, int K, int mBase, int nBase,
    float* __restrict__ C, int ldc, float scale)
{
    extern __shared__ bf16 sm[];
    const int tid = threadIdx.x;          // 0..127
    const int warp = tid >> 5;            // 0..3
    const int wm = warp >> 1;             // 0..1 (m group of 64)
    const int wn = warp & 1;              // 0..1 (n group of 64)

    wmma::fragment<wmma::accumulator, 16, 16, 16, float> acc[4][4];
#pragma unroll
    for (int i = 0; i < 4; i++)
#pragma unroll
        for (int j = 0; j < 4; j++) wmma::fill_fragment(acc[i][j], 0.0f);

    const bf16* Ap_h = Ah + (size_t)(mBase + tid) * lda;
    const bf16* Ap_l = Al + (size_t)(mBase + tid) * lda;
    const bf16* Bp_h = Bh + (size_t)(nBase + tid) * ldb;
    const bf16* Bp_l = Bl + (size_t)(nBase + tid) * ldb;
    const uint32_t dbase = smem_u32(sm) + tid * 80;

    const int T = K >> 5;

#define LOAD_STAGE(buf, k0) do { \
        uint32_t d = dbase + (buf) * 40960; \
        CP16(d,          Ap_h + (k0));      CP16(d + 16,          Ap_h + (k0) + 8); \
        CP16(d + 32,     Ap_h + (k0) + 16); CP16(d + 48,          Ap_h + (k0) + 24); \
        CP16(d + 10240,      Ap_l + (k0));      CP16(d + 10240 + 16, Ap_l + (k0) + 8); \
        CP16(d + 10240 + 32, Ap_l + (k0) + 16); CP16(d + 10240 + 48, Ap_l + (k0) + 24); \
        CP16(d + 20480,      Bp_h + (k0));      CP16(d + 20480 + 16, Bp_h + (k0) + 8); \
        CP16(d + 20480 + 32, Bp_h + (k0) + 16); CP16(d + 20480 + 48, Bp_h + (k0) + 24); \
        CP16(d + 30720,      Bp_l + (k0));      CP16(d + 30720 + 16, Bp_l + (k0) + 8); \
        CP16(d + 30720 + 32, Bp_l + (k0) + 16); CP16(d + 30720 + 48, Bp_l + (k0) + 24); \
        CP_COMMIT(); \
    } while (0)

    LOAD_STAGE(0, 0);

#pragma unroll 1
    for (int t = 0; t < T; t++) {
        if (t + 1 < T) {
            LOAD_STAGE((t + 1) & 1, (t + 1) * 32);
            CP_WAIT1();
        } else {
            CP_WAIT0();
        }
        __syncthreads();

        bf16* st   = sm + (t & 1) * 20480;
        bf16* Ah_s = st;
        bf16* Al_s = st + 5120;
        bf16* Bh_s = st + 10240;
        bf16* Bl_s = st + 15360;
#pragma unroll
        for (int ks = 0; ks < 32; ks += 16) {
            wmma::fragment<wmma::matrix_b, 16, 16, 16, bf16, wmma::col_major> bh[4], bl[4];
#pragma unroll
            for (int j = 0; j < 4; j++) {
                wmma::load_matrix_sync(bh[j], &Bh_s[(wn * 64 + j * 16) * 40 + ks], 40);
                wmma::load_matrix_sync(bl[j], &Bl_s[(wn * 64 + j * 16) * 40 + ks], 40);
            }
#pragma unroll
            for (int i = 0; i < 4; i++) {
                wmma::fragment<wmma::matrix_a, 16, 16, 16, bf16, wmma::row_major> ah, al;
                wmma::load_matrix_sync(ah, &Ah_s[(wm * 64 + i * 16) * 40 + ks], 40);
                wmma::load_matrix_sync(al, &Al_s[(wm * 64 + i * 16) * 40 + ks], 40);
#pragma unroll
                for (int j = 0; j < 4; j++) {
                    wmma::mma_sync(acc[i][j], ah, bl[j], acc[i][j]);
                    wmma::mma_sync(acc[i][j], al, bh[j], acc[i][j]);
                    wmma::mma_sync(acc[i][j], ah, bh[j], acc[i][j]);
                }
            }
        }
        __syncthreads();
    }
#undef LOAD_STAGE

#pragma unroll
    for (int i = 0; i < 4; i++)
#pragma unroll
        for (int j = 0; j < 4; j++) {
#pragma unroll
            for (int t = 0; t < acc[i][j].num_elements; t++) acc[i][j].x[t] *= scale;
            wmma::store_matrix_sync(
                C + (size_t)(mBase + wm * 64 + i * 16) * ldc + nBase + wn * 64 + j * 16,
                acc[i][j], ldc, wmma::mem_row_major);
        }
}

__global__ void __launch_bounds__(128) gemm_pre_kernel(
    const bf16* Ah, const bf16* Al, const bf16* Bh, const bf16* Bl,
    float* C, int ldc, int K)
{
    gemm_core(Ah, Al, Bh, Bl, K, K, K, blockIdx.y * 128, blockIdx.x * 128, C, ldc, 1.0f);
}

__global__ void __launch_bounds__(128) scores_pre_kernel(float* __restrict__ attn)
{
    const int h = blockIdx.z;
    const int mBase = blockIdx.y * 128;
    const int nBase = blockIdx.x * 128;
    if (nBase > mBase + 127) return;
    gemm_core(g_qh + h * H_DIM, g_ql + h * H_DIM,
              g_kh + (h >> 2) * H_DIM, g_kl + (h >> 2) * H_DIM,
              N_H * H_DIM, KV_DIM, H_DIM, mBase, nBase,
              attn + (size_t)h * S_LEN * S_LEN, S_LEN, SCALING);
}

// ===========================================================================
// wo GEMM: out = ctx @ wo^T with 2 fp16 products (ch*w + cl*w), fp32 accum.
// A = ctx hi/lo fp16 planes (22-bit), B = wo single fp16 plane (11-bit).
// BM=BN=128, BK=32, 256 threads (8 warps, warp tile 32x64), 2-stage cp.async.
// Stage (bytes): Ah@0, Al@10240, B@20480 -> 30720 B; 2 stages = 61440 B.
// ===========================================================================
#define WO_STAGE 30720
#define WO_SMEM  (2 * WO_STAGE)

__global__ void __launch_bounds__(256) gemm_wo16_kernel(
    const fp16* __restrict__ Ah, const fp16* __restrict__ Al,
    const fp16* __restrict__ B, float* __restrict__ C, int K)
{
    extern __shared__ fp16 smh[];
    const int tid = threadIdx.x;
    const int warp = tid >> 5;
    const int wm = warp & 3;       // 4 m-groups * 32 rows
    const int wn = warp >> 2;      // 2 n-groups * 64 cols
    const int mBase = blockIdx.y * 128;
    const int nBase = blockIdx.x * 128;

    wmma::fragment<wmma::accumulator, 16, 16, 16, float> acc[2][4];
#pragma unroll
    for (int i = 0; i < 2; i++)
#pragma unroll
        for (int j = 0; j < 4; j++) wmma::fill_fragment(acc[i][j], 0.0f);

    const int r  = tid >> 1;            // 0..127
    const int cc = (tid & 1) * 16;      // 0 or 16 (fp16 elems)

    const fp16* ApH = Ah + (size_t)(mBase + r) * K + cc;
    const fp16* ApL = Al + (size_t)(mBase + r) * K + cc;
    const fp16* Bp  = B  + (size_t)(nBase + r) * K + cc;
    const uint32_t dbase = smem_u32(smh) + r * 80 + cc * 2;

    const int T = K >> 5;

#define WO_LOAD(buf, k0) do { \
        uint32_t d = dbase + (buf) * WO_STAGE; \
        CP16(d,              ApH + (k0)); CP16(d + 16,          ApH + (k0) + 8); \
        CP16(d + 10240,      ApL + (k0)); CP16(d + 10240 + 16,  ApL + (k0) + 8); \
        CP16(d + 20480,      Bp  + (k0)); CP16(d + 20480 + 16,  Bp  + (k0) + 8); \
        CP_COMMIT(); \
    } while (0)

    WO_LOAD(0, 0);

#pragma unroll 1
    for (int t = 0; t < T; t++) {
        if (t + 1 < T) {
            WO_LOAD((t + 1) & 1, (t + 1) * 32);
            CP_WAIT1();
        } else {
            CP_WAIT0();
        }
        __syncthreads();

        fp16* st   = smh + (t & 1) * (WO_STAGE / 2);
        fp16* Ah_s = st;
        fp16* Al_s = st + 5120;
        fp16* B_s  = st + 10240;
#pragma unroll
        for (int ks = 0; ks < 32; ks += 16) {
            wmma::fragment<wmma::matrix_b, 16, 16, 16, fp16, wmma::col_major> bf[4];
#pragma unroll
            for (int j = 0; j < 4; j++)
                wmma::load_matrix_sync(bf[j], &B_s[(wn * 64 + j * 16) * 40 + ks], 40);
            wmma::fragment<wmma::matrix_a, 16, 16, 16, fp16, wmma::row_major> ah[2], al[2];
#pragma unroll
            for (int i = 0; i < 2; i++) {
                wmma::load_matrix_sync(ah[i], &Ah_s[(wm * 32 + i * 16) * 40 + ks], 40);
                wmma::load_matrix_sync(al[i], &Al_s[(wm * 32 + i * 16) * 40 + ks], 40);
            }
#pragma unroll
            for (int i = 0; i < 2; i++)
#pragma unroll
                for (int j = 0; j < 4; j++) {
                    wmma::mma_sync(acc[i][j], al[i], bf[j], acc[i][j]);
                    wmma::mma_sync(acc[i][j], ah[i], bf[j], acc[i][j]);
                }
        }
        __syncthreads();
    }
#undef WO_LOAD

#pragma unroll
    for (int i = 0; i < 2; i++)
#pragma unroll
        for (int j = 0; j < 4; j++)
            wmma::store_matrix_sync(
                C + (size_t)(mBase + wm * 32 + i * 16) * D_MODEL + nBase + wn * 64 + j * 16,
                acc[i][j], D_MODEL, wmma::mem_row_major);
}

// ===========================================================================
// alpha-entmax (alpha=1.5), 32-iter bisection, ONE WARP PER ROW (shfl only).
// Emits bf16 hi/lo split of the attn row for the AV GEMM.
// ===========================================================================
template <int CH>
__device__ __forceinline__ void entmax_row_warp(float* __restrict__ x,
                                                bf16* __restrict__ xh,
                                                bf16* __restrict__ xl,
                                                int n, int lane)
{
    float X[CH];
    float lmax = -INFINITY;
#pragma unroll
    for (int i = 0; i < CH; i++) {
        int j = lane + i * 32;
        if (j < n) {
            float v = x[j] * 0.5f;
            X[i] = v;
            lmax = fmaxf(lmax, v);
        } else {
            X[i] = -INFINITY;
        }
    }
#pragma unroll
    for (int o = 16; o > 0; o >>= 1) lmax = fmaxf(lmax, __shfl_xor_sync(0xffffffffu, lmax, o));

    float tau_lo = lmax - 1.0f;
    float dm = DM0;
    float tau_m = tau_lo;
#pragma unroll 1
    for (int it = 0; it < 32; it++) {
        dm *= 0.5f;
        tau_m = tau_lo + dm;
        float ls = 0.f;
#pragma unroll
        for (int i = 0; i < CH; i++) {
            float t = fmaxf(X[i] - tau_m, 0.f);
            ls = fmaf(t, t, ls);
        }
#pragma unroll
        for (int o = 16; o > 0; o >>= 1) ls += __shfl_xor_sync(0xffffffffu, ls, o);
        if (ls >= 1.0f) tau_lo = tau_m;
    }

    float ls = 0.f;
#pragma unroll
    for (int i = 0; i < CH; i++) {
        float t = fmaxf(X[i] - tau_m, 0.f);
        ls = fmaf(t, t, ls);
    }
#pragma unroll
    for (int o = 16; o > 0; o >>= 1) ls += __shfl_xor_sync(0xffffffffu, ls, o);
    float inv = 1.0f / ls;

#pragma unroll
    for (int i = 0; i < CH; i++) {
        int j = lane + i * 32;
        float t = fmaxf(X[i] - tau_m, 0.f);
        float v = (j < n) ? t * t * inv : 0.0f;
        x[j] = v;
        bf16 h, l;
        split_bf16(v, h, l);
        xh[j] = h; xl[j] = l;
    }
#pragma unroll
    for (int i = CH; i < 64; i++) {
        int j = lane + i * 32;
        x[j] = 0.0f;
        xh[j] = __float2bfloat16_rn(0.0f);
        xl[j] = __float2bfloat16_rn(0.0f);
    }
}

__global__ void __launch_bounds__(256) entmax_kernel(float* __restrict__ attn,
                                                     bf16* __restrict__ ath,
                                                     bf16* __restrict__ atl)
{
    const int idx = blockIdx.x * 8 + (threadIdx.x >> 5);
    const int lane = threadIdx.x & 31;
    const int h = idx >> 11;
    const int q = idx & 2047;
    size_t off = (size_t)h * S_LEN * S_LEN + (size_t)q * S_LEN;
    float* x = attn + off;
    bf16* xh = ath + off;
    bf16* xl = atl + off;
    const int n = q + 1;
    const int c8 = (((n + 31) >> 5) + 7) >> 3;

    switch (c8) {
        case 1: entmax_row_warp<8>(x, xh, xl, n, lane); break;
        case 2: entmax_row_warp<16>(x, xh, xl, n, lane); break;
        case 3: entmax_row_warp<24>(x, xh, xl, n, lane); break;
        case 4: entmax_row_warp<32>(x, xh, xl, n, lane); break;
        case 5: entmax_row_warp<40>(x, xh, xl, n, lane); break;
        case 6: entmax_row_warp<48>(x, xh, xl, n, lane); break;
        case 7: entmax_row_warp<56>(x, xh, xl, n, lane); break;
        default: entmax_row_warp<64>(x, xh, xl, n, lane); break;
    }
}

// ===========================================================================
// attn @ V: pre-split bf16 operands, pipelined cp.async double buffer.
// 128x128 C tile, BK=32, 256 threads, warp tile 32x64.
// ===========================================================================
#define AV_STAGE 37888
#define AV_SMEM  (2 * AV_STAGE)

__global__ void __launch_bounds__(256) av_kernel()
{
    extern __shared__ bf16 sm[];
    const int h = blockIdx.z;
    const int mBase = (gridDim.y - 1 - blockIdx.y) * 128;

    const int tid = threadIdx.x;
    const int warp = tid >> 5;
    const int wm = warp & 3;
    const int wn = warp >> 2;

    const size_t aoff = (size_t)h * S_LEN * S_LEN;
    const bf16* Ah_g = g_ath + aoff;
    const bf16* Al_g = g_atl + aoff;
    const bf16* Bh_g = g_vh + (h >> 2) * H_DIM;
    const bf16* Bl_g = g_vl + (h >> 2) * H_DIM;

    const int rA = tid >> 1;
    const int cA = (tid & 1) * 16;
    const int rB = tid >> 3;
    const int cB = (tid & 7) * 16;

    const bf16* ApH = Ah_g + (size_t)(mBase + rA) * S_LEN + cA;
    const bf16* ApL = Al_g + (size_t)(mBase + rA) * S_LEN + cA;
    const bf16* BpH = Bh_g + (size_t)rB * KV_DIM + cB;
    const bf16* BpL = Bl_g + (size_t)rB * KV_DIM + cB;

    const uint32_t sb = smem_u32(sm);
    const uint32_t dA = sb + rA * 80 + cA * 2;
    const uint32_t dB = sb + 20480 + rB * 272 + cB * 2;

    wmma::fragment<wmma::accumulator, 16, 16, 16, float> acc[2][4];
#pragma unroll
    for (int i = 0; i < 2; i++)
#pragma unroll
        for (int j = 0; j < 4; j++) wmma::fill_fragment(acc[i][j], 0.0f);

    const int T = (mBase + 128) >> 5;

#define AV_LOAD(buf, k0) do { \
        uint32_t da = dA + (buf) * AV_STAGE; \
        CP16(da,          ApH + (k0)); CP16(da + 16,          ApH + (k0) + 8); \
        CP16(da + 10240,  ApL + (k0)); CP16(da + 10240 + 16,  ApL + (k0) + 8); \
        uint32_t db = dB + (buf) * AV_STAGE; \
        CP16(db,          BpH + (size_t)(k0) * KV_DIM); CP16(db + 16, BpH + (size_t)(k0) * KV_DIM + 8); \
        CP16(db + 8704,   BpL + (size_t)(k0) * KV_DIM); CP16(db + 8704 + 16, BpL + (size_t)(k0) * KV_DIM + 8); \
        CP_COMMIT(); \
    } while (0)

    AV_LOAD(0, 0);

#pragma unroll 1
    for (int t = 0; t < T; t++) {
        if (t + 1 < T) {
            AV_LOAD((t + 1) & 1, (t + 1) * 32);
            CP_WAIT1();
        } else {
            CP_WAIT0();
        }
        __syncthreads();

        bf16* st   = sm + (t & 1) * (AV_STAGE / 2);
        bf16* Ah_s = st;
        bf16* Al_s = st + 5120;
        bf16* Bh_s = st + 10240;
        bf16* Bl_s = st + 14592;
#pragma unroll
        for (int ks = 0; ks < 32; ks += 16) {
            wmma::fragment<wmma::matrix_a, 16, 16, 16, bf16, wmma::row_major> ah[2], al[2];
            wmma::fragment<wmma::matrix_b, 16, 16, 16, bf16, wmma::row_major> bh[4], bl[4];
#pragma unroll
            for (int i = 0; i < 2; i++) {
                wmma::load_matrix_sync(ah[i], &Ah_s[(wm * 32 + i * 16) * 40 + ks], 40);
                wmma::load_matrix_sync(al[i], &Al_s[(wm * 32 + i * 16) * 40 + ks], 40);
            }
#pragma unroll
            for (int j = 0; j < 4; j++) {
                wmma::load_matrix_sync(bh[j], &Bh_s[ks * 136 + wn * 64 + j * 16], 136);
                wmma::load_matrix_sync(bl[j], &Bl_s[ks * 136 + wn * 64 + j * 16], 136);
            }
#pragma unroll
            for (int i = 0; i < 2; i++)
#pragma unroll
                for (int j = 0; j < 4; j++) {
                    wmma::mma_sync(acc[i][j], ah[i], bl[j], acc[i][j]);
                    wmma::mma_sync(acc[i][j], al[i], bh[j], acc[i][j]);
                    wmma::mma_sync(acc[i][j], ah[i], bh[j], acc[i][j]);
                }
        }
        __syncthreads();
    }
#undef AV_LOAD

#pragma unroll
    for (int i = 0; i < 2; i++)
#pragma unroll
        for (int j = 0; j < 4; j++)
            wmma::store_matrix_sync(
                g_ctx + (size_t)(mBase + wm * 32 + i * 16) * (N_H * H_DIM)
                      + h * H_DIM + wn * 64 + j * 16,
                acc[i][j], N_H * H_DIM, wmma::mem_row_major);
}

// ===========================================================================
extern "C" void kernel_launch(void* const* d_in, const int* in_sizes, int n_in,
                              void* d_out, int out_size)
{
    const float* hs   = (const float*)d_in[0];
    const float* cosb = (const float*)d_in[1];
    const float* sinb = (const float*)d_in[2];
    const float* wq   = (const float*)d_in[3];
    const float* wk   = (const float*)d_in[4];
    const float* wv   = (const float*)d_in[5];
    const float* wo   = (const float*)d_in[6];
    float* out = (float*)d_out;

    float *qkvp, *cp, *ap;
    cudaGetSymbolAddress((void**)&qkvp, g_qkv);
    cudaGetSymbolAddress((void**)&cp, g_ctx);
    cudaGetSymbolAddress((void**)&ap, g_attn);

    bf16 *hsh, *hsl, *wh, *wl, *qh, *ql, *kh, *kl, *vh, *vl, *ath, *atl;
    fp16 *ch16, *cl16, *wo16;
    cudaGetSymbolAddress((void**)&hsh, g_hsh); cudaGetSymbolAddress((void**)&hsl, g_hsl);
    cudaGetSymbolAddress((void**)&wh, g_wh);   cudaGetSymbolAddress((void**)&wl, g_wl);
    cudaGetSymbolAddress((void**)&qh, g_qh);   cudaGetSymbolAddress((void**)&ql, g_ql);
    cudaGetSymbolAddress((void**)&kh, g_kh);   cudaGetSymbolAddress((void**)&kl, g_kl);
    cudaGetSymbolAddress((void**)&vh, g_vh);   cudaGetSymbolAddress((void**)&vl, g_vl);
    cudaGetSymbolAddress((void**)&ath, g_ath); cudaGetSymbolAddress((void**)&atl, g_atl);
    cudaGetSymbolAddress((void**)&ch16, g_ch16); cudaGetSymbolAddress((void**)&cl16, g_cl16);
    cudaGetSymbolAddress((void**)&wo16, g_wo16);

    const size_t need = (size_t)S_LEN * D_MODEL + (size_t)N_H * S_LEN * S_LEN;
    float* attnBuf = ((size_t)out_size >= need) ? (out + (size_t)S_LEN * D_MODEL) : ap;

    cudaFuncSetAttribute(gemm_pre_kernel, cudaFuncAttributeMaxDynamicSharedMemorySize, GEMM_SMEM);
    cudaFuncSetAttribute(scores_pre_kernel, cudaFuncAttributeMaxDynamicSharedMemorySize, GEMM_SMEM);
    cudaFuncSetAttribute(av_kernel, cudaFuncAttributeMaxDynamicSharedMemorySize, AV_SMEM);
    cudaFuncSetAttribute(gemm_wo16_kernel, cudaFuncAttributeMaxDynamicSharedMemorySize, WO_SMEM);

    const int nBig = 2048 * 2048, nSml = 2048 * 512;

    // 0) pre-split inputs; weights into fused [wq; wk; wv] layout; wo as fp16
    split_kernel<<<nBig / 1024, 256>>>(hs, hsh, hsl, nBig);
    split_kernel<<<nBig / 1024, 256>>>(wq, wh, wl, nBig);
    split_kernel<<<nSml / 1024, 256>>>(wk, wh + (size_t)2048 * 2048, wl + (size_t)2048 * 2048, nSml);
    split_kernel<<<nSml / 1024, 256>>>(wv, wh + (size_t)2560 * 2048, wl + (size_t)2560 * 2048, nSml);
    split16_single_kernel<<<nBig / 1024, 256>>>(wo, wo16, nBig);

    // 1) fused qkv projection: [2048 x 3072] = hs @ [wq;wk;wv]^T
    gemm_pre_kernel<<<dim3(QKV_DIM / 128, S_LEN / 128), 128, GEMM_SMEM>>>(
        hsh, hsl, wh, wl, qkvp, QKV_DIM, D_MODEL);

    // 2) RoPE + split (q, k); strided split v
    {
        int totQ = S_LEN * N_H * (H_DIM / 2);
        int totK = S_LEN * N_KV * (H_DIM / 2);
        rope_split_kernel<<<(totQ + 255) / 256, 256>>>(qkvp, QKV_DIM, cosb, sinb, N_H, qh, ql);
        rope_split_kernel<<<(totK + 255) / 256, 256>>>(qkvp + 2048, QKV_DIM, cosb, sinb, N_KV, kh, kl);
        split_strided_kernel<<<nSml / 1024, 256>>>(qkvp + 2560, QKV_DIM, KV_DIM, vh, vl, nSml);
    }

    // 3) causal scores
    scores_pre_kernel<<<dim3(S_LEN / 128, S_LEN / 128, N_H), 128, GEMM_SMEM>>>(attnBuf);

    // 4) entmax in place (warp-per-row) + emit bf16 hi/lo attn
    entmax_kernel<<<(N_H * S_LEN) / 8, 256>>>(attnBuf, ath, atl);

    // 5) attn @ v -> ctx, then fp16-pair split of ctx
    av_kernel<<<dim3(1, S_LEN / 128, N_H), 256, AV_SMEM>>>();
    split16_pair_kernel<<<nBig / 1024, 256>>>(cp, ch16, cl16, nBig);

    // 6) out = ctx @ wo^T  (fp16 2-product)
    gemm_wo16_kernel<<<dim3(D_MODEL / 128, S_LEN / 128), 256, WO_SMEM>>>(
        ch16, cl16, wo16, out, D_MODEL);
}

// round 12
// speedup vs baseline: 1.7655x; 1.1267x over previous
#include <cuda_runtime.h>
#include <cuda_bf16.h>
#include <cuda_fp16.h>
#include <mma.h>
#include <math.h>
#include <stdint.h>

using namespace nvcuda;

#define S_LEN 2048
#define D_MODEL 2048
#define N_H 16
#define N_KV 4
#define H_DIM 128
#define SCALING 0.08838834764831845f
#define DM0 0.9779029130879204f
#define KV_DIM (N_KV * H_DIM)
#define QKV_DIM (N_H * H_DIM + 2 * KV_DIM)   // 3072

typedef __nv_bfloat16 bf16;
typedef __half fp16;

// fp32 scratch
__device__ float g_qkv[(size_t)S_LEN * QKV_DIM];
__device__ float g_ctx[(size_t)S_LEN * N_H * H_DIM];
__device__ float g_attn[(size_t)N_H * S_LEN * S_LEN];

// pre-split scratch
#define SZ_BIG  ((size_t)2048 * 2048)
#define SZ_SML  ((size_t)2048 * 512)
#define SZ_W    ((size_t)3072 * 2048)
#define SZ_ATT  ((size_t)N_H * S_LEN * S_LEN)
__device__ bf16 g_hsh[SZ_BIG], g_hsl[SZ_BIG];
__device__ bf16 g_wh[SZ_W],    g_wl[SZ_W];      // fused [wq; wk; wv]
__device__ bf16 g_qh[SZ_BIG],  g_ql[SZ_BIG];
__device__ bf16 g_kh[SZ_SML],  g_kl[SZ_SML];
// fp16 planes (out path)
__device__ fp16 g_ath[SZ_ATT], g_atl[SZ_ATT];   // attn hi/lo (entmax epilogue)
__device__ fp16 g_v16[SZ_SML];                  // V single plane
__device__ fp16 g_c16[SZ_BIG];                  // ctx single plane
__device__ fp16 g_wo16[SZ_BIG];                 // wo single plane

__device__ __forceinline__ void split_bf16(float v, bf16& hi, bf16& lo) {
    hi = __float2bfloat16_rn(v);
    lo = __float2bfloat16_rn(v - __bfloat162float(hi));
}
__device__ __forceinline__ uint32_t smem_u32(const void* p) {
    return (uint32_t)__cvta_generic_to_shared(p);
}
#define CP16(dst, src) asm volatile("cp.async.cg.shared.global [%0], [%1], 16;" :: "r"(dst), "l"(src))
#define CP_COMMIT()    asm volatile("cp.async.commit_group;" ::: "memory")
#define CP_WAIT1()     asm volatile("cp.async.wait_group 1;" ::: "memory")
#define CP_WAIT0()     asm volatile("cp.async.wait_group 0;" ::: "memory")

// ===========================================================================
// split kernels
// ===========================================================================
__global__ void split_kernel(const float* __restrict__ x,
                             bf16* __restrict__ hi, bf16* __restrict__ lo, int n)
{
    int i = (blockIdx.x * blockDim.x + threadIdx.x) * 4;
    if (i >= n) return;
    float4 v = *(const float4*)(x + i);
    bf16 h0, l0, h1, l1, h2, l2, h3, l3;
    split_bf16(v.x, h0, l0); split_bf16(v.y, h1, l1);
    split_bf16(v.z, h2, l2); split_bf16(v.w, h3, l3);
    __nv_bfloat162* H = (__nv_bfloat162*)(hi + i);
    __nv_bfloat162* L = (__nv_bfloat162*)(lo + i);
    H[0] = __halves2bfloat162(h0, h1); H[1] = __halves2bfloat162(h2, h3);
    L[0] = __halves2bfloat162(l0, l1); L[1] = __halves2bfloat162(l2, l3);
}

// fp32 -> fp16 single plane (contiguous)
__global__ void split16_single_kernel(const float* __restrict__ x,
                                      fp16* __restrict__ h, int n)
{
    int i = (blockIdx.x * blockDim.x + threadIdx.x) * 4;
    if (i >= n) return;
    float4 v = *(const float4*)(x + i);
    __half2* H = (__half2*)(h + i);
    H[0] = __halves2half2(__float2half_rn(v.x), __float2half_rn(v.y));
    H[1] = __halves2half2(__float2half_rn(v.z), __float2half_rn(v.w));
}

// fp32 strided rows -> fp16 single plane (dense)
__global__ void split16_single_strided_kernel(const float* __restrict__ x, int srcStride,
                                              int width, fp16* __restrict__ h, int n)
{
    int i = (blockIdx.x * blockDim.x + threadIdx.x) * 4;
    if (i >= n) return;
    int s = i / width;
    int c = i - s * width;
    float4 v = *(const float4*)(x + (size_t)s * srcStride + c);
    __half2* H = (__half2*)(h + i);
    H[0] = __halves2half2(__float2half_rn(v.x), __float2half_rn(v.y));
    H[1] = __halves2half2(__float2half_rn(v.z), __float2half_rn(v.w));
}

// ===========================================================================
// RoPE + split (bf16 pair — attn path keeps full precision)
// ===========================================================================
__global__ void rope_split_kernel(const float* __restrict__ X, int xStride,
                                  const float* __restrict__ cosb,
                                  const float* __restrict__ sinb, int nHeads,
                                  bf16* __restrict__ hi, bf16* __restrict__ lo)
{
    int idx = blockIdx.x * blockDim.x + threadIdx.x;
    int total = S_LEN * nHeads * (H_DIM / 2);
    if (idx >= total) return;
    int d = idx & 63;
    int t = idx >> 6;
    int hh = t % nHeads;
    int s  = t / nHeads;
    float c1 = cosb[s * H_DIM + d];
    float s1 = sinb[s * H_DIM + d];
    float c2 = cosb[s * H_DIM + d + 64];
    float s2 = sinb[s * H_DIM + d + 64];
    size_t src = (size_t)s * xStride + (size_t)hh * H_DIM + d;
    size_t dst = (size_t)s * nHeads * H_DIM + (size_t)hh * H_DIM + d;
    float x1 = X[src];
    float x2 = X[src + 64];
    float y1 = x1 * c1 - x2 * s1;
    float y2 = x2 * c2 + x1 * s2;
    bf16 h, l;
    split_bf16(y1, h, l); hi[dst] = h;      lo[dst] = l;
    split_bf16(y2, h, l); hi[dst + 64] = h; lo[dst + 64] = l;
}

// ===========================================================================
// Pipelined split-bf16 NT GEMM core (3-product): BM=BN=128, BK=32,
// 128 threads (4 warps), warp tile 64x64, 2-stage cp.async, 80KB SMEM.
// ===========================================================================
#define GEMM_SMEM (2 * 20480 * (int)sizeof(bf16))

__device__ __forceinline__ void gemm_core(
    const bf16* __restrict__ Ah, const bf16* __restrict__ Al,
    const bf16* __restrict__ Bh, const bf16* __restrict__ Bl,
    int lda, int ldb, int K, int mBase, int nBase,
    float* __restrict__ C, int ldc, float scale)
{
    extern __shared__ bf16 sm[];
    const int tid = threadIdx.x;          // 0..127
    const int warp = tid >> 5;            // 0..3
    const int wm = warp >> 1;             // 0..1 (m group of 64)
    const int wn = warp & 1;              // 0..1 (n group of 64)

    wmma::fragment<wmma::accumulator, 16, 16, 16, float> acc[4][4];
#pragma unroll
    for (int i = 0; i < 4; i++)
#pragma unroll
        for (int j = 0; j < 4; j++) wmma::fill_fragment(acc[i][j], 0.0f);

    const bf16* Ap_h = Ah + (size_t)(mBase + tid) * lda;
    const bf16* Ap_l = Al + (size_t)(mBase + tid) * lda;
    const bf16* Bp_h = Bh + (size_t)(nBase + tid) * ldb;
    const bf16* Bp_l = Bl + (size_t)(nBase + tid) * ldb;
    const uint32_t dbase = smem_u32(sm) + tid * 80;

    const int T = K >> 5;

#define LOAD_STAGE(buf, k0) do { \
        uint32_t d = dbase + (buf) * 40960; \
        CP16(d,          Ap_h + (k0));      CP16(d + 16,          Ap_h + (k0) + 8); \
        CP16(d + 32,     Ap_h + (k0) + 16); CP16(d + 48,          Ap_h + (k0) + 24); \
        CP16(d + 10240,      Ap_l + (k0));      CP16(d + 10240 + 16, Ap_l + (k0) + 8); \
        CP16(d + 10240 + 32, Ap_l + (k0) + 16); CP16(d + 10240 + 48, Ap_l + (k0) + 24); \
        CP16(d + 20480,      Bp_h + (k0));      CP16(d + 20480 + 16, Bp_h + (k0) + 8); \
        CP16(d + 20480 + 32, Bp_h + (k0) + 16); CP16(d + 20480 + 48, Bp_h + (k0) + 24); \
        CP16(d + 30720,      Bp_l + (k0));      CP16(d + 30720 + 16, Bp_l + (k0) + 8); \
        CP16(d + 30720 + 32, Bp_l + (k0) + 16); CP16(d + 30720 + 48, Bp_l + (k0) + 24); \
        CP_COMMIT(); \
    } while (0)

    LOAD_STAGE(0, 0);

#pragma unroll 1
    for (int t = 0; t < T; t++) {
        if (t + 1 < T) {
            LOAD_STAGE((t + 1) & 1, (t + 1) * 32);
            CP_WAIT1();
        } else {
            CP_WAIT0();
        }
        __syncthreads();

        bf16* st   = sm + (t & 1) * 20480;
        bf16* Ah_s = st;
        bf16* Al_s = st + 5120;
        bf16* Bh_s = st + 10240;
        bf16* Bl_s = st + 15360;
#pragma unroll
        for (int ks = 0; ks < 32; ks += 16) {
            wmma::fragment<wmma::matrix_b, 16, 16, 16, bf16, wmma::col_major> bh[4], bl[4];
#pragma unroll
            for (int j = 0; j < 4; j++) {
                wmma::load_matrix_sync(bh[j], &Bh_s[(wn * 64 + j * 16) * 40 + ks], 40);
                wmma::load_matrix_sync(bl[j], &Bl_s[(wn * 64 + j * 16) * 40 + ks], 40);
            }
#pragma unroll
            for (int i = 0; i < 4; i++) {
                wmma::fragment<wmma::matrix_a, 16, 16, 16, bf16, wmma::row_major> ah, al;
                wmma::load_matrix_sync(ah, &Ah_s[(wm * 64 + i * 16) * 40 + ks], 40);
                wmma::load_matrix_sync(al, &Al_s[(wm * 64 + i * 16) * 40 + ks], 40);
#pragma unroll
                for (int j = 0; j < 4; j++) {
                    wmma::mma_sync(acc[i][j], ah, bl[j], acc[i][j]);
                    wmma::mma_sync(acc[i][j], al, bh[j], acc[i][j]);
                    wmma::mma_sync(acc[i][j], ah, bh[j], acc[i][j]);
                }
            }
        }
        __syncthreads();
    }
#undef LOAD_STAGE

#pragma unroll
    for (int i = 0; i < 4; i++)
#pragma unroll
        for (int j = 0; j < 4; j++) {
#pragma unroll
            for (int t = 0; t < acc[i][j].num_elements; t++) acc[i][j].x[t] *= scale;
            wmma::store_matrix_sync(
                C + (size_t)(mBase + wm * 64 + i * 16) * ldc + nBase + wn * 64 + j * 16,
                acc[i][j], ldc, wmma::mem_row_major);
        }
}

__global__ void __launch_bounds__(128) gemm_pre_kernel(
    const bf16* Ah, const bf16* Al, const bf16* Bh, const bf16* Bl,
    float* C, int ldc, int K)
{
    gemm_core(Ah, Al, Bh, Bl, K, K, K, blockIdx.y * 128, blockIdx.x * 128, C, ldc, 1.0f);
}

__global__ void __launch_bounds__(128) scores_pre_kernel(float* __restrict__ attn)
{
    const int h = blockIdx.z;
    const int mBase = blockIdx.y * 128;
    const int nBase = blockIdx.x * 128;
    if (nBase > mBase + 127) return;
    gemm_core(g_qh + h * H_DIM, g_ql + h * H_DIM,
              g_kh + (h >> 2) * H_DIM, g_kl + (h >> 2) * H_DIM,
              N_H * H_DIM, KV_DIM, H_DIM, mBase, nBase,
              attn + (size_t)h * S_LEN * S_LEN, S_LEN, SCALING);
}

// ===========================================================================
// wo GEMM: out = ctx16 @ wo16^T, single fp16 product, fp32 accum.
// BM=BN=128, BK=32, 256 threads (warp tile 32x64), 2-stage cp.async.
// Stage (bytes): A@0 (10240), B@10240 (10240) -> 20480 B; 2 stages = 40960 B.
// ===========================================================================
#define WO_STAGE 20480
#define WO_SMEM  (2 * WO_STAGE)

__global__ void __launch_bounds__(256) gemm_wo16_kernel(
    const fp16* __restrict__ A, const fp16* __restrict__ B,
    float* __restrict__ C, int K)
{
    extern __shared__ fp16 smh[];
    const int tid = threadIdx.x;
    const int warp = tid >> 5;
    const int wm = warp & 3;
    const int wn = warp >> 2;
    const int mBase = blockIdx.y * 128;
    const int nBase = blockIdx.x * 128;

    wmma::fragment<wmma::accumulator, 16, 16, 16, float> acc[2][4];
#pragma unroll
    for (int i = 0; i < 2; i++)
#pragma unroll
        for (int j = 0; j < 4; j++) wmma::fill_fragment(acc[i][j], 0.0f);

    const int r  = tid >> 1;
    const int cc = (tid & 1) * 16;

    const fp16* Ap = A + (size_t)(mBase + r) * K + cc;
    const fp16* Bp = B + (size_t)(nBase + r) * K + cc;
    const uint32_t dbase = smem_u32(smh) + r * 80 + cc * 2;

    const int T = K >> 5;

#define WO_LOAD(buf, k0) do { \
        uint32_t d = dbase + (buf) * WO_STAGE; \
        CP16(d,          Ap + (k0)); CP16(d + 16,          Ap + (k0) + 8); \
        CP16(d + 10240,  Bp + (k0)); CP16(d + 10240 + 16,  Bp + (k0) + 8); \
        CP_COMMIT(); \
    } while (0)

    WO_LOAD(0, 0);

#pragma unroll 1
    for (int t = 0; t < T; t++) {
        if (t + 1 < T) {
            WO_LOAD((t + 1) & 1, (t + 1) * 32);
            CP_WAIT1();
        } else {
            CP_WAIT0();
        }
        __syncthreads();

        fp16* st  = smh + (t & 1) * (WO_STAGE / 2);
        fp16* A_s = st;
        fp16* B_s = st + 5120;
#pragma unroll
        for (int ks = 0; ks < 32; ks += 16) {
            wmma::fragment<wmma::matrix_b, 16, 16, 16, fp16, wmma::col_major> bf[4];
#pragma unroll
            for (int j = 0; j < 4; j++)
                wmma::load_matrix_sync(bf[j], &B_s[(wn * 64 + j * 16) * 40 + ks], 40);
            wmma::fragment<wmma::matrix_a, 16, 16, 16, fp16, wmma::row_major> af[2];
#pragma unroll
            for (int i = 0; i < 2; i++)
                wmma::load_matrix_sync(af[i], &A_s[(wm * 32 + i * 16) * 40 + ks], 40);
#pragma unroll
            for (int i = 0; i < 2; i++)
#pragma unroll
                for (int j = 0; j < 4; j++)
                    wmma::mma_sync(acc[i][j], af[i], bf[j], acc[i][j]);
        }
        __syncthreads();
    }
#undef WO_LOAD

#pragma unroll
    for (int i = 0; i < 2; i++)
#pragma unroll
        for (int j = 0; j < 4; j++)
            wmma::store_matrix_sync(
                C + (size_t)(mBase + wm * 32 + i * 16) * D_MODEL + nBase + wn * 64 + j * 16,
                acc[i][j], D_MODEL, wmma::mem_row_major);
}

// ===========================================================================
// alpha-entmax (alpha=1.5), 32-iter bisection, ONE WARP PER ROW (shfl only).
// Emits fp16 hi/lo split of the attn row for the AV GEMM.
// ===========================================================================
template <int CH>
__device__ __forceinline__ void entmax_row_warp(float* __restrict__ x,
                                                fp16* __restrict__ xh,
                                                fp16* __restrict__ xl,
                                                int n, int lane)
{
    float X[CH];
    float lmax = -INFINITY;
#pragma unroll
    for (int i = 0; i < CH; i++) {
        int j = lane + i * 32;
        if (j < n) {
            float v = x[j] * 0.5f;
            X[i] = v;
            lmax = fmaxf(lmax, v);
        } else {
            X[i] = -INFINITY;
        }
    }
#pragma unroll
    for (int o = 16; o > 0; o >>= 1) lmax = fmaxf(lmax, __shfl_xor_sync(0xffffffffu, lmax, o));

    float tau_lo = lmax - 1.0f;
    float dm = DM0;
    float tau_m = tau_lo;
#pragma unroll 1
    for (int it = 0; it < 32; it++) {
        dm *= 0.5f;
        tau_m = tau_lo + dm;
        float ls = 0.f;
#pragma unroll
        for (int i = 0; i < CH; i++) {
            float t = fmaxf(X[i] - tau_m, 0.f);
            ls = fmaf(t, t, ls);
        }
#pragma unroll
        for (int o = 16; o > 0; o >>= 1) ls += __shfl_xor_sync(0xffffffffu, ls, o);
        if (ls >= 1.0f) tau_lo = tau_m;
    }

    float ls = 0.f;
#pragma unroll
    for (int i = 0; i < CH; i++) {
        float t = fmaxf(X[i] - tau_m, 0.f);
        ls = fmaf(t, t, ls);
    }
#pragma unroll
    for (int o = 16; o > 0; o >>= 1) ls += __shfl_xor_sync(0xffffffffu, ls, o);
    float inv = 1.0f / ls;

#pragma unroll
    for (int i = 0; i < CH; i++) {
        int j = lane + i * 32;
        float t = fmaxf(X[i] - tau_m, 0.f);
        float v = (j < n) ? t * t * inv : 0.0f;
        x[j] = v;
        fp16 h = __float2half_rn(v);
        xh[j] = h;
        xl[j] = __float2half_rn(v - __half2float(h));
    }
#pragma unroll
    for (int i = CH; i < 64; i++) {
        int j = lane + i * 32;
        x[j] = 0.0f;
        xh[j] = __float2half_rn(0.0f);
        xl[j] = __float2half_rn(0.0f);
    }
}

__global__ void __launch_bounds__(256) entmax_kernel(float* __restrict__ attn,
                                                     fp16* __restrict__ ath,
                                                     fp16* __restrict__ atl)
{
    const int idx = blockIdx.x * 8 + (threadIdx.x >> 5);
    const int lane = threadIdx.x & 31;
    const int h = idx >> 11;
    const int q = idx & 2047;
    size_t off = (size_t)h * S_LEN * S_LEN + (size_t)q * S_LEN;
    float* x = attn + off;
    fp16* xh = ath + off;
    fp16* xl = atl + off;
    const int n = q + 1;
    const int c8 = (((n + 31) >> 5) + 7) >> 3;

    switch (c8) {
        case 1: entmax_row_warp<8>(x, xh, xl, n, lane); break;
        case 2: entmax_row_warp<16>(x, xh, xl, n, lane); break;
        case 3: entmax_row_warp<24>(x, xh, xl, n, lane); break;
        case 4: entmax_row_warp<32>(x, xh, xl, n, lane); break;
        case 5: entmax_row_warp<40>(x, xh, xl, n, lane); break;
        case 6: entmax_row_warp<48>(x, xh, xl, n, lane); break;
        case 7: entmax_row_warp<56>(x, xh, xl, n, lane); break;
        default: entmax_row_warp<64>(x, xh, xl, n, lane); break;
    }
}

// ===========================================================================
// attn @ V: attn fp16 hi/lo pair x V single fp16 plane = 2 products.
// 128x128 C tile, BK=32, 256 threads, warp tile 32x64, 2-stage cp.async.
// Stage (halfs): Ah@0 (5120), Al@5120, B@10240 (4352) -> 14592 halfs = 29184 B.
// ===========================================================================
#define AV_STAGE 29184
#define AV_SMEM  (2 * AV_STAGE)

__global__ void __launch_bounds__(256) av_kernel()
{
    extern __shared__ fp16 smh[];
    const int h = blockIdx.z;
    const int mBase = (gridDim.y - 1 - blockIdx.y) * 128;

    const int tid = threadIdx.x;
    const int warp = tid >> 5;
    const int wm = warp & 3;
    const int wn = warp >> 2;

    const size_t aoff = (size_t)h * S_LEN * S_LEN;
    const fp16* Ah_g = g_ath + aoff;
    const fp16* Al_g = g_atl + aoff;
    const fp16* B_g  = g_v16 + (h >> 2) * H_DIM;

    const int rA = tid >> 1;
    const int cA = (tid & 1) * 16;
    const int rB = tid >> 3;
    const int cB = (tid & 7) * 16;

    const fp16* ApH = Ah_g + (size_t)(mBase + rA) * S_LEN + cA;
    const fp16* ApL = Al_g + (size_t)(mBase + rA) * S_LEN + cA;
    const fp16* Bp  = B_g  + (size_t)rB * KV_DIM + cB;

    const uint32_t sb = smem_u32(smh);
    const uint32_t dA = sb + rA * 80 + cA * 2;
    const uint32_t dB = sb + 20480 + rB * 272 + cB * 2;

    wmma::fragment<wmma::accumulator, 16, 16, 16, float> acc[2][4];
#pragma unroll
    for (int i = 0; i < 2; i++)
#pragma unroll
        for (int j = 0; j < 4; j++) wmma::fill_fragment(acc[i][j], 0.0f);

    const int T = (mBase + 128) >> 5;

#define AV_LOAD(buf, k0) do { \
        uint32_t da = dA + (buf) * AV_STAGE; \
        CP16(da,         ApH + (k0)); CP16(da + 16,         ApH + (k0) + 8); \
        CP16(da + 10240, ApL + (k0)); CP16(da + 10240 + 16, ApL + (k0) + 8); \
        uint32_t db = dB + (buf) * AV_STAGE; \
        CP16(db, Bp + (size_t)(k0) * KV_DIM); CP16(db + 16, Bp + (size_t)(k0) * KV_DIM + 8); \
        CP_COMMIT(); \
    } while (0)

    AV_LOAD(0, 0);

#pragma unroll 1
    for (int t = 0; t < T; t++) {
        if (t + 1 < T) {
            AV_LOAD((t + 1) & 1, (t + 1) * 32);
            CP_WAIT1();
        } else {
            CP_WAIT0();
        }
        __syncthreads();

        fp16* st   = smh + (t & 1) * (AV_STAGE / 2);
        fp16* Ah_s = st;
        fp16* Al_s = st + 5120;
        fp16* B_s  = st + 10240;
#pragma unroll
        for (int ks = 0; ks < 32; ks += 16) {
            wmma::fragment<wmma::matrix_a, 16, 16, 16, fp16, wmma::row_major> ah[2], al[2];
            wmma::fragment<wmma::matrix_b, 16, 16, 16, fp16, wmma::row_major> bf[4];
#pragma unroll
            for (int i = 0; i < 2; i++) {
                wmma::load_matrix_sync(ah[i], &Ah_s[(wm * 32 + i * 16) * 40 + ks], 40);
                wmma::load_matrix_sync(al[i], &Al_s[(wm * 32 + i * 16) * 40 + ks], 40);
            }
#pragma unroll
            for (int j = 0; j < 4; j++)
                wmma::load_matrix_sync(bf[j], &B_s[ks * 136 + wn * 64 + j * 16], 136);
#pragma unroll
            for (int i = 0; i < 2; i++)
#pragma unroll
                for (int j = 0; j < 4; j++) {
                    wmma::mma_sync(acc[i][j], al[i], bf[j], acc[i][j]);
                    wmma::mma_sync(acc[i][j], ah[i], bf[j], acc[i][j]);
                }
        }
        __syncthreads();
    }
#undef AV_LOAD

#pragma unroll
    for (int i = 0; i < 2; i++)
#pragma unroll
        for (int j = 0; j < 4; j++)
            wmma::store_matrix_sync(
                g_ctx + (size_t)(mBase + wm * 32 + i * 16) * (N_H * H_DIM)
                      + h * H_DIM + wn * 64 + j * 16,
                acc[i][j], N_H * H_DIM, wmma::mem_row_major);
}

// ===========================================================================
extern "C" void kernel_launch(void* const* d_in, const int* in_sizes, int n_in,
                              void* d_out, int out_size)
{
    const float* hs   = (const float*)d_in[0];
    const float* cosb = (const float*)d_in[1];
    const float* sinb = (const float*)d_in[2];
    const float* wq   = (const float*)d_in[3];
    const float* wk   = (const float*)d_in[4];
    const float* wv   = (const float*)d_in[5];
    const float* wo   = (const float*)d_in[6];
    float* out = (float*)d_out;

    float *qkvp, *cp, *ap;
    cudaGetSymbolAddress((void**)&qkvp, g_qkv);
    cudaGetSymbolAddress((void**)&cp, g_ctx);
    cudaGetSymbolAddress((void**)&ap, g_attn);

    bf16 *hsh, *hsl, *wh, *wl, *qh, *ql, *kh, *kl;
    fp16 *ath, *atl, *v16, *c16, *wo16;
    cudaGetSymbolAddress((void**)&hsh, g_hsh); cudaGetSymbolAddress((void**)&hsl, g_hsl);
    cudaGetSymbolAddress((void**)&wh, g_wh);   cudaGetSymbolAddress((void**)&wl, g_wl);
    cudaGetSymbolAddress((void**)&qh, g_qh);   cudaGetSymbolAddress((void**)&ql, g_ql);
    cudaGetSymbolAddress((void**)&kh, g_kh);   cudaGetSymbolAddress((void**)&kl, g_kl);
    cudaGetSymbolAddress((void**)&ath, g_ath); cudaGetSymbolAddress((void**)&atl, g_atl);
    cudaGetSymbolAddress((void**)&v16, g_v16);
    cudaGetSymbolAddress((void**)&c16, g_c16);
    cudaGetSymbolAddress((void**)&wo16, g_wo16);

    const size_t need = (size_t)S_LEN * D_MODEL + (size_t)N_H * S_LEN * S_LEN;
    float* attnBuf = ((size_t)out_size >= need) ? (out + (size_t)S_LEN * D_MODEL) : ap;

    cudaFuncSetAttribute(gemm_pre_kernel, cudaFuncAttributeMaxDynamicSharedMemorySize, GEMM_SMEM);
    cudaFuncSetAttribute(scores_pre_kernel, cudaFuncAttributeMaxDynamicSharedMemorySize, GEMM_SMEM);
    cudaFuncSetAttribute(av_kernel, cudaFuncAttributeMaxDynamicSharedMemorySize, AV_SMEM);
    cudaFuncSetAttribute(gemm_wo16_kernel, cudaFuncAttributeMaxDynamicSharedMemorySize, WO_SMEM);

    const int nBig = 2048 * 2048, nSml = 2048 * 512;

    // 0) pre-split inputs; weights into fused [wq; wk; wv] layout; wo fp16
    split_kernel<<<nBig / 1024, 256>>>(hs, hsh, hsl, nBig);
    split_kernel<<<nBig / 1024, 256>>>(wq, wh, wl, nBig);
    split_kernel<<<nSml / 1024, 256>>>(wk, wh + (size_t)2048 * 2048, wl + (size_t)2048 * 2048, nSml);
    split_kernel<<<nSml / 1024, 256>>>(wv, wh + (size_t)2560 * 2048, wl + (size_t)2560 * 2048, nSml);
    split16_single_kernel<<<nBig / 1024, 256>>>(wo, wo16, nBig);

    // 1) fused qkv projection: [2048 x 3072] = hs @ [wq;wk;wv]^T
    gemm_pre_kernel<<<dim3(QKV_DIM / 128, S_LEN / 128), 128, GEMM_SMEM>>>(
        hsh, hsl, wh, wl, qkvp, QKV_DIM, D_MODEL);

    // 2) RoPE + split (q, k bf16 pairs); v -> single fp16 plane
    {
        int totQ = S_LEN * N_H * (H_DIM / 2);
        int totK = S_LEN * N_KV * (H_DIM / 2);
        rope_split_kernel<<<(totQ + 255) / 256, 256>>>(qkvp, QKV_DIM, cosb, sinb, N_H, qh, ql);
        rope_split_kernel<<<(totK + 255) / 256, 256>>>(qkvp + 2048, QKV_DIM, cosb, sinb, N_KV, kh, kl);
        split16_single_strided_kernel<<<nSml / 1024, 256>>>(qkvp + 2560, QKV_DIM, KV_DIM, v16, nSml);
    }

    // 3) causal scores (3-product bf16 — attn path keeps precision)
    scores_pre_kernel<<<dim3(S_LEN / 128, S_LEN / 128, N_H), 128, GEMM_SMEM>>>(attnBuf);

    // 4) entmax in place + emit fp16 hi/lo attn
    entmax_kernel<<<(N_H * S_LEN) / 8, 256>>>(attnBuf, ath, atl);

    // 5) attn @ v -> ctx (2-product fp16), then single-plane ctx split
    av_kernel<<<dim3(1, S_LEN / 128, N_H), 256, AV_SMEM>>>();
    split16_single_kernel<<<nBig / 1024, 256>>>(cp, c16, nBig);

    // 6) out = ctx16 @ wo16^T  (1-product fp16)
    gemm_wo16_kernel<<<dim3(D_MODEL / 128, S_LEN / 128), 256, WO_SMEM>>>(
        c16, wo16, out, D_MODEL);
}

// round 13
// speedup vs baseline: 1.7859x; 1.0116x over previous
#include <cuda_runtime.h>
#include <cuda_bf16.h>
#include <cuda_fp16.h>
#include <mma.h>
#include <math.h>
#include <stdint.h>

using namespace nvcuda;

#define S_LEN 2048
#define D_MODEL 2048
#define N_H 16
#define N_KV 4
#define H_DIM 128
#define SCALING 0.08838834764831845f
#define DM0 0.9779029130879204f
#define KV_DIM (N_KV * H_DIM)
#define QK_DIM (N_H * H_DIM + KV_DIM)   // 2560

typedef __nv_bfloat16 bf16;
typedef __half fp16;

// fp32 scratch
__device__ float g_qk[(size_t)S_LEN * QK_DIM];
__device__ float g_attn[(size_t)N_H * S_LEN * S_LEN];

// pre-split scratch
#define SZ_BIG  ((size_t)2048 * 2048)
#define SZ_SML  ((size_t)2048 * 512)
#define SZ_WQK  ((size_t)2560 * 2048)
#define SZ_ATT  ((size_t)N_H * S_LEN * S_LEN)
__device__ bf16 g_hsh[SZ_BIG], g_hsl[SZ_BIG];       // hs bf16 pair (qk proj)
__device__ bf16 g_wh[SZ_WQK],  g_wl[SZ_WQK];        // fused [wq; wk]
__device__ bf16 g_qh[SZ_BIG],  g_ql[SZ_BIG];
__device__ bf16 g_kh[SZ_SML],  g_kl[SZ_SML];
// fp16 planes (out path)
__device__ fp16 g_hs16h[SZ_BIG], g_hs16l[SZ_BIG];   // hs fp16 pair (v proj)
__device__ fp16 g_wv16[SZ_SML];                     // wv single plane
__device__ fp16 g_v16[SZ_SML];                      // V (written by v GEMM)
__device__ fp16 g_at16[SZ_ATT];                     // attn single plane (entmax)
__device__ fp16 g_c16[SZ_BIG];                      // ctx (written by AV GEMM)
__device__ fp16 g_wo16[SZ_BIG];                     // wo single plane

__device__ __forceinline__ void split_bf16(float v, bf16& hi, bf16& lo) {
    hi = __float2bfloat16_rn(v);
    lo = __float2bfloat16_rn(v - __bfloat162float(hi));
}
__device__ __forceinline__ uint32_t smem_u32(const void* p) {
    return (uint32_t)__cvta_generic_to_shared(p);
}
#define CP16(dst, src) asm volatile("cp.async.cg.shared.global [%0], [%1], 16;" :: "r"(dst), "l"(src))
#define CP_COMMIT()    asm volatile("cp.async.commit_group;" ::: "memory")
#define CP_WAIT1()     asm volatile("cp.async.wait_group 1;" ::: "memory")
#define CP_WAIT0()     asm volatile("cp.async.wait_group 0;" ::: "memory")

// ===========================================================================
// split kernels
// ===========================================================================
__global__ void split_kernel(const float* __restrict__ x,
                             bf16* __restrict__ hi, bf16* __restrict__ lo, int n)
{
    int i = (blockIdx.x * blockDim.x + threadIdx.x) * 4;
    if (i >= n) return;
    float4 v = *(const float4*)(x + i);
    bf16 h0, l0, h1, l1, h2, l2, h3, l3;
    split_bf16(v.x, h0, l0); split_bf16(v.y, h1, l1);
    split_bf16(v.z, h2, l2); split_bf16(v.w, h3, l3);
    __nv_bfloat162* H = (__nv_bfloat162*)(hi + i);
    __nv_bfloat162* L = (__nv_bfloat162*)(lo + i);
    H[0] = __halves2bfloat162(h0, h1); H[1] = __halves2bfloat162(h2, h3);
    L[0] = __halves2bfloat162(l0, l1); L[1] = __halves2bfloat162(l2, l3);
}

// fp32 -> fp16 hi/lo pair
__global__ void split16_pair_kernel(const float* __restrict__ x,
                                    fp16* __restrict__ hi, fp16* __restrict__ lo, int n)
{
    int i = (blockIdx.x * blockDim.x + threadIdx.x) * 4;
    if (i >= n) return;
    float4 v = *(const float4*)(x + i);
    fp16 h[4], l[4];
    const float* p = (const float*)&v;
#pragma unroll
    for (int e = 0; e < 4; e++) {
        h[e] = __float2half_rn(p[e]);
        l[e] = __float2half_rn(p[e] - __half2float(h[e]));
    }
    __half2* H = (__half2*)(hi + i);
    __half2* L = (__half2*)(lo + i);
    H[0] = __halves2half2(h[0], h[1]); H[1] = __halves2half2(h[2], h[3]);
    L[0] = __halves2half2(l[0], l[1]); L[1] = __halves2half2(l[2], l[3]);
}

// fp32 -> fp16 single plane
__global__ void split16_single_kernel(const float* __restrict__ x,
                                      fp16* __restrict__ h, int n)
{
    int i = (blockIdx.x * blockDim.x + threadIdx.x) * 4;
    if (i >= n) return;
    float4 v = *(const float4*)(x + i);
    __half2* H = (__half2*)(h + i);
    H[0] = __halves2half2(__float2half_rn(v.x), __float2half_rn(v.y));
    H[1] = __halves2half2(__float2half_rn(v.z), __float2half_rn(v.w));
}

// ===========================================================================
// RoPE + split (bf16 pair — attn path keeps full precision)
// ===========================================================================
__global__ void rope_split_kernel(const float* __restrict__ X, int xStride,
                                  const float* __restrict__ cosb,
                                  const float* __restrict__ sinb, int nHeads,
                                  bf16* __restrict__ hi, bf16* __restrict__ lo)
{
    int idx = blockIdx.x * blockDim.x + threadIdx.x;
    int total = S_LEN * nHeads * (H_DIM / 2);
    if (idx >= total) return;
    int d = idx & 63;
    int t = idx >> 6;
    int hh = t % nHeads;
    int s  = t / nHeads;
    float c1 = cosb[s * H_DIM + d];
    float s1 = sinb[s * H_DIM + d];
    float c2 = cosb[s * H_DIM + d + 64];
    float s2 = sinb[s * H_DIM + d + 64];
    size_t src = (size_t)s * xStride + (size_t)hh * H_DIM + d;
    size_t dst = (size_t)s * nHeads * H_DIM + (size_t)hh * H_DIM + d;
    float x1 = X[src];
    float x2 = X[src + 64];
    float y1 = x1 * c1 - x2 * s1;
    float y2 = x2 * c2 + x1 * s2;
    bf16 h, l;
    split_bf16(y1, h, l); hi[dst] = h;      lo[dst] = l;
    split_bf16(y2, h, l); hi[dst + 64] = h; lo[dst + 64] = l;
}

// ===========================================================================
// Pipelined split-bf16 NT GEMM core (3-product): BM=BN=128, BK=32,
// 128 threads (4 warps), warp tile 64x64, 2-stage cp.async, 80KB SMEM.
// ===========================================================================
#define GEMM_SMEM (2 * 20480 * (int)sizeof(bf16))

__device__ __forceinline__ void gemm_core(
    const bf16* __restrict__ Ah, const bf16* __restrict__ Al,
    const bf16* __restrict__ Bh, const bf16* __restrict__ Bl,
    int lda, int ldb, int K, int mBase, int nBase,
    float* __restrict__ C, int ldc, float scale)
{
    extern __shared__ bf16 sm[];
    const int tid = threadIdx.x;          // 0..127
    const int warp = tid >> 5;            // 0..3
    const int wm = warp >> 1;             // 0..1
    const int wn = warp & 1;              // 0..1

    wmma::fragment<wmma::accumulator, 16, 16, 16, float> acc[4][4];
#pragma unroll
    for (int i = 0; i < 4; i++)
#pragma unroll
        for (int j = 0; j < 4; j++) wmma::fill_fragment(acc[i][j], 0.0f);

    const bf16* Ap_h = Ah + (size_t)(mBase + tid) * lda;
    const bf16* Ap_l = Al + (size_t)(mBase + tid) * lda;
    const bf16* Bp_h = Bh + (size_t)(nBase + tid) * ldb;
    const bf16* Bp_l = Bl + (size_t)(nBase + tid) * ldb;
    const uint32_t dbase = smem_u32(sm) + tid * 80;

    const int T = K >> 5;

#define LOAD_STAGE(buf, k0) do { \
        uint32_t d = dbase + (buf) * 40960; \
        CP16(d,          Ap_h + (k0));      CP16(d + 16,          Ap_h + (k0) + 8); \
        CP16(d + 32,     Ap_h + (k0) + 16); CP16(d + 48,          Ap_h + (k0) + 24); \
        CP16(d + 10240,      Ap_l + (k0));      CP16(d + 10240 + 16, Ap_l + (k0) + 8); \
        CP16(d + 10240 + 32, Ap_l + (k0) + 16); CP16(d + 10240 + 48, Ap_l + (k0) + 24); \
        CP16(d + 20480,      Bp_h + (k0));      CP16(d + 20480 + 16, Bp_h + (k0) + 8); \
        CP16(d + 20480 + 32, Bp_h + (k0) + 16); CP16(d + 20480 + 48, Bp_h + (k0) + 24); \
        CP16(d + 30720,      Bp_l + (k0));      CP16(d + 30720 + 16, Bp_l + (k0) + 8); \
        CP16(d + 30720 + 32, Bp_l + (k0) + 16); CP16(d + 30720 + 48, Bp_l + (k0) + 24); \
        CP_COMMIT(); \
    } while (0)

    LOAD_STAGE(0, 0);

#pragma unroll 1
    for (int t = 0; t < T; t++) {
        if (t + 1 < T) {
            LOAD_STAGE((t + 1) & 1, (t + 1) * 32);
            CP_WAIT1();
        } else {
            CP_WAIT0();
        }
        __syncthreads();

        bf16* st   = sm + (t & 1) * 20480;
        bf16* Ah_s = st;
        bf16* Al_s = st + 5120;
        bf16* Bh_s = st + 10240;
        bf16* Bl_s = st + 15360;
#pragma unroll
        for (int ks = 0; ks < 32; ks += 16) {
            wmma::fragment<wmma::matrix_b, 16, 16, 16, bf16, wmma::col_major> bh[4], bl[4];
#pragma unroll
            for (int j = 0; j < 4; j++) {
                wmma::load_matrix_sync(bh[j], &Bh_s[(wn * 64 + j * 16) * 40 + ks], 40);
                wmma::load_matrix_sync(bl[j], &Bl_s[(wn * 64 + j * 16) * 40 + ks], 40);
            }
#pragma unroll
            for (int i = 0; i < 4; i++) {
                wmma::fragment<wmma::matrix_a, 16, 16, 16, bf16, wmma::row_major> ah, al;
                wmma::load_matrix_sync(ah, &Ah_s[(wm * 64 + i * 16) * 40 + ks], 40);
                wmma::load_matrix_sync(al, &Al_s[(wm * 64 + i * 16) * 40 + ks], 40);
#pragma unroll
                for (int j = 0; j < 4; j++) {
                    wmma::mma_sync(acc[i][j], ah, bl[j], acc[i][j]);
                    wmma::mma_sync(acc[i][j], al, bh[j], acc[i][j]);
                    wmma::mma_sync(acc[i][j], ah, bh[j], acc[i][j]);
                }
            }
        }
        __syncthreads();
    }
#undef LOAD_STAGE

#pragma unroll
    for (int i = 0; i < 4; i++)
#pragma unroll
        for (int j = 0; j < 4; j++) {
#pragma unroll
            for (int t = 0; t < acc[i][j].num_elements; t++) acc[i][j].x[t] *= scale;
            wmma::store_matrix_sync(
                C + (size_t)(mBase + wm * 64 + i * 16) * ldc + nBase + wn * 64 + j * 16,
                acc[i][j], ldc, wmma::mem_row_major);
        }
}

__global__ void __launch_bounds__(128) gemm_pre_kernel(
    const bf16* Ah, const bf16* Al, const bf16* Bh, const bf16* Bl,
    float* C, int ldc, int K)
{
    gemm_core(Ah, Al, Bh, Bl, K, K, K, blockIdx.y * 128, blockIdx.x * 128, C, ldc, 1.0f);
}

__global__ void __launch_bounds__(128) scores_pre_kernel(float* __restrict__ attn)
{
    const int h = blockIdx.z;
    const int mBase = blockIdx.y * 128;
    const int nBase = blockIdx.x * 128;
    if (nBase > mBase + 127) return;
    gemm_core(g_qh + h * H_DIM, g_ql + h * H_DIM,
              g_kh + (h >> 2) * H_DIM, g_kl + (h >> 2) * H_DIM,
              N_H * H_DIM, KV_DIM, H_DIM, mBase, nBase,
              attn + (size_t)h * S_LEN * S_LEN, S_LEN, SCALING);
}

// ===========================================================================
// v projection: V16 = hs16(hi/lo) @ wv16^T, 2 fp16 products, fp16 output.
// BM=BN=128, BK=32, 256 threads (warp tile 32x64), 2-stage cp.async.
// Stage (bytes): Ah@0, Al@10240, B@20480 -> 30720; 2 stages = 61440.
// ===========================================================================
#define V_STAGE 30720
#define V_SMEM  (2 * V_STAGE)

__global__ void __launch_bounds__(256) gemm_v16_kernel(
    const fp16* __restrict__ Ah, const fp16* __restrict__ Al,
    const fp16* __restrict__ B, fp16* __restrict__ C, int K, int ldc)
{
    extern __shared__ fp16 smh[];
    const int tid = threadIdx.x;
    const int warp = tid >> 5;
    const int wm = warp & 3;
    const int wn = warp >> 2;
    const int mBase = blockIdx.y * 128;
    const int nBase = blockIdx.x * 128;

    wmma::fragment<wmma::accumulator, 16, 16, 16, float> acc[2][4];
#pragma unroll
    for (int i = 0; i < 2; i++)
#pragma unroll
        for (int j = 0; j < 4; j++) wmma::fill_fragment(acc[i][j], 0.0f);

    const int r  = tid >> 1;
    const int cc = (tid & 1) * 16;

    const fp16* ApH = Ah + (size_t)(mBase + r) * K + cc;
    const fp16* ApL = Al + (size_t)(mBase + r) * K + cc;
    const fp16* Bp  = B  + (size_t)(nBase + r) * K + cc;
    const uint32_t dbase = smem_u32(smh) + r * 80 + cc * 2;

    const int T = K >> 5;

#define V_LOAD(buf, k0) do { \
        uint32_t d = dbase + (buf) * V_STAGE; \
        CP16(d,              ApH + (k0)); CP16(d + 16,          ApH + (k0) + 8); \
        CP16(d + 10240,      ApL + (k0)); CP16(d + 10240 + 16,  ApL + (k0) + 8); \
        CP16(d + 20480,      Bp  + (k0)); CP16(d + 20480 + 16,  Bp  + (k0) + 8); \
        CP_COMMIT(); \
    } while (0)

    V_LOAD(0, 0);

#pragma unroll 1
    for (int t = 0; t < T; t++) {
        if (t + 1 < T) {
            V_LOAD((t + 1) & 1, (t + 1) * 32);
            CP_WAIT1();
        } else {
            CP_WAIT0();
        }
        __syncthreads();

        fp16* st   = smh + (t & 1) * (V_STAGE / 2);
        fp16* Ah_s = st;
        fp16* Al_s = st + 5120;
        fp16* B_s  = st + 10240;
#pragma unroll
        for (int ks = 0; ks < 32; ks += 16) {
            wmma::fragment<wmma::matrix_b, 16, 16, 16, fp16, wmma::col_major> bf[4];
#pragma unroll
            for (int j = 0; j < 4; j++)
                wmma::load_matrix_sync(bf[j], &B_s[(wn * 64 + j * 16) * 40 + ks], 40);
            wmma::fragment<wmma::matrix_a, 16, 16, 16, fp16, wmma::row_major> ah[2], al[2];
#pragma unroll
            for (int i = 0; i < 2; i++) {
                wmma::load_matrix_sync(ah[i], &Ah_s[(wm * 32 + i * 16) * 40 + ks], 40);
                wmma::load_matrix_sync(al[i], &Al_s[(wm * 32 + i * 16) * 40 + ks], 40);
            }
#pragma unroll
            for (int i = 0; i < 2; i++)
#pragma unroll
                for (int j = 0; j < 4; j++) {
                    wmma::mma_sync(acc[i][j], al[i], bf[j], acc[i][j]);
                    wmma::mma_sync(acc[i][j], ah[i], bf[j], acc[i][j]);
                }
        }
        __syncthreads();
    }
#undef V_LOAD

#pragma unroll
    for (int i = 0; i < 2; i++)
#pragma unroll
        for (int j = 0; j < 4; j++) {
            wmma::fragment<wmma::accumulator, 16, 16, 16, fp16> hacc;
#pragma unroll
            for (int t = 0; t < hacc.num_elements; t++)
                hacc.x[t] = __float2half_rn(acc[i][j].x[t]);
            wmma::store_matrix_sync(
                C + (size_t)(mBase + wm * 32 + i * 16) * ldc + nBase + wn * 64 + j * 16,
                hacc, ldc, wmma::mem_row_major);
        }
}

// ===========================================================================
// wo GEMM: out = ctx16 @ wo16^T, single fp16 product, fp32 accum/out.
// ===========================================================================
#define WO_STAGE 20480
#define WO_SMEM  (2 * WO_STAGE)

__global__ void __launch_bounds__(256) gemm_wo16_kernel(
    const fp16* __restrict__ A, const fp16* __restrict__ B,
    float* __restrict__ C, int K)
{
    extern __shared__ fp16 smh[];
    const int tid = threadIdx.x;
    const int warp = tid >> 5;
    const int wm = warp & 3;
    const int wn = warp >> 2;
    const int mBase = blockIdx.y * 128;
    const int nBase = blockIdx.x * 128;

    wmma::fragment<wmma::accumulator, 16, 16, 16, float> acc[2][4];
#pragma unroll
    for (int i = 0; i < 2; i++)
#pragma unroll
        for (int j = 0; j < 4; j++) wmma::fill_fragment(acc[i][j], 0.0f);

    const int r  = tid >> 1;
    const int cc = (tid & 1) * 16;

    const fp16* Ap = A + (size_t)(mBase + r) * K + cc;
    const fp16* Bp = B + (size_t)(nBase + r) * K + cc;
    const uint32_t dbase = smem_u32(smh) + r * 80 + cc * 2;

    const int T = K >> 5;

#define WO_LOAD(buf, k0) do { \
        uint32_t d = dbase + (buf) * WO_STAGE; \
        CP16(d,          Ap + (k0)); CP16(d + 16,          Ap + (k0) + 8); \
        CP16(d + 10240,  Bp + (k0)); CP16(d + 10240 + 16,  Bp + (k0) + 8); \
        CP_COMMIT(); \
    } while (0)

    WO_LOAD(0, 0);

#pragma unroll 1
    for (int t = 0; t < T; t++) {
        if (t + 1 < T) {
            WO_LOAD((t + 1) & 1, (t + 1) * 32);
            CP_WAIT1();
        } else {
            CP_WAIT0();
        }
        __syncthreads();

        fp16* st  = smh + (t & 1) * (WO_STAGE / 2);
        fp16* A_s = st;
        fp16* B_s = st + 5120;
#pragma unroll
        for (int ks = 0; ks < 32; ks += 16) {
            wmma::fragment<wmma::matrix_b, 16, 16, 16, fp16, wmma::col_major> bf[4];
#pragma unroll
            for (int j = 0; j < 4; j++)
                wmma::load_matrix_sync(bf[j], &B_s[(wn * 64 + j * 16) * 40 + ks], 40);
            wmma::fragment<wmma::matrix_a, 16, 16, 16, fp16, wmma::row_major> af[2];
#pragma unroll
            for (int i = 0; i < 2; i++)
                wmma::load_matrix_sync(af[i], &A_s[(wm * 32 + i * 16) * 40 + ks], 40);
#pragma unroll
            for (int i = 0; i < 2; i++)
#pragma unroll
                for (int j = 0; j < 4; j++)
                    wmma::mma_sync(acc[i][j], af[i], bf[j], acc[i][j]);
        }
        __syncthreads();
    }
#undef WO_LOAD

#pragma unroll
    for (int i = 0; i < 2; i++)
#pragma unroll
        for (int j = 0; j < 4; j++)
            wmma::store_matrix_sync(
                C + (size_t)(mBase + wm * 32 + i * 16) * D_MODEL + nBase + wn * 64 + j * 16,
                acc[i][j], D_MODEL, wmma::mem_row_major);
}

// ===========================================================================
// alpha-entmax (alpha=1.5), 32-iter bisection, ONE WARP PER ROW (shfl only).
// Emits fp16 single-plane attn for the AV GEMM.
// ===========================================================================
template <int CH>
__device__ __forceinline__ void entmax_row_warp(float* __restrict__ x,
                                                fp16* __restrict__ xh,
                                                int n, int lane)
{
    float X[CH];
    float lmax = -INFINITY;
#pragma unroll
    for (int i = 0; i < CH; i++) {
        int j = lane + i * 32;
        if (j < n) {
            float v = x[j] * 0.5f;
            X[i] = v;
            lmax = fmaxf(lmax, v);
        } else {
            X[i] = -INFINITY;
        }
    }
#pragma unroll
    for (int o = 16; o > 0; o >>= 1) lmax = fmaxf(lmax, __shfl_xor_sync(0xffffffffu, lmax, o));

    float tau_lo = lmax - 1.0f;
    float dm = DM0;
    float tau_m = tau_lo;
#pragma unroll 1
    for (int it = 0; it < 32; it++) {
        dm *= 0.5f;
        tau_m = tau_lo + dm;
        float ls = 0.f;
#pragma unroll
        for (int i = 0; i < CH; i++) {
            float t = fmaxf(X[i] - tau_m, 0.f);
            ls = fmaf(t, t, ls);
        }
#pragma unroll
        for (int o = 16; o > 0; o >>= 1) ls += __shfl_xor_sync(0xffffffffu, ls, o);
        if (ls >= 1.0f) tau_lo = tau_m;
    }

    float ls = 0.f;
#pragma unroll
    for (int i = 0; i < CH; i++) {
        float t = fmaxf(X[i] - tau_m, 0.f);
        ls = fmaf(t, t, ls);
    }
#pragma unroll
    for (int o = 16; o > 0; o >>= 1) ls += __shfl_xor_sync(0xffffffffu, ls, o);
    float inv = 1.0f / ls;

#pragma unroll
    for (int i = 0; i < CH; i++) {
        int j = lane + i * 32;
        float t = fmaxf(X[i] - tau_m, 0.f);
        float v = (j < n) ? t * t * inv : 0.0f;
        x[j] = v;
        xh[j] = __float2half_rn(v);
    }
#pragma unroll
    for (int i = CH; i < 64; i++) {
        int j = lane + i * 32;
        x[j] = 0.0f;
        xh[j] = __float2half_rn(0.0f);
    }
}

__global__ void __launch_bounds__(256) entmax_kernel(float* __restrict__ attn,
                                                     fp16* __restrict__ at16)
{
    const int idx = blockIdx.x * 8 + (threadIdx.x >> 5);
    const int lane = threadIdx.x & 31;
    const int h = idx >> 11;
    const int q = idx & 2047;
    size_t off = (size_t)h * S_LEN * S_LEN + (size_t)q * S_LEN;
    float* x = attn + off;
    fp16* xh = at16 + off;
    const int n = q + 1;
    const int c8 = (((n + 31) >> 5) + 7) >> 3;

    switch (c8) {
        case 1: entmax_row_warp<8>(x, xh, n, lane); break;
        case 2: entmax_row_warp<16>(x, xh, n, lane); break;
        case 3: entmax_row_warp<24>(x, xh, n, lane); break;
        case 4: entmax_row_warp<32>(x, xh, n, lane); break;
        case 5: entmax_row_warp<40>(x, xh, n, lane); break;
        case 6: entmax_row_warp<48>(x, xh, n, lane); break;
        case 7: entmax_row_warp<56>(x, xh, n, lane); break;
        default: entmax_row_warp<64>(x, xh, n, lane); break;
    }
}

// ===========================================================================
// attn @ V: attn fp16 single x V fp16 single = 1 product, fp16 ctx output.
// 128x128 C tile, BK=32, 256 threads, warp tile 32x64, 2-stage cp.async.
// Stage (bytes): A@0 (10240), B@10240 (8704) -> 18944; 2 stages = 37888.
// ===========================================================================
#define AV_STAGE 18944
#define AV_SMEM  (2 * AV_STAGE)

__global__ void __launch_bounds__(256) av_kernel()
{
    extern __shared__ fp16 smh[];
    const int h = blockIdx.z;
    const int mBase = (gridDim.y - 1 - blockIdx.y) * 128;

    const int tid = threadIdx.x;
    const int warp = tid >> 5;
    const int wm = warp & 3;
    const int wn = warp >> 2;

    const fp16* A_g = g_at16 + (size_t)h * S_LEN * S_LEN;
    const fp16* B_g = g_v16 + (h >> 2) * H_DIM;

    const int rA = tid >> 1;
    const int cA = (tid & 1) * 16;
    const int rB = tid >> 3;
    const int cB = (tid & 7) * 16;

    const fp16* Ap = A_g + (size_t)(mBase + rA) * S_LEN + cA;
    const fp16* Bp = B_g + (size_t)rB * KV_DIM + cB;

    const uint32_t sb = smem_u32(smh);
    const uint32_t dA = sb + rA * 80 + cA * 2;
    const uint32_t dB = sb + 10240 + rB * 272 + cB * 2;

    wmma::fragment<wmma::accumulator, 16, 16, 16, float> acc[2][4];
#pragma unroll
    for (int i = 0; i < 2; i++)
#pragma unroll
        for (int j = 0; j < 4; j++) wmma::fill_fragment(acc[i][j], 0.0f);

    const int T = (mBase + 128) >> 5;

#define AV_LOAD(buf, k0) do { \
        uint32_t da = dA + (buf) * AV_STAGE; \
        CP16(da, Ap + (k0)); CP16(da + 16, Ap + (k0) + 8); \
        uint32_t db = dB + (buf) * AV_STAGE; \
        CP16(db, Bp + (size_t)(k0) * KV_DIM); CP16(db + 16, Bp + (size_t)(k0) * KV_DIM + 8); \
        CP_COMMIT(); \
    } while (0)

    AV_LOAD(0, 0);

#pragma unroll 1
    for (int t = 0; t < T; t++) {
        if (t + 1 < T) {
            AV_LOAD((t + 1) & 1, (t + 1) * 32);
            CP_WAIT1();
        } else {
            CP_WAIT0();
        }
        __syncthreads();

        fp16* st  = smh + (t & 1) * (AV_STAGE / 2);
        fp16* A_s = st;
        fp16* B_s = st + 5120;
#pragma unroll
        for (int ks = 0; ks < 32; ks += 16) {
            wmma::fragment<wmma::matrix_a, 16, 16, 16, fp16, wmma::row_major> af[2];
            wmma::fragment<wmma::matrix_b, 16, 16, 16, fp16, wmma::row_major> bf[4];
#pragma unroll
            for (int i = 0; i < 2; i++)
                wmma::load_matrix_sync(af[i], &A_s[(wm * 32 + i * 16) * 40 + ks], 40);
#pragma unroll
            for (int j = 0; j < 4; j++)
                wmma::load_matrix_sync(bf[j], &B_s[ks * 136 + wn * 64 + j * 16], 136);
#pragma unroll
            for (int i = 0; i < 2; i++)
#pragma unroll
                for (int j = 0; j < 4; j++)
                    wmma::mma_sync(acc[i][j], af[i], bf[j], acc[i][j]);
        }
        __syncthreads();
    }
#undef AV_LOAD

#pragma unroll
    for (int i = 0; i < 2; i++)
#pragma unroll
        for (int j = 0; j < 4; j++) {
            wmma::fragment<wmma::accumulator, 16, 16, 16, fp16> hacc;
#pragma unroll
            for (int t = 0; t < hacc.num_elements; t++)
                hacc.x[t] = __float2half_rn(acc[i][j].x[t]);
            wmma::store_matrix_sync(
                g_c16 + (size_t)(mBase + wm * 32 + i * 16) * (N_H * H_DIM)
                      + h * H_DIM + wn * 64 + j * 16,
                hacc, N_H * H_DIM, wmma::mem_row_major);
        }
}

// ===========================================================================
extern "C" void kernel_launch(void* const* d_in, const int* in_sizes, int n_in,
                              void* d_out, int out_size)
{
    const float* hs   = (const float*)d_in[0];
    const float* cosb = (const float*)d_in[1];
    const float* sinb = (const float*)d_in[2];
    const float* wq   = (const float*)d_in[3];
    const float* wk   = (const float*)d_in[4];
    const float* wv   = (const float*)d_in[5];
    const float* wo   = (const float*)d_in[6];
    float* out = (float*)d_out;

    float *qkp, *ap;
    cudaGetSymbolAddress((void**)&qkp, g_qk);
    cudaGetSymbolAddress((void**)&ap, g_attn);

    bf16 *hsh, *hsl, *wh, *wl, *qh, *ql, *kh, *kl;
    fp16 *hs16h, *hs16l, *wv16, *v16, *at16, *c16, *wo16;
    cudaGetSymbolAddress((void**)&hsh, g_hsh); cudaGetSymbolAddress((void**)&hsl, g_hsl);
    cudaGetSymbolAddress((void**)&wh, g_wh);   cudaGetSymbolAddress((void**)&wl, g_wl);
    cudaGetSymbolAddress((void**)&qh, g_qh);   cudaGetSymbolAddress((void**)&ql, g_ql);
    cudaGetSymbolAddress((void**)&kh, g_kh);   cudaGetSymbolAddress((void**)&kl, g_kl);
    cudaGetSymbolAddress((void**)&hs16h, g_hs16h); cudaGetSymbolAddress((void**)&hs16l, g_hs16l);
    cudaGetSymbolAddress((void**)&wv16, g_wv16);
    cudaGetSymbolAddress((void**)&v16, g_v16);
    cudaGetSymbolAddress((void**)&at16, g_at16);
    cudaGetSymbolAddress((void**)&c16, g_c16);
    cudaGetSymbolAddress((void**)&wo16, g_wo16);

    const size_t need = (size_t)S_LEN * D_MODEL + (size_t)N_H * S_LEN * S_LEN;
    float* attnBuf = ((size_t)out_size >= need) ? (out + (size_t)S_LEN * D_MODEL) : ap;

    cudaFuncSetAttribute(gemm_pre_kernel, cudaFuncAttributeMaxDynamicSharedMemorySize, GEMM_SMEM);
    cudaFuncSetAttribute(scores_pre_kernel, cudaFuncAttributeMaxDynamicSharedMemorySize, GEMM_SMEM);
    cudaFuncSetAttribute(av_kernel, cudaFuncAttributeMaxDynamicSharedMemorySize, AV_SMEM);
    cudaFuncSetAttribute(gemm_wo16_kernel, cudaFuncAttributeMaxDynamicSharedMemorySize, WO_SMEM);
    cudaFuncSetAttribute(gemm_v16_kernel, cudaFuncAttributeMaxDynamicSharedMemorySize, V_SMEM);

    const int nBig = 2048 * 2048, nSml = 2048 * 512;

    // 0) pre-splits
    split_kernel<<<nBig / 1024, 256>>>(hs, hsh, hsl, nBig);
    split16_pair_kernel<<<nBig / 1024, 256>>>(hs, hs16h, hs16l, nBig);
    split_kernel<<<nBig / 1024, 256>>>(wq, wh, wl, nBig);
    split_kernel<<<nSml / 1024, 256>>>(wk, wh + (size_t)2048 * 2048, wl + (size_t)2048 * 2048, nSml);
    split16_single_kernel<<<nSml / 1024, 256>>>(wv, wv16, nSml);
    split16_single_kernel<<<nBig / 1024, 256>>>(wo, wo16, nBig);

    // 1) qk projection: [2048 x 2560] = hs @ [wq;wk]^T  (3-product bf16)
    gemm_pre_kernel<<<dim3(QK_DIM / 128, S_LEN / 128), 128, GEMM_SMEM>>>(
        hsh, hsl, wh, wl, qkp, QK_DIM, D_MODEL);
    // 1b) v projection: fp16 2-product, fp16 output
    gemm_v16_kernel<<<dim3(KV_DIM / 128, S_LEN / 128), 256, V_SMEM>>>(
        hs16h, hs16l, wv16, v16, D_MODEL, KV_DIM);

    // 2) RoPE + split (q, k bf16 pairs)
    {
        int totQ = S_LEN * N_H * (H_DIM / 2);
        int totK = S_LEN * N_KV * (H_DIM / 2);
        rope_split_kernel<<<(totQ + 255) / 256, 256>>>(qkp, QK_DIM, cosb, sinb, N_H, qh, ql);
        rope_split_kernel<<<(totK + 255) / 256, 256>>>(qkp + 2048, QK_DIM, cosb, sinb, N_KV, kh, kl);
    }

    // 3) causal scores (3-product bf16 — attn path keeps precision)
    scores_pre_kernel<<<dim3(S_LEN / 128, S_LEN / 128, N_H), 128, GEMM_SMEM>>>(attnBuf);

    // 4) entmax in place + emit fp16 attn plane
    entmax_kernel<<<(N_H * S_LEN) / 8, 256>>>(attnBuf, at16);

    // 5) attn @ v -> ctx16 (1-product fp16, fp16 out)
    av_kernel<<<dim3(1, S_LEN / 128, N_H), 256, AV_SMEM>>>();

    // 6) out = ctx16 @ wo16^T  (1-product fp16)
    gemm_wo16_kernel<<<dim3(D_MODEL / 128, S_LEN / 128), 256, WO_SMEM>>>(
        c16, wo16, out, D_MODEL);
}

// round 14
// speedup vs baseline: 1.9321x; 1.0818x over previous
#include <cuda_runtime.h>
#include <cuda_bf16.h>
#include <cuda_fp16.h>
#include <mma.h>
#include <math.h>
#include <stdint.h>

using namespace nvcuda;

#define S_LEN 2048
#define D_MODEL 2048
#define N_H 16
#define N_KV 4
#define H_DIM 128
#define SCALING 0.08838834764831845f
#define DM0 0.9779029130879204f
#define KV_DIM (N_KV * H_DIM)
#define QK_DIM (N_H * H_DIM + KV_DIM)   // 2560
#define QK_XTILES (QK_DIM / 128)        // 20
#define V_XTILES (KV_DIM / 128)         // 4

typedef __nv_bfloat16 bf16;
typedef __half fp16;

// fp32 scratch
__device__ float g_qk[(size_t)S_LEN * QK_DIM];
__device__ float g_attn[(size_t)N_H * S_LEN * S_LEN];

// pre-split scratch
#define SZ_BIG  ((size_t)2048 * 2048)
#define SZ_SML  ((size_t)2048 * 512)
#define SZ_WQK  ((size_t)2560 * 2048)
#define SZ_ATT  ((size_t)N_H * S_LEN * S_LEN)
__device__ bf16 g_hsh[SZ_BIG], g_hsl[SZ_BIG];       // hs bf16 pair (qk proj)
__device__ bf16 g_wh[SZ_WQK],  g_wl[SZ_WQK];        // fused [wq; wk]
__device__ bf16 g_qh[SZ_BIG],  g_ql[SZ_BIG];
__device__ bf16 g_kh[SZ_SML],  g_kl[SZ_SML];
// fp16 planes (out path)
__device__ fp16 g_hs16h[SZ_BIG], g_hs16l[SZ_BIG];   // hs fp16 pair (v proj)
__device__ fp16 g_wv16[SZ_SML];                     // wv single plane
__device__ fp16 g_v16[SZ_SML];                      // V (written by v GEMM)
__device__ fp16 g_at16[SZ_ATT];                     // attn single plane (entmax)
__device__ fp16 g_c16[SZ_BIG];                      // ctx (written by AV GEMM)
__device__ fp16 g_wo16[SZ_BIG];                     // wo single plane

__device__ __forceinline__ void split_bf16(float v, bf16& hi, bf16& lo) {
    hi = __float2bfloat16_rn(v);
    lo = __float2bfloat16_rn(v - __bfloat162float(hi));
}
__device__ __forceinline__ uint32_t smem_u32(const void* p) {
    return (uint32_t)__cvta_generic_to_shared(p);
}
#define CP16(dst, src) asm volatile("cp.async.cg.shared.global [%0], [%1], 16;" :: "r"(dst), "l"(src))
#define CP_COMMIT()    asm volatile("cp.async.commit_group;" ::: "memory")
#define CP_WAIT1()     asm volatile("cp.async.wait_group 1;" ::: "memory")
#define CP_WAIT0()     asm volatile("cp.async.wait_group 0;" ::: "memory")

// ===========================================================================
// split kernels
// ===========================================================================
__global__ void split_kernel(const float* __restrict__ x,
                             bf16* __restrict__ hi, bf16* __restrict__ lo, int n)
{
    int i = (blockIdx.x * blockDim.x + threadIdx.x) * 4;
    if (i >= n) return;
    float4 v = *(const float4*)(x + i);
    bf16 h0, l0, h1, l1, h2, l2, h3, l3;
    split_bf16(v.x, h0, l0); split_bf16(v.y, h1, l1);
    split_bf16(v.z, h2, l2); split_bf16(v.w, h3, l3);
    __nv_bfloat162* H = (__nv_bfloat162*)(hi + i);
    __nv_bfloat162* L = (__nv_bfloat162*)(lo + i);
    H[0] = __halves2bfloat162(h0, h1); H[1] = __halves2bfloat162(h2, h3);
    L[0] = __halves2bfloat162(l0, l1); L[1] = __halves2bfloat162(l2, l3);
}

// hs: one read -> bf16 pair + fp16 pair
__global__ void split_hs4_kernel(const float* __restrict__ x,
                                 bf16* __restrict__ bh, bf16* __restrict__ bl,
                                 fp16* __restrict__ fh, fp16* __restrict__ fl, int n)
{
    int i = (blockIdx.x * blockDim.x + threadIdx.x) * 4;
    if (i >= n) return;
    float4 v = *(const float4*)(x + i);
    const float* p = (const float*)&v;
    bf16 h[4], l[4];
    fp16 fh4[4], fl4[4];
#pragma unroll
    for (int e = 0; e < 4; e++) {
        split_bf16(p[e], h[e], l[e]);
        fh4[e] = __float2half_rn(p[e]);
        fl4[e] = __float2half_rn(p[e] - __half2float(fh4[e]));
    }
    __nv_bfloat162* BH = (__nv_bfloat162*)(bh + i);
    __nv_bfloat162* BL = (__nv_bfloat162*)(bl + i);
    BH[0] = __halves2bfloat162(h[0], h[1]); BH[1] = __halves2bfloat162(h[2], h[3]);
    BL[0] = __halves2bfloat162(l[0], l[1]); BL[1] = __halves2bfloat162(l[2], l[3]);
    __half2* FH = (__half2*)(fh + i);
    __half2* FL = (__half2*)(fl + i);
    FH[0] = __halves2half2(fh4[0], fh4[1]); FH[1] = __halves2half2(fh4[2], fh4[3]);
    FL[0] = __halves2half2(fl4[0], fl4[1]); FL[1] = __halves2half2(fl4[2], fl4[3]);
}

// fp32 -> fp16 single plane
__global__ void split16_single_kernel(const float* __restrict__ x,
                                      fp16* __restrict__ h, int n)
{
    int i = (blockIdx.x * blockDim.x + threadIdx.x) * 4;
    if (i >= n) return;
    float4 v = *(const float4*)(x + i);
    __half2* H = (__half2*)(h + i);
    H[0] = __halves2half2(__float2half_rn(v.x), __float2half_rn(v.y));
    H[1] = __halves2half2(__float2half_rn(v.z), __float2half_rn(v.w));
}

// ===========================================================================
// RoPE + split (bf16 pair — attn path keeps full precision)
// ===========================================================================
__global__ void rope_split_kernel(const float* __restrict__ X, int xStride,
                                  const float* __restrict__ cosb,
                                  const float* __restrict__ sinb, int nHeads,
                                  bf16* __restrict__ hi, bf16* __restrict__ lo)
{
    int idx = blockIdx.x * blockDim.x + threadIdx.x;
    int total = S_LEN * nHeads * (H_DIM / 2);
    if (idx >= total) return;
    int d = idx & 63;
    int t = idx >> 6;
    int hh = t % nHeads;
    int s  = t / nHeads;
    float c1 = cosb[s * H_DIM + d];
    float s1 = sinb[s * H_DIM + d];
    float c2 = cosb[s * H_DIM + d + 64];
    float s2 = sinb[s * H_DIM + d + 64];
    size_t src = (size_t)s * xStride + (size_t)hh * H_DIM + d;
    size_t dst = (size_t)s * nHeads * H_DIM + (size_t)hh * H_DIM + d;
    float x1 = X[src];
    float x2 = X[src + 64];
    float y1 = x1 * c1 - x2 * s1;
    float y2 = x2 * c2 + x1 * s2;
    bf16 h, l;
    split_bf16(y1, h, l); hi[dst] = h;      lo[dst] = l;
    split_bf16(y2, h, l); hi[dst + 64] = h; lo[dst + 64] = l;
}

// ===========================================================================
// Pipelined split-bf16 NT GEMM core (3-product): BM=BN=128, BK=32,
// 128 threads (4 warps), warp tile 64x64, 2-stage cp.async, 80KB SMEM.
// ===========================================================================
#define GEMM_SMEM (2 * 20480 * (int)sizeof(bf16))

__device__ __forceinline__ void gemm_core(
    const bf16* __restrict__ Ah, const bf16* __restrict__ Al,
    const bf16* __restrict__ Bh, const bf16* __restrict__ Bl,
    int lda, int ldb, int K, int mBase, int nBase,
    float* __restrict__ C, int ldc, float scale)
{
    extern __shared__ char smraw[];
    bf16* sm = (bf16*)smraw;
    const int tid = threadIdx.x;          // 0..127
    const int warp = tid >> 5;            // 0..3
    const int wm = warp >> 1;             // 0..1
    const int wn = warp & 1;              // 0..1

    wmma::fragment<wmma::accumulator, 16, 16, 16, float> acc[4][4];
#pragma unroll
    for (int i = 0; i < 4; i++)
#pragma unroll
        for (int j = 0; j < 4; j++) wmma::fill_fragment(acc[i][j], 0.0f);

    const bf16* Ap_h = Ah + (size_t)(mBase + tid) * lda;
    const bf16* Ap_l = Al + (size_t)(mBase + tid) * lda;
    const bf16* Bp_h = Bh + (size_t)(nBase + tid) * ldb;
    const bf16* Bp_l = Bl + (size_t)(nBase + tid) * ldb;
    const uint32_t dbase = smem_u32(sm) + tid * 80;

    const int T = K >> 5;

#define LOAD_STAGE(buf, k0) do { \
        uint32_t d = dbase + (buf) * 40960; \
        CP16(d,          Ap_h + (k0));      CP16(d + 16,          Ap_h + (k0) + 8); \
        CP16(d + 32,     Ap_h + (k0) + 16); CP16(d + 48,          Ap_h + (k0) + 24); \
        CP16(d + 10240,      Ap_l + (k0));      CP16(d + 10240 + 16, Ap_l + (k0) + 8); \
        CP16(d + 10240 + 32, Ap_l + (k0) + 16); CP16(d + 10240 + 48, Ap_l + (k0) + 24); \
        CP16(d + 20480,      Bp_h + (k0));      CP16(d + 20480 + 16, Bp_h + (k0) + 8); \
        CP16(d + 20480 + 32, Bp_h + (k0) + 16); CP16(d + 20480 + 48, Bp_h + (k0) + 24); \
        CP16(d + 30720,      Bp_l + (k0));      CP16(d + 30720 + 16, Bp_l + (k0) + 8); \
        CP16(d + 30720 + 32, Bp_l + (k0) + 16); CP16(d + 30720 + 48, Bp_l + (k0) + 24); \
        CP_COMMIT(); \
    } while (0)

    LOAD_STAGE(0, 0);

#pragma unroll 1
    for (int t = 0; t < T; t++) {
        if (t + 1 < T) {
            LOAD_STAGE((t + 1) & 1, (t + 1) * 32);
            CP_WAIT1();
        } else {
            CP_WAIT0();
        }
        __syncthreads();

        bf16* st   = sm + (t & 1) * 20480;
        bf16* Ah_s = st;
        bf16* Al_s = st + 5120;
        bf16* Bh_s = st + 10240;
        bf16* Bl_s = st + 15360;
#pragma unroll
        for (int ks = 0; ks < 32; ks += 16) {
            wmma::fragment<wmma::matrix_b, 16, 16, 16, bf16, wmma::col_major> bh[4], bl[4];
#pragma unroll
            for (int j = 0; j < 4; j++) {
                wmma::load_matrix_sync(bh[j], &Bh_s[(wn * 64 + j * 16) * 40 + ks], 40);
                wmma::load_matrix_sync(bl[j], &Bl_s[(wn * 64 + j * 16) * 40 + ks], 40);
            }
#pragma unroll
            for (int i = 0; i < 4; i++) {
                wmma::fragment<wmma::matrix_a, 16, 16, 16, bf16, wmma::row_major> ah, al;
                wmma::load_matrix_sync(ah, &Ah_s[(wm * 64 + i * 16) * 40 + ks], 40);
                wmma::load_matrix_sync(al, &Al_s[(wm * 64 + i * 16) * 40 + ks], 40);
#pragma unroll
                for (int j = 0; j < 4; j++) {
                    wmma::mma_sync(acc[i][j], ah, bl[j], acc[i][j]);
                    wmma::mma_sync(acc[i][j], al, bh[j], acc[i][j]);
                    wmma::mma_sync(acc[i][j], ah, bh[j], acc[i][j]);
                }
            }
        }
        __syncthreads();
    }
#undef LOAD_STAGE

#pragma unroll
    for (int i = 0; i < 4; i++)
#pragma unroll
        for (int j = 0; j < 4; j++) {
#pragma unroll
            for (int t = 0; t < acc[i][j].num_elements; t++) acc[i][j].x[t] *= scale;
            wmma::store_matrix_sync(
                C + (size_t)(mBase + wm * 64 + i * 16) * ldc + nBase + wn * 64 + j * 16,
                acc[i][j], ldc, wmma::mem_row_major);
        }
}

// ===========================================================================
// fp16 2-product core (128 threads, warp tile 64x64): C16 = Ah/Al @ B^T.
// Stage (halfs): Ah@0 (5120), Al@5120, B@10240 -> 15360 halfs = 30720 B.
// ===========================================================================
__device__ __forceinline__ void v16_core(
    const fp16* __restrict__ Ah, const fp16* __restrict__ Al,
    const fp16* __restrict__ B, fp16* __restrict__ C,
    int K, int mBase, int nBase, int ldc)
{
    extern __shared__ char smraw[];
    fp16* sm = (fp16*)smraw;
    const int tid = threadIdx.x;
    const int warp = tid >> 5;
    const int wm = warp >> 1;
    const int wn = warp & 1;

    wmma::fragment<wmma::accumulator, 16, 16, 16, float> acc[4][4];
#pragma unroll
    for (int i = 0; i < 4; i++)
#pragma unroll
        for (int j = 0; j < 4; j++) wmma::fill_fragment(acc[i][j], 0.0f);

    const fp16* ApH = Ah + (size_t)(mBase + tid) * K;
    const fp16* ApL = Al + (size_t)(mBase + tid) * K;
    const fp16* Bp  = B  + (size_t)(nBase + tid) * K;
    const uint32_t dbase = smem_u32(sm) + tid * 80;

    const int T = K >> 5;

#define V_LOAD(buf, k0) do { \
        uint32_t d = dbase + (buf) * 30720; \
        CP16(d,          ApH + (k0));      CP16(d + 16,          ApH + (k0) + 8); \
        CP16(d + 32,     ApH + (k0) + 16); CP16(d + 48,          ApH + (k0) + 24); \
        CP16(d + 10240,      ApL + (k0));      CP16(d + 10240 + 16, ApL + (k0) + 8); \
        CP16(d + 10240 + 32, ApL + (k0) + 16); CP16(d + 10240 + 48, ApL + (k0) + 24); \
        CP16(d + 20480,      Bp + (k0));       CP16(d + 20480 + 16, Bp + (k0) + 8); \
        CP16(d + 20480 + 32, Bp + (k0) + 16);  CP16(d + 20480 + 48, Bp + (k0) + 24); \
        CP_COMMIT(); \
    } while (0)

    V_LOAD(0, 0);

#pragma unroll 1
    for (int t = 0; t < T; t++) {
        if (t + 1 < T) {
            V_LOAD((t + 1) & 1, (t + 1) * 32);
            CP_WAIT1();
        } else {
            CP_WAIT0();
        }
        __syncthreads();

        fp16* st   = sm + (t & 1) * 15360;
        fp16* Ah_s = st;
        fp16* Al_s = st + 5120;
        fp16* B_s  = st + 10240;
#pragma unroll
        for (int ks = 0; ks < 32; ks += 16) {
            wmma::fragment<wmma::matrix_b, 16, 16, 16, fp16, wmma::col_major> bf[4];
#pragma unroll
            for (int j = 0; j < 4; j++)
                wmma::load_matrix_sync(bf[j], &B_s[(wn * 64 + j * 16) * 40 + ks], 40);
#pragma unroll
            for (int i = 0; i < 4; i++) {
                wmma::fragment<wmma::matrix_a, 16, 16, 16, fp16, wmma::row_major> ah, al;
                wmma::load_matrix_sync(ah, &Ah_s[(wm * 64 + i * 16) * 40 + ks], 40);
                wmma::load_matrix_sync(al, &Al_s[(wm * 64 + i * 16) * 40 + ks], 40);
#pragma unroll
                for (int j = 0; j < 4; j++) {
                    wmma::mma_sync(acc[i][j], al, bf[j], acc[i][j]);
                    wmma::mma_sync(acc[i][j], ah, bf[j], acc[i][j]);
                }
            }
        }
        __syncthreads();
    }
#undef V_LOAD

#pragma unroll
    for (int i = 0; i < 4; i++)
#pragma unroll
        for (int j = 0; j < 4; j++) {
            wmma::fragment<wmma::accumulator, 16, 16, 16, fp16> hacc;
#pragma unroll
            for (int t = 0; t < hacc.num_elements; t++)
                hacc.x[t] = __float2half_rn(acc[i][j].x[t]);
            wmma::store_matrix_sync(
                C + (size_t)(mBase + wm * 64 + i * 16) * ldc + nBase + wn * 64 + j * 16,
                hacc, ldc, wmma::mem_row_major);
        }
}

// ===========================================================================
// Fused projection launch: x<20 -> qk tile (bf16 3-prod), x>=20 -> v tile.
// ===========================================================================
__global__ void __launch_bounds__(128) fused_proj_kernel()
{
    const int x = blockIdx.x;
    const int mBase = blockIdx.y * 128;
    if (x < QK_XTILES) {
        gemm_core(g_hsh, g_hsl, g_wh, g_wl, D_MODEL, D_MODEL, D_MODEL,
                  mBase, x * 128, g_qk, QK_DIM, 1.0f);
    } else {
        v16_core(g_hs16h, g_hs16l, g_wv16, g_v16, D_MODEL,
                 mBase, (x - QK_XTILES) * 128, KV_DIM);
    }
}

__global__ void __launch_bounds__(128) scores_pre_kernel(float* __restrict__ attn)
{
    const int h = blockIdx.z;
    const int mBase = blockIdx.y * 128;
    const int nBase = blockIdx.x * 128;
    if (nBase > mBase + 127) return;
    gemm_core(g_qh + h * H_DIM, g_ql + h * H_DIM,
              g_kh + (h >> 2) * H_DIM, g_kl + (h >> 2) * H_DIM,
              N_H * H_DIM, KV_DIM, H_DIM, mBase, nBase,
              attn + (size_t)h * S_LEN * S_LEN, S_LEN, SCALING);
}

// ===========================================================================
// wo GEMM: out = ctx16 @ wo16^T, single fp16 product, fp32 accum/out.
// ===========================================================================
#define WO_STAGE 20480
#define WO_SMEM  (2 * WO_STAGE)

__global__ void __launch_bounds__(256) gemm_wo16_kernel(
    const fp16* __restrict__ A, const fp16* __restrict__ B,
    float* __restrict__ C, int K)
{
    extern __shared__ char smraw[];
    fp16* smh = (fp16*)smraw;
    const int tid = threadIdx.x;
    const int warp = tid >> 5;
    const int wm = warp & 3;
    const int wn = warp >> 2;
    const int mBase = blockIdx.y * 128;
    const int nBase = blockIdx.x * 128;

    wmma::fragment<wmma::accumulator, 16, 16, 16, float> acc[2][4];
#pragma unroll
    for (int i = 0; i < 2; i++)
#pragma unroll
        for (int j = 0; j < 4; j++) wmma::fill_fragment(acc[i][j], 0.0f);

    const int r  = tid >> 1;
    const int cc = (tid & 1) * 16;

    const fp16* Ap = A + (size_t)(mBase + r) * K + cc;
    const fp16* Bp = B + (size_t)(nBase + r) * K + cc;
    const uint32_t dbase = smem_u32(smh) + r * 80 + cc * 2;

    const int T = K >> 5;

#define WO_LOAD(buf, k0) do { \
        uint32_t d = dbase + (buf) * WO_STAGE; \
        CP16(d,          Ap + (k0)); CP16(d + 16,          Ap + (k0) + 8); \
        CP16(d + 10240,  Bp + (k0)); CP16(d + 10240 + 16,  Bp + (k0) + 8); \
        CP_COMMIT(); \
    } while (0)

    WO_LOAD(0, 0);

#pragma unroll 1
    for (int t = 0; t < T; t++) {
        if (t + 1 < T) {
            WO_LOAD((t + 1) & 1, (t + 1) * 32);
            CP_WAIT1();
        } else {
            CP_WAIT0();
        }
        __syncthreads();

        fp16* st  = smh + (t & 1) * (WO_STAGE / 2);
        fp16* A_s = st;
        fp16* B_s = st + 5120;
#pragma unroll
        for (int ks = 0; ks < 32; ks += 16) {
            wmma::fragment<wmma::matrix_b, 16, 16, 16, fp16, wmma::col_major> bf[4];
#pragma unroll
            for (int j = 0; j < 4; j++)
                wmma::load_matrix_sync(bf[j], &B_s[(wn * 64 + j * 16) * 40 + ks], 40);
            wmma::fragment<wmma::matrix_a, 16, 16, 16, fp16, wmma::row_major> af[2];
#pragma unroll
            for (int i = 0; i < 2; i++)
                wmma::load_matrix_sync(af[i], &A_s[(wm * 32 + i * 16) * 40 + ks], 40);
#pragma unroll
            for (int i = 0; i < 2; i++)
#pragma unroll
                for (int j = 0; j < 4; j++)
                    wmma::mma_sync(acc[i][j], af[i], bf[j], acc[i][j]);
        }
        __syncthreads();
    }
#undef WO_LOAD

#pragma unroll
    for (int i = 0; i < 2; i++)
#pragma unroll
        for (int j = 0; j < 4; j++)
            wmma::store_matrix_sync(
                C + (size_t)(mBase + wm * 32 + i * 16) * D_MODEL + nBase + wn * 64 + j * 16,
                acc[i][j], D_MODEL, wmma::mem_row_major);
}

// ===========================================================================
// alpha-entmax (alpha=1.5), 32-iter bisection, ONE WARP PER ROW (shfl only).
// Emits fp16 single-plane attn for the AV GEMM.
// ===========================================================================
template <int CH>
__device__ __forceinline__ void entmax_row_warp(float* __restrict__ x,
                                                fp16* __restrict__ xh,
                                                int n, int lane)
{
    float X[CH];
    float lmax = -INFINITY;
#pragma unroll
    for (int i = 0; i < CH; i++) {
        int j = lane + i * 32;
        if (j < n) {
            float v = x[j] * 0.5f;
            X[i] = v;
            lmax = fmaxf(lmax, v);
        } else {
            X[i] = -INFINITY;
        }
    }
#pragma unroll
    for (int o = 16; o > 0; o >>= 1) lmax = fmaxf(lmax, __shfl_xor_sync(0xffffffffu, lmax, o));

    float tau_lo = lmax - 1.0f;
    float dm = DM0;
    float tau_m = tau_lo;
#pragma unroll 1
    for (int it = 0; it < 32; it++) {
        dm *= 0.5f;
        tau_m = tau_lo + dm;
        float ls = 0.f;
#pragma unroll
        for (int i = 0; i < CH; i++) {
            float t = fmaxf(X[i] - tau_m, 0.f);
            ls = fmaf(t, t, ls);
        }
#pragma unroll
        for (int o = 16; o > 0; o >>= 1) ls += __shfl_xor_sync(0xffffffffu, ls, o);
        if (ls >= 1.0f) tau_lo = tau_m;
    }

    float ls = 0.f;
#pragma unroll
    for (int i = 0; i < CH; i++) {
        float t = fmaxf(X[i] - tau_m, 0.f);
        ls = fmaf(t, t, ls);
    }
#pragma unroll
    for (int o = 16; o > 0; o >>= 1) ls += __shfl_xor_sync(0xffffffffu, ls, o);
    float inv = 1.0f / ls;

#pragma unroll
    for (int i = 0; i < CH; i++) {
        int j = lane + i * 32;
        float t = fmaxf(X[i] - tau_m, 0.f);
        float v = (j < n) ? t * t * inv : 0.0f;
        x[j] = v;
        xh[j] = __float2half_rn(v);
    }
#pragma unroll
    for (int i = CH; i < 64; i++) {
        int j = lane + i * 32;
        x[j] = 0.0f;
        xh[j] = __float2half_rn(0.0f);
    }
}

__global__ void __launch_bounds__(256) entmax_kernel(float* __restrict__ attn,
                                                     fp16* __restrict__ at16)
{
    const int idx = blockIdx.x * 8 + (threadIdx.x >> 5);
    const int lane = threadIdx.x & 31;
    const int h = idx >> 11;
    const int q = idx & 2047;
    size_t off = (size_t)h * S_LEN * S_LEN + (size_t)q * S_LEN;
    float* x = attn + off;
    fp16* xh = at16 + off;
    const int n = q + 1;
    const int c8 = (((n + 31) >> 5) + 7) >> 3;

    switch (c8) {
        case 1: entmax_row_warp<8>(x, xh, n, lane); break;
        case 2: entmax_row_warp<16>(x, xh, n, lane); break;
        case 3: entmax_row_warp<24>(x, xh, n, lane); break;
        case 4: entmax_row_warp<32>(x, xh, n, lane); break;
        case 5: entmax_row_warp<40>(x, xh, n, lane); break;
        case 6: entmax_row_warp<48>(x, xh, n, lane); break;
        case 7: entmax_row_warp<56>(x, xh, n, lane); break;
        default: entmax_row_warp<64>(x, xh, n, lane); break;
    }
}

// ===========================================================================
// attn @ V: attn fp16 single x V fp16 single = 1 product, fp16 ctx output.
// 128x128 C tile, BK=32, 256 threads, warp tile 32x64, 2-stage cp.async.
// ===========================================================================
#define AV_STAGE 18944
#define AV_SMEM  (2 * AV_STAGE)

__global__ void __launch_bounds__(256) av_kernel()
{
    extern __shared__ char smraw[];
    fp16* smh = (fp16*)smraw;
    const int h = blockIdx.z;
    const int mBase = (gridDim.y - 1 - blockIdx.y) * 128;

    const int tid = threadIdx.x;
    const int warp = tid >> 5;
    const int wm = warp & 3;
    const int wn = warp >> 2;

    const fp16* A_g = g_at16 + (size_t)h * S_LEN * S_LEN;
    const fp16* B_g = g_v16 + (h >> 2) * H_DIM;

    const int rA = tid >> 1;
    const int cA = (tid & 1) * 16;
    const int rB = tid >> 3;
    const int cB = (tid & 7) * 16;

    const fp16* Ap = A_g + (size_t)(mBase + rA) * S_LEN + cA;
    const fp16* Bp = B_g + (size_t)rB * KV_DIM + cB;

    const uint32_t sb = smem_u32(smh);
    const uint32_t dA = sb + rA * 80 + cA * 2;
    const uint32_t dB = sb + 10240 + rB * 272 + cB * 2;

    wmma::fragment<wmma::accumulator, 16, 16, 16, float> acc[2][4];
#pragma unroll
    for (int i = 0; i < 2; i++)
#pragma unroll
        for (int j = 0; j < 4; j++) wmma::fill_fragment(acc[i][j], 0.0f);

    const int T = (mBase + 128) >> 5;

#define AV_LOAD(buf, k0) do { \
        uint32_t da = dA + (buf) * AV_STAGE; \
        CP16(da, Ap + (k0)); CP16(da + 16, Ap + (k0) + 8); \
        uint32_t db = dB + (buf) * AV_STAGE; \
        CP16(db, Bp + (size_t)(k0) * KV_DIM); CP16(db + 16, Bp + (size_t)(k0) * KV_DIM + 8); \
        CP_COMMIT(); \
    } while (0)

    AV_LOAD(0, 0);

#pragma unroll 1
    for (int t = 0; t < T; t++) {
        if (t + 1 < T) {
            AV_LOAD((t + 1) & 1, (t + 1) * 32);
            CP_WAIT1();
        } else {
            CP_WAIT0();
        }
        __syncthreads();

        fp16* st  = smh + (t & 1) * (AV_STAGE / 2);
        fp16* A_s = st;
        fp16* B_s = st + 5120;
#pragma unroll
        for (int ks = 0; ks < 32; ks += 16) {
            wmma::fragment<wmma::matrix_a, 16, 16, 16, fp16, wmma::row_major> af[2];
            wmma::fragment<wmma::matrix_b, 16, 16, 16, fp16, wmma::row_major> bf[4];
#pragma unroll
            for (int i = 0; i < 2; i++)
                wmma::load_matrix_sync(af[i], &A_s[(wm * 32 + i * 16) * 40 + ks], 40);
#pragma unroll
            for (int j = 0; j < 4; j++)
                wmma::load_matrix_sync(bf[j], &B_s[ks * 136 + wn * 64 + j * 16], 136);
#pragma unroll
            for (int i = 0; i < 2; i++)
#pragma unroll
                for (int j = 0; j < 4; j++)
                    wmma::mma_sync(acc[i][j], af[i], bf[j], acc[i][j]);
        }
        __syncthreads();
    }
#undef AV_LOAD

#pragma unroll
    for (int i = 0; i < 2; i++)
#pragma unroll
        for (int j = 0; j < 4; j++) {
            wmma::fragment<wmma::accumulator, 16, 16, 16, fp16> hacc;
#pragma unroll
            for (int t = 0; t < hacc.num_elements; t++)
                hacc.x[t] = __float2half_rn(acc[i][j].x[t]);
            wmma::store_matrix_sync(
                g_c16 + (size_t)(mBase + wm * 32 + i * 16) * (N_H * H_DIM)
                      + h * H_DIM + wn * 64 + j * 16,
                hacc, N_H * H_DIM, wmma::mem_row_major);
        }
}

// ===========================================================================
extern "C" void kernel_launch(void* const* d_in, const int* in_sizes, int n_in,
                              void* d_out, int out_size)
{
    const float* hs   = (const float*)d_in[0];
    const float* cosb = (const float*)d_in[1];
    const float* sinb = (const float*)d_in[2];
    const float* wq   = (const float*)d_in[3];
    const float* wk   = (const float*)d_in[4];
    const float* wv   = (const float*)d_in[5];
    const float* wo   = (const float*)d_in[6];
    float* out = (float*)d_out;

    float *qkp, *ap;
    cudaGetSymbolAddress((void**)&qkp, g_qk);
    cudaGetSymbolAddress((void**)&ap, g_attn);

    bf16 *hsh, *hsl, *wh, *wl, *qh, *ql, *kh, *kl;
    fp16 *hs16h, *hs16l, *wv16, *at16, *c16, *wo16;
    cudaGetSymbolAddress((void**)&hsh, g_hsh); cudaGetSymbolAddress((void**)&hsl, g_hsl);
    cudaGetSymbolAddress((void**)&wh, g_wh);   cudaGetSymbolAddress((void**)&wl, g_wl);
    cudaGetSymbolAddress((void**)&qh, g_qh);   cudaGetSymbolAddress((void**)&ql, g_ql);
    cudaGetSymbolAddress((void**)&kh, g_kh);   cudaGetSymbolAddress((void**)&kl, g_kl);
    cudaGetSymbolAddress((void**)&hs16h, g_hs16h); cudaGetSymbolAddress((void**)&hs16l, g_hs16l);
    cudaGetSymbolAddress((void**)&wv16, g_wv16);
    cudaGetSymbolAddress((void**)&at16, g_at16);
    cudaGetSymbolAddress((void**)&c16, g_c16);
    cudaGetSymbolAddress((void**)&wo16, g_wo16);

    const size_t need = (size_t)S_LEN * D_MODEL + (size_t)N_H * S_LEN * S_LEN;
    float* attnBuf = ((size_t)out_size >= need) ? (out + (size_t)S_LEN * D_MODEL) : ap;

    cudaFuncSetAttribute(fused_proj_kernel, cudaFuncAttributeMaxDynamicSharedMemorySize, GEMM_SMEM);
    cudaFuncSetAttribute(scores_pre_kernel, cudaFuncAttributeMaxDynamicSharedMemorySize, GEMM_SMEM);
    cudaFuncSetAttribute(av_kernel, cudaFuncAttributeMaxDynamicSharedMemorySize, AV_SMEM);
    cudaFuncSetAttribute(gemm_wo16_kernel, cudaFuncAttributeMaxDynamicSharedMemorySize, WO_SMEM);

    const int nBig = 2048 * 2048, nSml = 2048 * 512;

    // 0) pre-splits (hs: single pass -> bf16 pair + fp16 pair)
    split_hs4_kernel<<<nBig / 1024, 256>>>(hs, hsh, hsl, hs16h, hs16l, nBig);
    split_kernel<<<nBig / 1024, 256>>>(wq, wh, wl, nBig);
    split_kernel<<<nSml / 1024, 256>>>(wk, wh + (size_t)2048 * 2048, wl + (size_t)2048 * 2048, nSml);
    split16_single_kernel<<<nSml / 1024, 256>>>(wv, wv16, nSml);
    split16_single_kernel<<<nBig / 1024, 256>>>(wo, wo16, nBig);

    // 1) fused qk + v projection, one launch (v rides qk's partial wave)
    fused_proj_kernel<<<dim3(QK_XTILES + V_XTILES, S_LEN / 128), 128, GEMM_SMEM>>>();

    // 2) RoPE + split (q, k bf16 pairs)
    {
        int totQ = S_LEN * N_H * (H_DIM / 2);
        int totK = S_LEN * N_KV * (H_DIM / 2);
        rope_split_kernel<<<(totQ + 255) / 256, 256>>>(qkp, QK_DIM, cosb, sinb, N_H, qh, ql);
        rope_split_kernel<<<(totK + 255) / 256, 256>>>(qkp + 2048, QK_DIM, cosb, sinb, N_KV, kh, kl);
    }

    // 3) causal scores (3-product bf16 — attn path keeps precision)
    scores_pre_kernel<<<dim3(S_LEN / 128, S_LEN / 128, N_H), 128, GEMM_SMEM>>>(attnBuf);

    // 4) entmax in place + emit fp16 attn plane
    entmax_kernel<<<(N_H * S_LEN) / 8, 256>>>(attnBuf, at16);

    // 5) attn @ v -> ctx16 (1-product fp16, fp16 out)
    av_kernel<<<dim3(1, S_LEN / 128, N_H), 256, AV_SMEM>>>();

    // 6) out = ctx16 @ wo16^T  (1-product fp16)
    gemm_wo16_kernel<<<dim3(D_MODEL / 128, S_LEN / 128), 256, WO_SMEM>>>(
        c16, wo16, out, D_MODEL);
}

// round 15
// speedup vs baseline: 2.1638x; 1.1199x over previous
#include <cuda_runtime.h>
#include <cuda_bf16.h>
#include <cuda_fp16.h>
#include <mma.h>
#include <math.h>
#include <stdint.h>

using namespace nvcuda;

#define S_LEN 2048
#define D_MODEL 2048
#define N_H 16
#define N_KV 4
#define H_DIM 128
#define SCALING 0.08838834764831845f
#define DM0 0.9779029130879204f
#define KV_DIM (N_KV * H_DIM)
#define QK_DIM (N_H * H_DIM + KV_DIM)   // 2560
#define QK_XTILES (QK_DIM / 128)        // 20
#define ALL_XTILES 24                   // 3072/128

typedef __nv_bfloat16 bf16;
typedef __half fp16;

// fp32 scratch
__device__ float g_qk[(size_t)S_LEN * QK_DIM];
__device__ float g_attn[(size_t)N_H * S_LEN * S_LEN];

// scratch
#define SZ_BIG  ((size_t)2048 * 2048)
#define SZ_SML  ((size_t)2048 * 512)
#define SZ_WALL ((size_t)3072 * 2048)
#define SZ_ATT  ((size_t)N_H * S_LEN * S_LEN)
__device__ bf16 g_qh[SZ_BIG],  g_ql[SZ_BIG];        // q bf16 pair (rope out)
__device__ bf16 g_kh[SZ_SML],  g_kl[SZ_SML];        // k bf16 pair (rope out)
__device__ fp16 g_hs16h[SZ_BIG], g_hs16l[SZ_BIG];   // hs fp16 pair
__device__ fp16 g_w16[SZ_WALL];                     // fused [wq; wk; wv] fp16 single
__device__ fp16 g_v16[SZ_SML];                      // V (written by proj GEMM)
__device__ fp16 g_at16[SZ_ATT];                     // attn single plane (entmax)
__device__ fp16 g_c16[SZ_BIG];                      // ctx (written by AV GEMM)
__device__ fp16 g_wo16[SZ_BIG];                     // wo single plane

__device__ __forceinline__ void split_bf16(float v, bf16& hi, bf16& lo) {
    hi = __float2bfloat16_rn(v);
    lo = __float2bfloat16_rn(v - __bfloat162float(hi));
}
__device__ __forceinline__ uint32_t smem_u32(const void* p) {
    return (uint32_t)__cvta_generic_to_shared(p);
}
#define CP16(dst, src) asm volatile("cp.async.cg.shared.global [%0], [%1], 16;" :: "r"(dst), "l"(src))
#define CP_COMMIT()    asm volatile("cp.async.commit_group;" ::: "memory")
#define CP_WAIT1()     asm volatile("cp.async.wait_group 1;" ::: "memory")
#define CP_WAIT0()     asm volatile("cp.async.wait_group 0;" ::: "memory")

// ===========================================================================
// Fused input split: hs->fp16 pair; wq/wk/wv->w16 single; wo->wo16 single.
// Linear 4-element slots across 5 segments.
// ===========================================================================
#define SEG_HS  (2048 * 2048)
#define SEG_WQ  (2048 * 2048)
#define SEG_WK  (512 * 2048)
#define SEG_WV  (512 * 2048)
#define SEG_WO  (2048 * 2048)
#define SPLIT_TOTAL (SEG_HS + SEG_WQ + SEG_WK + SEG_WV + SEG_WO)

__global__ void split_all_kernel(const float* __restrict__ hs,
                                 const float* __restrict__ wq,
                                 const float* __restrict__ wk,
                                 const float* __restrict__ wv,
                                 const float* __restrict__ wo)
{
    int i = (blockIdx.x * blockDim.x + threadIdx.x) * 4;
    if (i >= SPLIT_TOTAL) return;

    const float* src;
    fp16* dstS = nullptr;
    fp16 *dH = nullptr, *dL = nullptr;
    int off;
    if (i < SEG_HS) {
        off = i; src = hs + off; dH = g_hs16h + off; dL = g_hs16l + off;
    } else if (i < SEG_HS + SEG_WQ) {
        off = i - SEG_HS; src = wq + off; dstS = g_w16 + off;
    } else if (i < SEG_HS + SEG_WQ + SEG_WK) {
        off = i - SEG_HS - SEG_WQ; src = wk + off; dstS = g_w16 + (size_t)2048 * 2048 + off;
    } else if (i < SEG_HS + SEG_WQ + SEG_WK + SEG_WV) {
        off = i - SEG_HS - SEG_WQ - SEG_WK; src = wv + off; dstS = g_w16 + (size_t)2560 * 2048 + off;
    } else {
        off = i - SEG_HS - SEG_WQ - SEG_WK - SEG_WV; src = wo + off; dstS = g_wo16 + off;
    }

    float4 v = *(const float4*)src;
    if (dstS) {
        __half2* H = (__half2*)dstS;
        H[0] = __halves2half2(__float2half_rn(v.x), __float2half_rn(v.y));
        H[1] = __halves2half2(__float2half_rn(v.z), __float2half_rn(v.w));
    } else {
        const float* p = (const float*)&v;
        fp16 h[4], l[4];
#pragma unroll
        for (int e = 0; e < 4; e++) {
            h[e] = __float2half_rn(p[e]);
            l[e] = __float2half_rn(p[e] - __half2float(h[e]));
        }
        __half2* H = (__half2*)dH;
        __half2* L = (__half2*)dL;
        H[0] = __halves2half2(h[0], h[1]); H[1] = __halves2half2(h[2], h[3]);
        L[0] = __halves2half2(l[0], l[1]); L[1] = __halves2half2(l[2], l[3]);
    }
}

// ===========================================================================
// RoPE + split (bf16 pair — attn path keeps full precision)
// ===========================================================================
__global__ void rope_split_kernel(const float* __restrict__ X, int xStride,
                                  const float* __restrict__ cosb,
                                  const float* __restrict__ sinb, int nHeads,
                                  bf16* __restrict__ hi, bf16* __restrict__ lo)
{
    int idx = blockIdx.x * blockDim.x + threadIdx.x;
    int total = S_LEN * nHeads * (H_DIM / 2);
    if (idx >= total) return;
    int d = idx & 63;
    int t = idx >> 6;
    int hh = t % nHeads;
    int s  = t / nHeads;
    float c1 = cosb[s * H_DIM + d];
    float s1 = sinb[s * H_DIM + d];
    float c2 = cosb[s * H_DIM + d + 64];
    float s2 = sinb[s * H_DIM + d + 64];
    size_t src = (size_t)s * xStride + (size_t)hh * H_DIM + d;
    size_t dst = (size_t)s * nHeads * H_DIM + (size_t)hh * H_DIM + d;
    float x1 = X[src];
    float x2 = X[src + 64];
    float y1 = x1 * c1 - x2 * s1;
    float y2 = x2 * c2 + x1 * s2;
    bf16 h, l;
    split_bf16(y1, h, l); hi[dst] = h;      lo[dst] = l;
    split_bf16(y2, h, l); hi[dst + 64] = h; lo[dst + 64] = l;
}

// ===========================================================================
// fp16 2-product projection core (128 threads, warp tile 64x64).
// C = Ah/Al (fp16 pair) @ B(fp16 single)^T, fp32 accum, OutT output.
// Stage (halfs): Ah@0 (5120), Al@5120, B@10240 -> 15360 halfs = 30720 B.
// ===========================================================================
#define PROJ_SMEM (2 * 30720)

template <typename OutT>
__device__ __forceinline__ void proj16_core(
    const fp16* __restrict__ Ah, const fp16* __restrict__ Al,
    const fp16* __restrict__ B, OutT* __restrict__ C,
    int K, int mBase, int nBaseW, int nBaseC, int ldc)
{
    extern __shared__ char smraw[];
    fp16* sm = (fp16*)smraw;
    const int tid = threadIdx.x;
    const int warp = tid >> 5;
    const int wm = warp >> 1;
    const int wn = warp & 1;

    wmma::fragment<wmma::accumulator, 16, 16, 16, float> acc[4][4];
#pragma unroll
    for (int i = 0; i < 4; i++)
#pragma unroll
        for (int j = 0; j < 4; j++) wmma::fill_fragment(acc[i][j], 0.0f);

    const fp16* ApH = Ah + (size_t)(mBase + tid) * K;
    const fp16* ApL = Al + (size_t)(mBase + tid) * K;
    const fp16* Bp  = B  + (size_t)(nBaseW + tid) * K;
    const uint32_t dbase = smem_u32(sm) + tid * 80;

    const int T = K >> 5;

#define P_LOAD(buf, k0) do { \
        uint32_t d = dbase + (buf) * 30720; \
        CP16(d,          ApH + (k0));      CP16(d + 16,          ApH + (k0) + 8); \
        CP16(d + 32,     ApH + (k0) + 16); CP16(d + 48,          ApH + (k0) + 24); \
        CP16(d + 10240,      ApL + (k0));      CP16(d + 10240 + 16, ApL + (k0) + 8); \
        CP16(d + 10240 + 32, ApL + (k0) + 16); CP16(d + 10240 + 48, ApL + (k0) + 24); \
        CP16(d + 20480,      Bp + (k0));       CP16(d + 20480 + 16, Bp + (k0) + 8); \
        CP16(d + 20480 + 32, Bp + (k0) + 16);  CP16(d + 20480 + 48, Bp + (k0) + 24); \
        CP_COMMIT(); \
    } while (0)

    P_LOAD(0, 0);

#pragma unroll 1
    for (int t = 0; t < T; t++) {
        if (t + 1 < T) {
            P_LOAD((t + 1) & 1, (t + 1) * 32);
            CP_WAIT1();
        } else {
            CP_WAIT0();
        }
        __syncthreads();

        fp16* st   = sm + (t & 1) * 15360;
        fp16* Ah_s = st;
        fp16* Al_s = st + 5120;
        fp16* B_s  = st + 10240;
#pragma unroll
        for (int ks = 0; ks < 32; ks += 16) {
            wmma::fragment<wmma::matrix_b, 16, 16, 16, fp16, wmma::col_major> bf[4];
#pragma unroll
            for (int j = 0; j < 4; j++)
                wmma::load_matrix_sync(bf[j], &B_s[(wn * 64 + j * 16) * 40 + ks], 40);
#pragma unroll
            for (int i = 0; i < 4; i++) {
                wmma::fragment<wmma::matrix_a, 16, 16, 16, fp16, wmma::row_major> ah, al;
                wmma::load_matrix_sync(ah, &Ah_s[(wm * 64 + i * 16) * 40 + ks], 40);
                wmma::load_matrix_sync(al, &Al_s[(wm * 64 + i * 16) * 40 + ks], 40);
#pragma unroll
                for (int j = 0; j < 4; j++) {
                    wmma::mma_sync(acc[i][j], al, bf[j], acc[i][j]);
                    wmma::mma_sync(acc[i][j], ah, bf[j], acc[i][j]);
                }
            }
        }
        __syncthreads();
    }
#undef P_LOAD

#pragma unroll
    for (int i = 0; i < 4; i++)
#pragma unroll
        for (int j = 0; j < 4; j++) {
            OutT* dst = C + (size_t)(mBase + wm * 64 + i * 16) * ldc + nBaseC + wn * 64 + j * 16;
            if constexpr (sizeof(OutT) == 4) {
                wmma::store_matrix_sync((float*)dst, acc[i][j], ldc, wmma::mem_row_major);
            } else {
                wmma::fragment<wmma::accumulator, 16, 16, 16, fp16> hacc;
#pragma unroll
                for (int t = 0; t < hacc.num_elements; t++)
                    hacc.x[t] = __float2half_rn(acc[i][j].x[t]);
                wmma::store_matrix_sync((fp16*)dst, hacc, ldc, wmma::mem_row_major);
            }
        }
}

// Fused projection: x<20 -> qk tile (fp32 out), x>=20 -> v tile (fp16 out).
__global__ void __launch_bounds__(128) fused_proj_kernel()
{
    const int x = blockIdx.x;
    const int mBase = blockIdx.y * 128;
    if (x < QK_XTILES) {
        proj16_core<float>(g_hs16h, g_hs16l, g_w16, g_qk, D_MODEL,
                           mBase, x * 128, x * 128, QK_DIM);
    } else {
        proj16_core<fp16>(g_hs16h, g_hs16l, g_w16, g_v16, D_MODEL,
                          mBase, x * 128, (x - QK_XTILES) * 128, KV_DIM);
    }
}

// ===========================================================================
// Pipelined split-bf16 NT GEMM core (3-product) — scores only. BM=BN=128,
// BK=32, 128 threads, warp tile 64x64, 2-stage cp.async, 80KB SMEM.
// ===========================================================================
#define GEMM_SMEM (2 * 20480 * (int)sizeof(bf16))

__global__ void __launch_bounds__(128) scores_pre_kernel(float* __restrict__ attn)
{
    const int h = blockIdx.z;
    const int mBase = blockIdx.y * 128;
    const int nBase = blockIdx.x * 128;
    if (nBase > mBase + 127) return;

    extern __shared__ char smraw[];
    bf16* sm = (bf16*)smraw;
    const bf16* Ah = g_qh + h * H_DIM;
    const bf16* Al = g_ql + h * H_DIM;
    const bf16* Bh = g_kh + (h >> 2) * H_DIM;
    const bf16* Bl = g_kl + (h >> 2) * H_DIM;
    float* C = attn + (size_t)h * S_LEN * S_LEN;
    const int lda = N_H * H_DIM, ldb = KV_DIM, K = H_DIM, ldc = S_LEN;

    const int tid = threadIdx.x;
    const int warp = tid >> 5;
    const int wm = warp >> 1;
    const int wn = warp & 1;

    wmma::fragment<wmma::accumulator, 16, 16, 16, float> acc[4][4];
#pragma unroll
    for (int i = 0; i < 4; i++)
#pragma unroll
        for (int j = 0; j < 4; j++) wmma::fill_fragment(acc[i][j], 0.0f);

    const bf16* Ap_h = Ah + (size_t)(mBase + tid) * lda;
    const bf16* Ap_l = Al + (size_t)(mBase + tid) * lda;
    const bf16* Bp_h = Bh + (size_t)(nBase + tid) * ldb;
    const bf16* Bp_l = Bl + (size_t)(nBase + tid) * ldb;
    const uint32_t dbase = smem_u32(sm) + tid * 80;

    const int T = K >> 5;

#define LOAD_STAGE(buf, k0) do { \
        uint32_t d = dbase + (buf) * 40960; \
        CP16(d,          Ap_h + (k0));      CP16(d + 16,          Ap_h + (k0) + 8); \
        CP16(d + 32,     Ap_h + (k0) + 16); CP16(d + 48,          Ap_h + (k0) + 24); \
        CP16(d + 10240,      Ap_l + (k0));      CP16(d + 10240 + 16, Ap_l + (k0) + 8); \
        CP16(d + 10240 + 32, Ap_l + (k0) + 16); CP16(d + 10240 + 48, Ap_l + (k0) + 24); \
        CP16(d + 20480,      Bp_h + (k0));      CP16(d + 20480 + 16, Bp_h + (k0) + 8); \
        CP16(d + 20480 + 32, Bp_h + (k0) + 16); CP16(d + 20480 + 48, Bp_h + (k0) + 24); \
        CP16(d + 30720,      Bp_l + (k0));      CP16(d + 30720 + 16, Bp_l + (k0) + 8); \
        CP16(d + 30720 + 32, Bp_l + (k0) + 16); CP16(d + 30720 + 48, Bp_l + (k0) + 24); \
        CP_COMMIT(); \
    } while (0)

    LOAD_STAGE(0, 0);

#pragma unroll 1
    for (int t = 0; t < T; t++) {
        if (t + 1 < T) {
            LOAD_STAGE((t + 1) & 1, (t + 1) * 32);
            CP_WAIT1();
        } else {
            CP_WAIT0();
        }
        __syncthreads();

        bf16* st   = sm + (t & 1) * 20480;
        bf16* Ah_s = st;
        bf16* Al_s = st + 5120;
        bf16* Bh_s = st + 10240;
        bf16* Bl_s = st + 15360;
#pragma unroll
        for (int ks = 0; ks < 32; ks += 16) {
            wmma::fragment<wmma::matrix_b, 16, 16, 16, bf16, wmma::col_major> bh[4], bl[4];
#pragma unroll
            for (int j = 0; j < 4; j++) {
                wmma::load_matrix_sync(bh[j], &Bh_s[(wn * 64 + j * 16) * 40 + ks], 40);
                wmma::load_matrix_sync(bl[j], &Bl_s[(wn * 64 + j * 16) * 40 + ks], 40);
            }
#pragma unroll
            for (int i = 0; i < 4; i++) {
                wmma::fragment<wmma::matrix_a, 16, 16, 16, bf16, wmma::row_major> ah, al;
                wmma::load_matrix_sync(ah, &Ah_s[(wm * 64 + i * 16) * 40 + ks], 40);
                wmma::load_matrix_sync(al, &Al_s[(wm * 64 + i * 16) * 40 + ks], 40);
#pragma unroll
                for (int j = 0; j < 4; j++) {
                    wmma::mma_sync(acc[i][j], ah, bl[j], acc[i][j]);
                    wmma::mma_sync(acc[i][j], al, bh[j], acc[i][j]);
                    wmma::mma_sync(acc[i][j], ah, bh[j], acc[i][j]);
                }
            }
        }
        __syncthreads();
    }
#undef LOAD_STAGE

#pragma unroll
    for (int i = 0; i < 4; i++)
#pragma unroll
        for (int j = 0; j < 4; j++) {
#pragma unroll
            for (int t = 0; t < acc[i][j].num_elements; t++) acc[i][j].x[t] *= SCALING;
            wmma::store_matrix_sync(
                C + (size_t)(mBase + wm * 64 + i * 16) * ldc + nBase + wn * 64 + j * 16,
                acc[i][j], ldc, wmma::mem_row_major);
        }
}

// ===========================================================================
// wo GEMM: out = ctx16 @ wo16^T, single fp16 product, fp32 accum/out.
// ===========================================================================
#define WO_STAGE 20480
#define WO_SMEM  (2 * WO_STAGE)

__global__ void __launch_bounds__(256) gemm_wo16_kernel(
    const fp16* __restrict__ A, const fp16* __restrict__ B,
    float* __restrict__ C, int K)
{
    extern __shared__ char smraw[];
    fp16* smh = (fp16*)smraw;
    const int tid = threadIdx.x;
    const int warp = tid >> 5;
    const int wm = warp & 3;
    const int wn = warp >> 2;
    const int mBase = blockIdx.y * 128;
    const int nBase = blockIdx.x * 128;

    wmma::fragment<wmma::accumulator, 16, 16, 16, float> acc[2][4];
#pragma unroll
    for (int i = 0; i < 2; i++)
#pragma unroll
        for (int j = 0; j < 4; j++) wmma::fill_fragment(acc[i][j], 0.0f);

    const int r  = tid >> 1;
    const int cc = (tid & 1) * 16;

    const fp16* Ap = A + (size_t)(mBase + r) * K + cc;
    const fp16* Bp = B + (size_t)(nBase + r) * K + cc;
    const uint32_t dbase = smem_u32(smh) + r * 80 + cc * 2;

    const int T = K >> 5;

#define WO_LOAD(buf, k0) do { \
        uint32_t d = dbase + (buf) * WO_STAGE; \
        CP16(d,          Ap + (k0)); CP16(d + 16,          Ap + (k0) + 8); \
        CP16(d + 10240,  Bp + (k0)); CP16(d + 10240 + 16,  Bp + (k0) + 8); \
        CP_COMMIT(); \
    } while (0)

    WO_LOAD(0, 0);

#pragma unroll 1
    for (int t = 0; t < T; t++) {
        if (t + 1 < T) {
            WO_LOAD((t + 1) & 1, (t + 1) * 32);
            CP_WAIT1();
        } else {
            CP_WAIT0();
        }
        __syncthreads();

        fp16* st  = smh + (t & 1) * (WO_STAGE / 2);
        fp16* A_s = st;
        fp16* B_s = st + 5120;
#pragma unroll
        for (int ks = 0; ks < 32; ks += 16) {
            wmma::fragment<wmma::matrix_b, 16, 16, 16, fp16, wmma::col_major> bf[4];
#pragma unroll
            for (int j = 0; j < 4; j++)
                wmma::load_matrix_sync(bf[j], &B_s[(wn * 64 + j * 16) * 40 + ks], 40);
            wmma::fragment<wmma::matrix_a, 16, 16, 16, fp16, wmma::row_major> af[2];
#pragma unroll
            for (int i = 0; i < 2; i++)
                wmma::load_matrix_sync(af[i], &A_s[(wm * 32 + i * 16) * 40 + ks], 40);
#pragma unroll
            for (int i = 0; i < 2; i++)
#pragma unroll
                for (int j = 0; j < 4; j++)
                    wmma::mma_sync(acc[i][j], af[i], bf[j], acc[i][j]);
        }
        __syncthreads();
    }
#undef WO_LOAD

#pragma unroll
    for (int i = 0; i < 2; i++)
#pragma unroll
        for (int j = 0; j < 4; j++)
            wmma::store_matrix_sync(
                C + (size_t)(mBase + wm * 32 + i * 16) * D_MODEL + nBase + wn * 64 + j * 16,
                acc[i][j], D_MODEL, wmma::mem_row_major);
}

// ===========================================================================
// alpha-entmax (alpha=1.5), 32-iter bisection, ONE WARP PER ROW (shfl only).
// Emits fp16 single-plane attn for the AV GEMM.
// ===========================================================================
template <int CH>
__device__ __forceinline__ void entmax_row_warp(float* __restrict__ x,
                                                fp16* __restrict__ xh,
                                                int n, int lane)
{
    float X[CH];
    float lmax = -INFINITY;
#pragma unroll
    for (int i = 0; i < CH; i++) {
        int j = lane + i * 32;
        if (j < n) {
            float v = x[j] * 0.5f;
            X[i] = v;
            lmax = fmaxf(lmax, v);
        } else {
            X[i] = -INFINITY;
        }
    }
#pragma unroll
    for (int o = 16; o > 0; o >>= 1) lmax = fmaxf(lmax, __shfl_xor_sync(0xffffffffu, lmax, o));

    float tau_lo = lmax - 1.0f;
    float dm = DM0;
    float tau_m = tau_lo;
#pragma unroll 1
    for (int it = 0; it < 32; it++) {
        dm *= 0.5f;
        tau_m = tau_lo + dm;
        float ls = 0.f;
#pragma unroll
        for (int i = 0; i < CH; i++) {
            float t = fmaxf(X[i] - tau_m, 0.f);
            ls = fmaf(t, t, ls);
        }
#pragma unroll
        for (int o = 16; o > 0; o >>= 1) ls += __shfl_xor_sync(0xffffffffu, ls, o);
        if (ls >= 1.0f) tau_lo = tau_m;
    }

    float ls = 0.f;
#pragma unroll
    for (int i = 0; i < CH; i++) {
        float t = fmaxf(X[i] - tau_m, 0.f);
        ls = fmaf(t, t, ls);
    }
#pragma unroll
    for (int o = 16; o > 0; o >>= 1) ls += __shfl_xor_sync(0xffffffffu, ls, o);
    float inv = 1.0f / ls;

#pragma unroll
    for (int i = 0; i < CH; i++) {
        int j = lane + i * 32;
        float t = fmaxf(X[i] - tau_m, 0.f);
        float v = (j < n) ? t * t * inv : 0.0f;
        x[j] = v;
        xh[j] = __float2half_rn(v);
    }
#pragma unroll
    for (int i = CH; i < 64; i++) {
        int j = lane + i * 32;
        x[j] = 0.0f;
        xh[j] = __float2half_rn(0.0f);
    }
}

__global__ void __launch_bounds__(256) entmax_kernel(float* __restrict__ attn,
                                                     fp16* __restrict__ at16)
{
    const int idx = blockIdx.x * 8 + (threadIdx.x >> 5);
    const int lane = threadIdx.x & 31;
    const int h = idx >> 11;
    const int q = idx & 2047;
    size_t off = (size_t)h * S_LEN * S_LEN + (size_t)q * S_LEN;
    float* x = attn + off;
    fp16* xh = at16 + off;
    const int n = q + 1;
    const int c8 = (((n + 31) >> 5) + 7) >> 3;

    switch (c8) {
        case 1: entmax_row_warp<8>(x, xh, n, lane); break;
        case 2: entmax_row_warp<16>(x, xh, n, lane); break;
        case 3: entmax_row_warp<24>(x, xh, n, lane); break;
        case 4: entmax_row_warp<32>(x, xh, n, lane); break;
        case 5: entmax_row_warp<40>(x, xh, n, lane); break;
        case 6: entmax_row_warp<48>(x, xh, n, lane); break;
        case 7: entmax_row_warp<56>(x, xh, n, lane); break;
        default: entmax_row_warp<64>(x, xh, n, lane); break;
    }
}

// ===========================================================================
// attn @ V: attn fp16 single x V fp16 single = 1 product, fp16 ctx output.
// ===========================================================================
#define AV_STAGE 18944
#define AV_SMEM  (2 * AV_STAGE)

__global__ void __launch_bounds__(256) av_kernel()
{
    extern __shared__ char smraw[];
    fp16* smh = (fp16*)smraw;
    const int h = blockIdx.z;
    const int mBase = (gridDim.y - 1 - blockIdx.y) * 128;

    const int tid = threadIdx.x;
    const int warp = tid >> 5;
    const int wm = warp & 3;
    const int wn = warp >> 2;

    const fp16* A_g = g_at16 + (size_t)h * S_LEN * S_LEN;
    const fp16* B_g = g_v16 + (h >> 2) * H_DIM;

    const int rA = tid >> 1;
    const int cA = (tid & 1) * 16;
    const int rB = tid >> 3;
    const int cB = (tid & 7) * 16;

    const fp16* Ap = A_g + (size_t)(mBase + rA) * S_LEN + cA;
    const fp16* Bp = B_g + (size_t)rB * KV_DIM + cB;

    const uint32_t sb = smem_u32(smh);
    const uint32_t dA = sb + rA * 80 + cA * 2;
    const uint32_t dB = sb + 10240 + rB * 272 + cB * 2;

    wmma::fragment<wmma::accumulator, 16, 16, 16, float> acc[2][4];
#pragma unroll
    for (int i = 0; i < 2; i++)
#pragma unroll
        for (int j = 0; j < 4; j++) wmma::fill_fragment(acc[i][j], 0.0f);

    const int T = (mBase + 128) >> 5;

#define AV_LOAD(buf, k0) do { \
        uint32_t da = dA + (buf) * AV_STAGE; \
        CP16(da, Ap + (k0)); CP16(da + 16, Ap + (k0) + 8); \
        uint32_t db = dB + (buf) * AV_STAGE; \
        CP16(db, Bp + (size_t)(k0) * KV_DIM); CP16(db + 16, Bp + (size_t)(k0) * KV_DIM + 8); \
        CP_COMMIT(); \
    } while (0)

    AV_LOAD(0, 0);

#pragma unroll 1
    for (int t = 0; t < T; t++) {
        if (t + 1 < T) {
            AV_LOAD((t + 1) & 1, (t + 1) * 32);
            CP_WAIT1();
        } else {
            CP_WAIT0();
        }
        __syncthreads();

        fp16* st  = smh + (t & 1) * (AV_STAGE / 2);
        fp16* A_s = st;
        fp16* B_s = st + 5120;
#pragma unroll
        for (int ks = 0; ks < 32; ks += 16) {
            wmma::fragment<wmma::matrix_a, 16, 16, 16, fp16, wmma::row_major> af[2];
            wmma::fragment<wmma::matrix_b, 16, 16, 16, fp16, wmma::row_major> bf[4];
#pragma unroll
            for (int i = 0; i < 2; i++)
                wmma::load_matrix_sync(af[i], &A_s[(wm * 32 + i * 16) * 40 + ks], 40);
#pragma unroll
            for (int j = 0; j < 4; j++)
                wmma::load_matrix_sync(bf[j], &B_s[ks * 136 + wn * 64 + j * 16], 136);
#pragma unroll
            for (int i = 0; i < 2; i++)
#pragma unroll
                for (int j = 0; j < 4; j++)
                    wmma::mma_sync(acc[i][j], af[i], bf[j], acc[i][j]);
        }
        __syncthreads();
    }
#undef AV_LOAD

#pragma unroll
    for (int i = 0; i < 2; i++)
#pragma unroll
        for (int j = 0; j < 4; j++) {
            wmma::fragment<wmma::accumulator, 16, 16, 16, fp16> hacc;
#pragma unroll
            for (int t = 0; t < hacc.num_elements; t++)
                hacc.x[t] = __float2half_rn(acc[i][j].x[t]);
            wmma::store_matrix_sync(
                g_c16 + (size_t)(mBase + wm * 32 + i * 16) * (N_H * H_DIM)
                      + h * H_DIM + wn * 64 + j * 16,
                hacc, N_H * H_DIM, wmma::mem_row_major);
        }
}

// ===========================================================================
extern "C" void kernel_launch(void* const* d_in, const int* in_sizes, int n_in,
                              void* d_out, int out_size)
{
    const float* hs   = (const float*)d_in[0];
    const float* cosb = (const float*)d_in[1];
    const float* sinb = (const float*)d_in[2];
    const float* wq   = (const float*)d_in[3];
    const float* wk   = (const float*)d_in[4];
    const float* wv   = (const float*)d_in[5];
    const float* wo   = (const float*)d_in[6];
    float* out = (float*)d_out;

    float *qkp, *ap;
    cudaGetSymbolAddress((void**)&qkp, g_qk);
    cudaGetSymbolAddress((void**)&ap, g_attn);

    bf16 *qh, *ql, *kh, *kl;
    fp16 *at16, *c16, *wo16;
    cudaGetSymbolAddress((void**)&qh, g_qh);   cudaGetSymbolAddress((void**)&ql, g_ql);
    cudaGetSymbolAddress((void**)&kh, g_kh);   cudaGetSymbolAddress((void**)&kl, g_kl);
    cudaGetSymbolAddress((void**)&at16, g_at16);
    cudaGetSymbolAddress((void**)&c16, g_c16);
    cudaGetSymbolAddress((void**)&wo16, g_wo16);

    const size_t need = (size_t)S_LEN * D_MODEL + (size_t)N_H * S_LEN * S_LEN;
    float* attnBuf = ((size_t)out_size >= need) ? (out + (size_t)S_LEN * D_MODEL) : ap;

    cudaFuncSetAttribute(fused_proj_kernel, cudaFuncAttributeMaxDynamicSharedMemorySize, PROJ_SMEM);
    cudaFuncSetAttribute(scores_pre_kernel, cudaFuncAttributeMaxDynamicSharedMemorySize, GEMM_SMEM);
    cudaFuncSetAttribute(av_kernel, cudaFuncAttributeMaxDynamicSharedMemorySize, AV_SMEM);
    cudaFuncSetAttribute(gemm_wo16_kernel, cudaFuncAttributeMaxDynamicSharedMemorySize, WO_SMEM);

    // 0) fused input splits (one launch)
    split_all_kernel<<<(SPLIT_TOTAL / 4 + 255) / 256, 256>>>(hs, wq, wk, wv, wo);

    // 1) fused qkv projection: fp16 2-product; qk -> fp32, v -> fp16
    fused_proj_kernel<<<dim3(ALL_XTILES, S_LEN / 128), 128, PROJ_SMEM>>>();

    // 2) RoPE + split (q, k bf16 pairs)
    {
        int totQ = S_LEN * N_H * (H_DIM / 2);
        int totK = S_LEN * N_KV * (H_DIM / 2);
        rope_split_kernel<<<(totQ + 255) / 256, 256>>>(qkp, QK_DIM, cosb, sinb, N_H, qh, ql);
        rope_split_kernel<<<(totK + 255) / 256, 256>>>(qkp + 2048, QK_DIM, cosb, sinb, N_KV, kh, kl);
    }

    // 3) causal scores (3-product bf16 on rope'd q/k)
    scores_pre_kernel<<<dim3(S_LEN / 128, S_LEN / 128, N_H), 128, GEMM_SMEM>>>(attnBuf);

    // 4) entmax in place + emit fp16 attn plane
    entmax_kernel<<<(N_H * S_LEN) / 8, 256>>>(attnBuf, at16);

    // 5) attn @ v -> ctx16 (1-product fp16, fp16 out)
    av_kernel<<<dim3(1, S_LEN / 128, N_H), 256, AV_SMEM>>>();

    // 6) out = ctx16 @ wo16^T  (1-product fp16)
    gemm_wo16_kernel<<<dim3(D_MODEL / 128, S_LEN / 128), 256, WO_SMEM>>>(
        c16, wo16, out, D_MODEL);
}

// round 16
// speedup vs baseline: 2.1829x; 1.0088x over previous
#include <cuda_runtime.h>
#include <cuda_bf16.h>
#include <cuda_fp16.h>
#include <mma.h>
#include <math.h>
#include <stdint.h>

using namespace nvcuda;

#define S_LEN 2048
#define D_MODEL 2048
#define N_H 16
#define N_KV 4
#define H_DIM 128
#define SCALING 0.08838834764831845f
#define DM0 0.9779029130879204f
#define KV_DIM (N_KV * H_DIM)
#define QK_DIM (N_H * H_DIM + KV_DIM)   // 2560
#define ALL_DIM 3072
#define ALL_XTILES 24

typedef __nv_bfloat16 bf16;
typedef __half fp16;

// fp32 scratch
__device__ float g_attn[(size_t)N_H * S_LEN * S_LEN];
__device__ float g_pp[2][(size_t)S_LEN * ALL_DIM];   // split-K partials

// scratch
#define SZ_BIG  ((size_t)2048 * 2048)
#define SZ_SML  ((size_t)2048 * 512)
#define SZ_WALL ((size_t)3072 * 2048)
#define SZ_ATT  ((size_t)N_H * S_LEN * S_LEN)
__device__ bf16 g_qh[SZ_BIG],  g_ql[SZ_BIG];        // q bf16 pair (rope out)
__device__ bf16 g_kh[SZ_SML],  g_kl[SZ_SML];        // k bf16 pair (rope out)
__device__ fp16 g_hs16h[SZ_BIG], g_hs16l[SZ_BIG];   // hs fp16 pair
__device__ fp16 g_w16[SZ_WALL];                     // fused [wq; wk; wv] fp16 single
__device__ fp16 g_v16[SZ_SML];                      // V (written by combiner)
__device__ fp16 g_at16[SZ_ATT];                     // attn single plane (entmax)
__device__ fp16 g_c16[SZ_BIG];                      // ctx (written by AV GEMM)
__device__ fp16 g_wo16[SZ_BIG];                     // wo single plane

__device__ __forceinline__ void split_bf16(float v, bf16& hi, bf16& lo) {
    hi = __float2bfloat16_rn(v);
    lo = __float2bfloat16_rn(v - __bfloat162float(hi));
}
__device__ __forceinline__ uint32_t smem_u32(const void* p) {
    return (uint32_t)__cvta_generic_to_shared(p);
}
#define CP16(dst, src) asm volatile("cp.async.cg.shared.global [%0], [%1], 16;" :: "r"(dst), "l"(src))
#define CP_COMMIT()    asm volatile("cp.async.commit_group;" ::: "memory")
#define CP_WAIT1()     asm volatile("cp.async.wait_group 1;" ::: "memory")
#define CP_WAIT0()     asm volatile("cp.async.wait_group 0;" ::: "memory")

// ===========================================================================
// Fused input split: hs->fp16 pair; wq/wk/wv->w16 single; wo->wo16 single.
// ===========================================================================
#define SEG_HS  (2048 * 2048)
#define SEG_WQ  (2048 * 2048)
#define SEG_WK  (512 * 2048)
#define SEG_WV  (512 * 2048)
#define SEG_WO  (2048 * 2048)
#define SPLIT_TOTAL (SEG_HS + SEG_WQ + SEG_WK + SEG_WV + SEG_WO)

__global__ void split_all_kernel(const float* __restrict__ hs,
                                 const float* __restrict__ wq,
                                 const float* __restrict__ wk,
                                 const float* __restrict__ wv,
                                 const float* __restrict__ wo)
{
    int i = (blockIdx.x * blockDim.x + threadIdx.x) * 4;
    if (i >= SPLIT_TOTAL) return;

    const float* src;
    fp16* dstS = nullptr;
    fp16 *dH = nullptr, *dL = nullptr;
    int off;
    if (i < SEG_HS) {
        off = i; src = hs + off; dH = g_hs16h + off; dL = g_hs16l + off;
    } else if (i < SEG_HS + SEG_WQ) {
        off = i - SEG_HS; src = wq + off; dstS = g_w16 + off;
    } else if (i < SEG_HS + SEG_WQ + SEG_WK) {
        off = i - SEG_HS - SEG_WQ; src = wk + off; dstS = g_w16 + (size_t)2048 * 2048 + off;
    } else if (i < SEG_HS + SEG_WQ + SEG_WK + SEG_WV) {
        off = i - SEG_HS - SEG_WQ - SEG_WK; src = wv + off; dstS = g_w16 + (size_t)2560 * 2048 + off;
    } else {
        off = i - SEG_HS - SEG_WQ - SEG_WK - SEG_WV; src = wo + off; dstS = g_wo16 + off;
    }

    float4 v = *(const float4*)src;
    if (dstS) {
        __half2* H = (__half2*)dstS;
        H[0] = __halves2half2(__float2half_rn(v.x), __float2half_rn(v.y));
        H[1] = __halves2half2(__float2half_rn(v.z), __float2half_rn(v.w));
    } else {
        const float* p = (const float*)&v;
        fp16 h[4], l[4];
#pragma unroll
        for (int e = 0; e < 4; e++) {
            h[e] = __float2half_rn(p[e]);
            l[e] = __float2half_rn(p[e] - __half2float(h[e]));
        }
        __half2* H = (__half2*)dH;
        __half2* L = (__half2*)dL;
        H[0] = __halves2half2(h[0], h[1]); H[1] = __halves2half2(h[2], h[3]);
        L[0] = __halves2half2(l[0], l[1]); L[1] = __halves2half2(l[2], l[3]);
    }
}

// ===========================================================================
// fp16 2-product projection, split-K=2, fp32 partial output.
// grid (24, 16, 2); 128 threads; warp tile 64x64; K half = 1024.
// Stage (halfs): Ah@0 (5120), Al@5120, B@10240 -> 15360 halfs = 30720 B.
// ===========================================================================
#define PROJ_SMEM (2 * 30720)

__global__ void __launch_bounds__(128) fused_proj_kernel()
{
    extern __shared__ char smraw[];
    fp16* sm = (fp16*)smraw;
    const int x = blockIdx.x;
    const int mBase = blockIdx.y * 128;
    const int z = blockIdx.z;
    const int kOff = z * 1024;
    const int nBase = x * 128;
    float* C = g_pp[z];

    const int tid = threadIdx.x;
    const int warp = tid >> 5;
    const int wm = warp >> 1;
    const int wn = warp & 1;

    wmma::fragment<wmma::accumulator, 16, 16, 16, float> acc[4][4];
#pragma unroll
    for (int i = 0; i < 4; i++)
#pragma unroll
        for (int j = 0; j < 4; j++) wmma::fill_fragment(acc[i][j], 0.0f);

    const fp16* ApH = g_hs16h + (size_t)(mBase + tid) * D_MODEL + kOff;
    const fp16* ApL = g_hs16l + (size_t)(mBase + tid) * D_MODEL + kOff;
    const fp16* Bp  = g_w16  + (size_t)(nBase + tid) * D_MODEL + kOff;
    const uint32_t dbase = smem_u32(sm) + tid * 80;

    const int T = 1024 >> 5;   // 32

#define P_LOAD(buf, k0) do { \
        uint32_t d = dbase + (buf) * 30720; \
        CP16(d,          ApH + (k0));      CP16(d + 16,          ApH + (k0) + 8); \
        CP16(d + 32,     ApH + (k0) + 16); CP16(d + 48,          ApH + (k0) + 24); \
        CP16(d + 10240,      ApL + (k0));      CP16(d + 10240 + 16, ApL + (k0) + 8); \
        CP16(d + 10240 + 32, ApL + (k0) + 16); CP16(d + 10240 + 48, ApL + (k0) + 24); \
        CP16(d + 20480,      Bp + (k0));       CP16(d + 20480 + 16, Bp + (k0) + 8); \
        CP16(d + 20480 + 32, Bp + (k0) + 16);  CP16(d + 20480 + 48, Bp + (k0) + 24); \
        CP_COMMIT(); \
    } while (0)

    P_LOAD(0, 0);

#pragma unroll 1
    for (int t = 0; t < T; t++) {
        if (t + 1 < T) {
            P_LOAD((t + 1) & 1, (t + 1) * 32);
            CP_WAIT1();
        } else {
            CP_WAIT0();
        }
        __syncthreads();

        fp16* st   = sm + (t & 1) * 15360;
        fp16* Ah_s = st;
        fp16* Al_s = st + 5120;
        fp16* B_s  = st + 10240;
#pragma unroll
        for (int ks = 0; ks < 32; ks += 16) {
            wmma::fragment<wmma::matrix_b, 16, 16, 16, fp16, wmma::col_major> bf[4];
#pragma unroll
            for (int j = 0; j < 4; j++)
                wmma::load_matrix_sync(bf[j], &B_s[(wn * 64 + j * 16) * 40 + ks], 40);
#pragma unroll
            for (int i = 0; i < 4; i++) {
                wmma::fragment<wmma::matrix_a, 16, 16, 16, fp16, wmma::row_major> ah, al;
                wmma::load_matrix_sync(ah, &Ah_s[(wm * 64 + i * 16) * 40 + ks], 40);
                wmma::load_matrix_sync(al, &Al_s[(wm * 64 + i * 16) * 40 + ks], 40);
#pragma unroll
                for (int j = 0; j < 4; j++) {
                    wmma::mma_sync(acc[i][j], al, bf[j], acc[i][j]);
                    wmma::mma_sync(acc[i][j], ah, bf[j], acc[i][j]);
                }
            }
        }
        __syncthreads();
    }
#undef P_LOAD

#pragma unroll
    for (int i = 0; i < 4; i++)
#pragma unroll
        for (int j = 0; j < 4; j++)
            wmma::store_matrix_sync(
                C + (size_t)(mBase + wm * 64 + i * 16) * ALL_DIM + nBase + wn * 64 + j * 16,
                acc[i][j], ALL_DIM, wmma::mem_row_major);
}

// ===========================================================================
// Combine split-K partials + RoPE + split: one launch.
// Ranges: q pairs | k pairs | v quads.
// ===========================================================================
#define Q_PAIRS (S_LEN * N_H * 64)
#define K_PAIRS (S_LEN * N_KV * 64)
#define V_QUADS (S_LEN * KV_DIM / 4)
#define COMB_TOTAL (Q_PAIRS + K_PAIRS + V_QUADS)

__global__ void rope_combine_kernel(const float* __restrict__ cosb,
                                    const float* __restrict__ sinb)
{
    int idx = blockIdx.x * blockDim.x + threadIdx.x;
    if (idx >= COMB_TOTAL) return;

    const float* p0 = g_pp[0];
    const float* p1 = g_pp[1];

    if (idx < Q_PAIRS + K_PAIRS) {
        int nHeads, colBase;
        bf16 *hi, *lo;
        int li;
        if (idx < Q_PAIRS) { nHeads = N_H; colBase = 0; hi = g_qh; lo = g_ql; li = idx; }
        else { nHeads = N_KV; colBase = 2048; hi = g_kh; lo = g_kl; li = idx - Q_PAIRS; }
        int d = li & 63;
        int t = li >> 6;
        int hh = t % nHeads;
        int s  = t / nHeads;
        size_t src = (size_t)s * ALL_DIM + colBase + hh * H_DIM + d;
        float x1 = p0[src] + p1[src];
        float x2 = p0[src + 64] + p1[src + 64];
        float c1 = cosb[s * H_DIM + d];
        float s1 = sinb[s * H_DIM + d];
        float c2 = cosb[s * H_DIM + d + 64];
        float s2 = sinb[s * H_DIM + d + 64];
        float y1 = x1 * c1 - x2 * s1;
        float y2 = x2 * c2 + x1 * s2;
        size_t dst = (size_t)s * nHeads * H_DIM + (size_t)hh * H_DIM + d;
        bf16 h, l;
        split_bf16(y1, h, l); hi[dst] = h;      lo[dst] = l;
        split_bf16(y2, h, l); hi[dst + 64] = h; lo[dst + 64] = l;
    } else {
        int vq = idx - Q_PAIRS - K_PAIRS;
        int s = vq >> 7;                 // 512/4 = 128 quads per row
        int c4 = (vq & 127) * 4;
        size_t src = (size_t)s * ALL_DIM + 2560 + c4;
        float4 a = *(const float4*)(p0 + src);
        float4 b = *(const float4*)(p1 + src);
        float v0 = a.x + b.x, v1 = a.y + b.y, v2 = a.z + b.z, v3 = a.w + b.w;
        __half2* H = (__half2*)(g_v16 + (size_t)s * KV_DIM + c4);
        H[0] = __halves2half2(__float2half_rn(v0), __float2half_rn(v1));
        H[1] = __halves2half2(__float2half_rn(v2), __float2half_rn(v3));
    }
}

// ===========================================================================
// Scores: 3-product bf16, triangle-packed grid (136 tile pairs x 16 heads).
// BM=BN=128, BK=32, 128 threads, warp tile 64x64, 2-stage cp.async.
// ===========================================================================
#define GEMM_SMEM (2 * 20480 * (int)sizeof(bf16))
#define TRI_TILES 136

__global__ void __launch_bounds__(128) scores_pre_kernel(float* __restrict__ attn)
{
    const int h = blockIdx.z;
    int p = blockIdx.x;
    int m = (int)((__fsqrt_rn(8.0f * p + 1.0f) - 1.0f) * 0.5f);
    while ((m + 1) * (m + 2) / 2 <= p) m++;
    while (m * (m + 1) / 2 > p) m--;
    const int mBase = m * 128;
    const int nBase = (p - m * (m + 1) / 2) * 128;

    extern __shared__ char smraw[];
    bf16* sm = (bf16*)smraw;
    const bf16* Ah = g_qh + h * H_DIM;
    const bf16* Al = g_ql + h * H_DIM;
    const bf16* Bh = g_kh + (h >> 2) * H_DIM;
    const bf16* Bl = g_kl + (h >> 2) * H_DIM;
    float* C = attn + (size_t)h * S_LEN * S_LEN;
    const int lda = N_H * H_DIM, ldb = KV_DIM, K = H_DIM, ldc = S_LEN;

    const int tid = threadIdx.x;
    const int warp = tid >> 5;
    const int wm = warp >> 1;
    const int wn = warp & 1;

    wmma::fragment<wmma::accumulator, 16, 16, 16, float> acc[4][4];
#pragma unroll
    for (int i = 0; i < 4; i++)
#pragma unroll
        for (int j = 0; j < 4; j++) wmma::fill_fragment(acc[i][j], 0.0f);

    const bf16* Ap_h = Ah + (size_t)(mBase + tid) * lda;
    const bf16* Ap_l = Al + (size_t)(mBase + tid) * lda;
    const bf16* Bp_h = Bh + (size_t)(nBase + tid) * ldb;
    const bf16* Bp_l = Bl + (size_t)(nBase + tid) * ldb;
    const uint32_t dbase = smem_u32(sm) + tid * 80;

    const int T = K >> 5;

#define LOAD_STAGE(buf, k0) do { \
        uint32_t d = dbase + (buf) * 40960; \
        CP16(d,          Ap_h + (k0));      CP16(d + 16,          Ap_h + (k0) + 8); \
        CP16(d + 32,     Ap_h + (k0) + 16); CP16(d + 48,          Ap_h + (k0) + 24); \
        CP16(d + 10240,      Ap_l + (k0));      CP16(d + 10240 + 16, Ap_l + (k0) + 8); \
        CP16(d + 10240 + 32, Ap_l + (k0) + 16); CP16(d + 10240 + 48, Ap_l + (k0) + 24); \
        CP16(d + 20480,      Bp_h + (k0));      CP16(d + 20480 + 16, Bp_h + (k0) + 8); \
        CP16(d + 20480 + 32, Bp_h + (k0) + 16); CP16(d + 20480 + 48, Bp_h + (k0) + 24); \
        CP16(d + 30720,      Bp_l + (k0));      CP16(d + 30720 + 16, Bp_l + (k0) + 8); \
        CP16(d + 30720 + 32, Bp_l + (k0) + 16); CP16(d + 30720 + 48, Bp_l + (k0) + 24); \
        CP_COMMIT(); \
    } while (0)

    LOAD_STAGE(0, 0);

#pragma unroll 1
    for (int t = 0; t < T; t++) {
        if (t + 1 < T) {
            LOAD_STAGE((t + 1) & 1, (t + 1) * 32);
            CP_WAIT1();
        } else {
            CP_WAIT0();
        }
        __syncthreads();

        bf16* st   = sm + (t & 1) * 20480;
        bf16* Ah_s = st;
        bf16* Al_s = st + 5120;
        bf16* Bh_s = st + 10240;
        bf16* Bl_s = st + 15360;
#pragma unroll
        for (int ks = 0; ks < 32; ks += 16) {
            wmma::fragment<wmma::matrix_b, 16, 16, 16, bf16, wmma::col_major> bh[4], bl[4];
#pragma unroll
            for (int j = 0; j < 4; j++) {
                wmma::load_matrix_sync(bh[j], &Bh_s[(wn * 64 + j * 16) * 40 + ks], 40);
                wmma::load_matrix_sync(bl[j], &Bl_s[(wn * 64 + j * 16) * 40 + ks], 40);
            }
#pragma unroll
            for (int i = 0; i < 4; i++) {
                wmma::fragment<wmma::matrix_a, 16, 16, 16, bf16, wmma::row_major> ah, al;
                wmma::load_matrix_sync(ah, &Ah_s[(wm * 64 + i * 16) * 40 + ks], 40);
                wmma::load_matrix_sync(al, &Al_s[(wm * 64 + i * 16) * 40 + ks], 40);
#pragma unroll
                for (int j = 0; j < 4; j++) {
                    wmma::mma_sync(acc[i][j], ah, bl[j], acc[i][j]);
                    wmma::mma_sync(acc[i][j], al, bh[j], acc[i][j]);
                    wmma::mma_sync(acc[i][j], ah, bh[j], acc[i][j]);
                }
            }
        }
        __syncthreads();
    }
#undef LOAD_STAGE

#pragma unroll
    for (int i = 0; i < 4; i++)
#pragma unroll
        for (int j = 0; j < 4; j++) {
#pragma unroll
            for (int t = 0; t < acc[i][j].num_elements; t++) acc[i][j].x[t] *= SCALING;
            wmma::store_matrix_sync(
                C + (size_t)(mBase + wm * 64 + i * 16) * ldc + nBase + wn * 64 + j * 16,
                acc[i][j], ldc, wmma::mem_row_major);
        }
}

// ===========================================================================
// wo GEMM: out = ctx16 @ wo16^T, single fp16 product, fp32 accum/out.
// ===========================================================================
#define WO_STAGE 20480
#define WO_SMEM  (2 * WO_STAGE)

__global__ void __launch_bounds__(256) gemm_wo16_kernel(
    const fp16* __restrict__ A, const fp16* __restrict__ B,
    float* __restrict__ C, int K)
{
    extern __shared__ char smraw[];
    fp16* smh = (fp16*)smraw;
    const int tid = threadIdx.x;
    const int warp = tid >> 5;
    const int wm = warp & 3;
    const int wn = warp >> 2;
    const int mBase = blockIdx.y * 128;
    const int nBase = blockIdx.x * 128;

    wmma::fragment<wmma::accumulator, 16, 16, 16, float> acc[2][4];
#pragma unroll
    for (int i = 0; i < 2; i++)
#pragma unroll
        for (int j = 0; j < 4; j++) wmma::fill_fragment(acc[i][j], 0.0f);

    const int r  = tid >> 1;
    const int cc = (tid & 1) * 16;

    const fp16* Ap = A + (size_t)(mBase + r) * K + cc;
    const fp16* Bp = B + (size_t)(nBase + r) * K + cc;
    const uint32_t dbase = smem_u32(smh) + r * 80 + cc * 2;

    const int T = K >> 5;

#define WO_LOAD(buf, k0) do { \
        uint32_t d = dbase + (buf) * WO_STAGE; \
        CP16(d,          Ap + (k0)); CP16(d + 16,          Ap + (k0) + 8); \
        CP16(d + 10240,  Bp + (k0)); CP16(d + 10240 + 16,  Bp + (k0) + 8); \
        CP_COMMIT(); \
    } while (0)

    WO_LOAD(0, 0);

#pragma unroll 1
    for (int t = 0; t < T; t++) {
        if (t + 1 < T) {
            WO_LOAD((t + 1) & 1, (t + 1) * 32);
            CP_WAIT1();
        } else {
            CP_WAIT0();
        }
        __syncthreads();

        fp16* st  = smh + (t & 1) * (WO_STAGE / 2);
        fp16* A_s = st;
        fp16* B_s = st + 5120;
#pragma unroll
        for (int ks = 0; ks < 32; ks += 16) {
            wmma::fragment<wmma::matrix_b, 16, 16, 16, fp16, wmma::col_major> bf[4];
#pragma unroll
            for (int j = 0; j < 4; j++)
                wmma::load_matrix_sync(bf[j], &B_s[(wn * 64 + j * 16) * 40 + ks], 40);
            wmma::fragment<wmma::matrix_a, 16, 16, 16, fp16, wmma::row_major> af[2];
#pragma unroll
            for (int i = 0; i < 2; i++)
                wmma::load_matrix_sync(af[i], &A_s[(wm * 32 + i * 16) * 40 + ks], 40);
#pragma unroll
            for (int i = 0; i < 2; i++)
#pragma unroll
                for (int j = 0; j < 4; j++)
                    wmma::mma_sync(acc[i][j], af[i], bf[j], acc[i][j]);
        }
        __syncthreads();
    }
#undef WO_LOAD

#pragma unroll
    for (int i = 0; i < 2; i++)
#pragma unroll
        for (int j = 0; j < 4; j++)
            wmma::store_matrix_sync(
                C + (size_t)(mBase + wm * 32 + i * 16) * D_MODEL + nBase + wn * 64 + j * 16,
                acc[i][j], D_MODEL, wmma::mem_row_major);
}

// ===========================================================================
// alpha-entmax (alpha=1.5), 32-iter bisection, ONE WARP PER ROW (shfl only).
// ===========================================================================
template <int CH>
__device__ __forceinline__ void entmax_row_warp(float* __restrict__ x,
                                                fp16* __restrict__ xh,
                                                int n, int lane)
{
    float X[CH];
    float lmax = -INFINITY;
#pragma unroll
    for (int i = 0; i < CH; i++) {
        int j = lane + i * 32;
        if (j < n) {
            float v = x[j] * 0.5f;
            X[i] = v;
            lmax = fmaxf(lmax, v);
        } else {
            X[i] = -INFINITY;
        }
    }
#pragma unroll
    for (int o = 16; o > 0; o >>= 1) lmax = fmaxf(lmax, __shfl_xor_sync(0xffffffffu, lmax, o));

    float tau_lo = lmax - 1.0f;
    float dm = DM0;
    float tau_m = tau_lo;
#pragma unroll 1
    for (int it = 0; it < 32; it++) {
        dm *= 0.5f;
        tau_m = tau_lo + dm;
        float ls = 0.f;
#pragma unroll
        for (int i = 0; i < CH; i++) {
            float t = fmaxf(X[i] - tau_m, 0.f);
            ls = fmaf(t, t, ls);
        }
#pragma unroll
        for (int o = 16; o > 0; o >>= 1) ls += __shfl_xor_sync(0xffffffffu, ls, o);
        if (ls >= 1.0f) tau_lo = tau_m;
    }

    float ls = 0.f;
#pragma unroll
    for (int i = 0; i < CH; i++) {
        float t = fmaxf(X[i] - tau_m, 0.f);
        ls = fmaf(t, t, ls);
    }
#pragma unroll
    for (int o = 16; o > 0; o >>= 1) ls += __shfl_xor_sync(0xffffffffu, ls, o);
    float inv = 1.0f / ls;

#pragma unroll
    for (int i = 0; i < CH; i++) {
        int j = lane + i * 32;
        float t = fmaxf(X[i] - tau_m, 0.f);
        float v = (j < n) ? t * t * inv : 0.0f;
        x[j] = v;
        xh[j] = __float2half_rn(v);
    }
#pragma unroll
    for (int i = CH; i < 64; i++) {
        int j = lane + i * 32;
        x[j] = 0.0f;
        xh[j] = __float2half_rn(0.0f);
    }
}

__global__ void __launch_bounds__(256) entmax_kernel(float* __restrict__ attn,
                                                     fp16* __restrict__ at16)
{
    const int idx = blockIdx.x * 8 + (threadIdx.x >> 5);
    const int lane = threadIdx.x & 31;
    const int h = idx >> 11;
    const int q = idx & 2047;
    size_t off = (size_t)h * S_LEN * S_LEN + (size_t)q * S_LEN;
    float* x = attn + off;
    fp16* xh = at16 + off;
    const int n = q + 1;
    const int c8 = (((n + 31) >> 5) + 7) >> 3;

    switch (c8) {
        case 1: entmax_row_warp<8>(x, xh, n, lane); break;
        case 2: entmax_row_warp<16>(x, xh, n, lane); break;
        case 3: entmax_row_warp<24>(x, xh, n, lane); break;
        case 4: entmax_row_warp<32>(x, xh, n, lane); break;
        case 5: entmax_row_warp<40>(x, xh, n, lane); break;
        case 6: entmax_row_warp<48>(x, xh, n, lane); break;
        case 7: entmax_row_warp<56>(x, xh, n, lane); break;
        default: entmax_row_warp<64>(x, xh, n, lane); break;
    }
}

// ===========================================================================
// attn @ V: attn fp16 single x V fp16 single = 1 product, fp16 ctx output.
// ===========================================================================
#define AV_STAGE 18944
#define AV_SMEM  (2 * AV_STAGE)

__global__ void __launch_bounds__(256) av_kernel()
{
    extern __shared__ char smraw[];
    fp16* smh = (fp16*)smraw;
    const int h = blockIdx.z;
    const int mBase = (gridDim.y - 1 - blockIdx.y) * 128;

    const int tid = threadIdx.x;
    const int warp = tid >> 5;
    const int wm = warp & 3;
    const int wn = warp >> 2;

    const fp16* A_g = g_at16 + (size_t)h * S_LEN * S_LEN;
    const fp16* B_g = g_v16 + (h >> 2) * H_DIM;

    const int rA = tid >> 1;
    const int cA = (tid & 1) * 16;
    const int rB = tid >> 3;
    const int cB = (tid & 7) * 16;

    const fp16* Ap = A_g + (size_t)(mBase + rA) * S_LEN + cA;
    const fp16* Bp = B_g + (size_t)rB * KV_DIM + cB;

    const uint32_t sb = smem_u32(smh);
    const uint32_t dA = sb + rA * 80 + cA * 2;
    const uint32_t dB = sb + 10240 + rB * 272 + cB * 2;

    wmma::fragment<wmma::accumulator, 16, 16, 16, float> acc[2][4];
#pragma unroll
    for (int i = 0; i < 2; i++)
#pragma unroll
        for (int j = 0; j < 4; j++) wmma::fill_fragment(acc[i][j], 0.0f);

    const int T = (mBase + 128) >> 5;

#define AV_LOAD(buf, k0) do { \
        uint32_t da = dA + (buf) * AV_STAGE; \
        CP16(da, Ap + (k0)); CP16(da + 16, Ap + (k0) + 8); \
        uint32_t db = dB + (buf) * AV_STAGE; \
        CP16(db, Bp + (size_t)(k0) * KV_DIM); CP16(db + 16, Bp + (size_t)(k0) * KV_DIM + 8); \
        CP_COMMIT(); \
    } while (0)

    AV_LOAD(0, 0);

#pragma unroll 1
    for (int t = 0; t < T; t++) {
        if (t + 1 < T) {
            AV_LOAD((t + 1) & 1, (t + 1) * 32);
            CP_WAIT1();
        } else {
            CP_WAIT0();
        }
        __syncthreads();

        fp16* st  = smh + (t & 1) * (AV_STAGE / 2);
        fp16* A_s = st;
        fp16* B_s = st + 5120;
#pragma unroll
        for (int ks = 0; ks < 32; ks += 16) {
            wmma::fragment<wmma::matrix_a, 16, 16, 16, fp16, wmma::row_major> af[2];
            wmma::fragment<wmma::matrix_b, 16, 16, 16, fp16, wmma::row_major> bf[4];
#pragma unroll
            for (int i = 0; i < 2; i++)
                wmma::load_matrix_sync(af[i], &A_s[(wm * 32 + i * 16) * 40 + ks], 40);
#pragma unroll
            for (int j = 0; j < 4; j++)
                wmma::load_matrix_sync(bf[j], &B_s[ks * 136 + wn * 64 + j * 16], 136);
#pragma unroll
            for (int i = 0; i < 2; i++)
#pragma unroll
                for (int j = 0; j < 4; j++)
                    wmma::mma_sync(acc[i][j], af[i], bf[j], acc[i][j]);
        }
        __syncthreads();
    }
#undef AV_LOAD

#pragma unroll
    for (int i = 0; i < 2; i++)
#pragma unroll
        for (int j = 0; j < 4; j++) {
            wmma::fragment<wmma::accumulator, 16, 16, 16, fp16> hacc;
#pragma unroll
            for (int t = 0; t < hacc.num_elements; t++)
                hacc.x[t] = __float2half_rn(acc[i][j].x[t]);
            wmma::store_matrix_sync(
                g_c16 + (size_t)(mBase + wm * 32 + i * 16) * (N_H * H_DIM)
                      + h * H_DIM + wn * 64 + j * 16,
                hacc, N_H * H_DIM, wmma::mem_row_major);
        }
}

// ===========================================================================
extern "C" void kernel_launch(void* const* d_in, const int* in_sizes, int n_in,
                              void* d_out, int out_size)
{
    const float* hs   = (const float*)d_in[0];
    const float* cosb = (const float*)d_in[1];
    const float* sinb = (const float*)d_in[2];
    const float* wq   = (const float*)d_in[3];
    const float* wk   = (const float*)d_in[4];
    const float* wv   = (const float*)d_in[5];
    const float* wo   = (const float*)d_in[6];
    float* out = (float*)d_out;

    float* ap;
    cudaGetSymbolAddress((void**)&ap, g_attn);

    fp16 *at16, *c16, *wo16;
    cudaGetSymbolAddress((void**)&at16, g_at16);
    cudaGetSymbolAddress((void**)&c16, g_c16);
    cudaGetSymbolAddress((void**)&wo16, g_wo16);

    const size_t need = (size_t)S_LEN * D_MODEL + (size_t)N_H * S_LEN * S_LEN;
    float* attnBuf = ((size_t)out_size >= need) ? (out + (size_t)S_LEN * D_MODEL) : ap;

    cudaFuncSetAttribute(fused_proj_kernel, cudaFuncAttributeMaxDynamicSharedMemorySize, PROJ_SMEM);
    cudaFuncSetAttribute(scores_pre_kernel, cudaFuncAttributeMaxDynamicSharedMemorySize, GEMM_SMEM);
    cudaFuncSetAttribute(av_kernel, cudaFuncAttributeMaxDynamicSharedMemorySize, AV_SMEM);
    cudaFuncSetAttribute(gemm_wo16_kernel, cudaFuncAttributeMaxDynamicSharedMemorySize, WO_SMEM);

    // 0) fused input splits
    split_all_kernel<<<(SPLIT_TOTAL / 4 + 255) / 256, 256>>>(hs, wq, wk, wv, wo);

    // 1) split-K=2 projection into partials (768 half-CTAs -> balanced waves)
    fused_proj_kernel<<<dim3(ALL_XTILES, S_LEN / 128, 2), 128, PROJ_SMEM>>>();

    // 2) combine + RoPE + split (one launch)
    rope_combine_kernel<<<(COMB_TOTAL + 255) / 256, 256>>>(cosb, sinb);

    // 3) causal scores (triangle-packed grid)
    scores_pre_kernel<<<dim3(TRI_TILES, 1, N_H), 128, GEMM_SMEM>>>(attnBuf);

    // 4) entmax in place + emit fp16 attn plane
    entmax_kernel<<<(N_H * S_LEN) / 8, 256>>>(attnBuf, at16);

    // 5) attn @ v -> ctx16
    av_kernel<<<dim3(1, S_LEN / 128, N_H), 256, AV_SMEM>>>();

    // 6) out = ctx16 @ wo16^T
    gemm_wo16_kernel<<<dim3(D_MODEL / 128, S_LEN / 128), 256, WO_SMEM>>>(
        c16, wo16, out, D_MODEL);
}